// round 1
// baseline (speedup 1.0000x reference)
#include <cuda_runtime.h>
#include <math.h>
#include <stdint.h>

// ---------------- problem constants ----------------
#define BB 4
#define TT 4096
#define DD 1024
#define FF 4096
#define HH 16
#define HD 64
#define KS 512                 // selected tokens per batch (T * 0.125)
#define DQ 256                 // D/4 predictor hidden
#define ROWS (BB*KS)           // 2048
#define NTOK (BB*TT)           // 16384

// ---------------- device scratch (static, no runtime alloc) ----------------
__device__ float g_scores[NTOK];
__device__ float g_tgt[NTOK];
__device__ int   g_idx[ROWS];
__device__ float g_gate[ROWS];
__device__ float g_sel[ROWS*DD];
__device__ float g_a[ROWS*DD];
__device__ float g_q[ROWS*DD];
__device__ float g_k[ROWS*DD];
__device__ float g_v[ROWS*DD];
__device__ float g_att[(size_t)BB*HH*KS*KS];   // 16.7M floats = 64MB
__device__ float g_pv[ROWS*DD];
__device__ float g_h[ROWS*DD];
__device__ float g_m[ROWS*DD];
__device__ float g_gb[ROWS*FF];
__device__ float g_ub[ROWS*FF];
__device__ float g_bo[ROWS*DD];
__device__ float g_h1[(size_t)NTOK*DQ];
__device__ float g_pred[NTOK];

// ---------------- helpers ----------------
__device__ __forceinline__ float gelu_tanh(float x) {
    float x3 = x*x*x;
    return 0.5f * x * (1.f + tanhf(0.7978845608028654f * (x + 0.044715f * x3)));
}
__device__ __forceinline__ float bce_term(float x, float t) {
    return fmaxf(x, 0.f) - x*t + log1pf(expf(-fabsf(x)));
}

// ---------------- K1: router scores = hs @ router_w ----------------
__global__ void scores_kernel(const float* __restrict__ hs, const float* __restrict__ rw,
                              float* __restrict__ scores) {
    int warp = (blockIdx.x * blockDim.x + threadIdx.x) >> 5;
    int lane = threadIdx.x & 31;
    if (warp >= NTOK) return;
    const float4* row = (const float4*)(hs + (size_t)warp * DD);
    const float4* w4  = (const float4*)rw;
    float s = 0.f;
    #pragma unroll 4
    for (int i = lane; i < DD/4; i += 32) {
        float4 a = row[i], b = w4[i];
        s += a.x*b.x + a.y*b.y + a.z*b.z + a.w*b.w;
    }
    #pragma unroll
    for (int o = 16; o; o >>= 1) s += __shfl_xor_sync(0xffffffffu, s, o);
    if (lane == 0) scores[warp] = s;
}

// ---------------- K2: per-batch top-k via bitonic sort ----------------
__device__ __forceinline__ bool desc_first(float v1, int i1, float v2, int i2) {
    // true if (v1,i1) should come before (v2,i2) in descending-value order
    return (v1 > v2) || (v1 == v2 && i1 < i2);
}
__global__ void topk_kernel(const float* __restrict__ scores, float* __restrict__ tgt,
                            int* __restrict__ idxo, float* __restrict__ gateo) {
    __shared__ float sv[TT];
    __shared__ int   si[TT];
    int b = blockIdx.x, tid = threadIdx.x;
    const float* sc = scores + (size_t)b * TT;
    for (int i = tid; i < TT; i += 1024) {
        sv[i] = sc[i]; si[i] = i; tgt[(size_t)b*TT + i] = 0.f;
    }
    __syncthreads();
    // bitonic sort, descending by value
    for (int kk = 2; kk <= TT; kk <<= 1) {
        for (int j = kk >> 1; j > 0; j >>= 1) {
            for (int i = tid; i < TT; i += 1024) {
                int ixj = i ^ j;
                if (ixj > i) {
                    bool dirDesc = ((i & kk) == 0);
                    float v1 = sv[i], v2 = sv[ixj];
                    int   i1 = si[i], i2 = si[ixj];
                    bool first = desc_first(v1, i1, v2, i2);
                    bool sw = dirDesc ? (!first) : first;
                    if (sw) { sv[i]=v2; sv[ixj]=v1; si[i]=i2; si[ixj]=i1; }
                }
            }
            __syncthreads();
        }
    }
    // mark targets
    for (int i = tid; i < KS; i += 1024) tgt[(size_t)b*TT + si[i]] = 1.f;
    __syncthreads();
    // sort top-512 indices ascending (in place in si[0..512))
    for (int kk = 2; kk <= KS; kk <<= 1) {
        for (int j = kk >> 1; j > 0; j >>= 1) {
            if (tid < KS) {
                int i = tid, ixj = i ^ j;
                if (ixj > i) {
                    bool asc = ((i & kk) == 0);
                    int a = si[i], c = si[ixj];
                    bool sw = asc ? (a > c) : (a < c);
                    if (sw) { si[i] = c; si[ixj] = a; }
                }
            }
            __syncthreads();
        }
    }
    for (int i = tid; i < KS; i += 1024) {
        int ix = si[i];
        idxo[b*KS + i] = ix;
        float s = sc[ix];
        gateo[b*KS + i] = 1.f / (1.f + expf(-s));
    }
}

// ---------------- K3: copy hidden -> out ----------------
__global__ void copy_kernel(const float4* __restrict__ src, float4* __restrict__ dst, int n4) {
    int stride = gridDim.x * blockDim.x;
    for (int i = blockIdx.x * blockDim.x + threadIdx.x; i < n4; i += stride)
        dst[i] = src[i];
}

// ---------------- K4: gather selected rows ----------------
__global__ void gather_kernel(const float* __restrict__ hs, const int* __restrict__ idx,
                              float* __restrict__ sel) {
    int r = blockIdx.x;
    int b = r / KS;
    int pos = idx[r];
    const float4* src = (const float4*)(hs + ((size_t)b*TT + pos) * DD);
    float4* dst = (float4*)(sel + (size_t)r * DD);
    dst[threadIdx.x] = src[threadIdx.x];   // 256 threads * 4 = 1024
}

// ---------------- K5: rmsnorm ----------------
__global__ void rmsnorm_kernel(const float* __restrict__ in, const float* __restrict__ g,
                               float* __restrict__ out) {
    __shared__ float red[8];
    int r = blockIdx.x, tid = threadIdx.x;
    const float4* x4 = (const float4*)(in + (size_t)r * DD);
    float4 x = x4[tid];
    float ss = x.x*x.x + x.y*x.y + x.z*x.z + x.w*x.w;
    #pragma unroll
    for (int o = 16; o; o >>= 1) ss += __shfl_xor_sync(0xffffffffu, ss, o);
    if ((tid & 31) == 0) red[tid >> 5] = ss;
    __syncthreads();
    if (tid < 8) {
        float v = red[tid];
        #pragma unroll
        for (int o = 4; o; o >>= 1) v += __shfl_xor_sync(0xffu, v, o);
        if (tid == 0) red[0] = v;
    }
    __syncthreads();
    float rs = rsqrtf(red[0] / (float)DD + 1e-6f);
    const float4* g4 = (const float4*)g;
    float4 gg = g4[tid];
    float4 o4 = make_float4(x.x*rs*gg.x, x.y*rs*gg.y, x.z*rs*gg.z, x.w*rs*gg.w);
    ((float4*)(out + (size_t)r * DD))[tid] = o4;
}

// ---------------- K6: generic SGEMM 128x128x8, optional epilogue ----------------
// epi: 0 = none, 1 = gelu(acc + bias[col]), 2 = acc + resid[row,col]
__global__ __launch_bounds__(256)
void sgemm128(const float* __restrict__ A, const float* __restrict__ B, float* __restrict__ C,
              int M, int N, int K, const float* __restrict__ aux, int epi) {
    __shared__ float As[8][128];
    __shared__ float Bs[8][128];
    int tid = threadIdx.x;
    int m0 = blockIdx.y * 128, n0 = blockIdx.x * 128;
    int aRow = tid >> 1, aCol = (tid & 1) * 4;
    int bRow = tid >> 5, bCol = (tid & 31) * 4;
    const float* Ag = A + (size_t)(m0 + aRow) * K + aCol;
    const float* Bg = B + (size_t)bRow * N + n0 + bCol;
    int ty = tid >> 4, tx = tid & 15;
    float acc[8][8];
    #pragma unroll
    for (int i = 0; i < 8; i++)
        #pragma unroll
        for (int j = 0; j < 8; j++) acc[i][j] = 0.f;

    for (int kk = 0; kk < K; kk += 8) {
        float4 a4 = *(const float4*)Ag; Ag += 8;
        float4 b4 = *(const float4*)Bg; Bg += (size_t)8 * N;
        __syncthreads();
        As[aCol+0][aRow] = a4.x; As[aCol+1][aRow] = a4.y;
        As[aCol+2][aRow] = a4.z; As[aCol+3][aRow] = a4.w;
        *(float4*)&Bs[bRow][bCol] = b4;
        __syncthreads();
        #pragma unroll
        for (int k8 = 0; k8 < 8; k8++) {
            float ar[8], br[8];
            #pragma unroll
            for (int i = 0; i < 8; i++) ar[i] = As[k8][ty*8 + i];
            #pragma unroll
            for (int j = 0; j < 8; j++) br[j] = Bs[k8][tx*8 + j];
            #pragma unroll
            for (int i = 0; i < 8; i++)
                #pragma unroll
                for (int j = 0; j < 8; j++) acc[i][j] += ar[i] * br[j];
        }
    }
    #pragma unroll
    for (int i = 0; i < 8; i++) {
        int row = m0 + ty*8 + i;
        #pragma unroll
        for (int j = 0; j < 8; j += 4) {
            int col = n0 + tx*8 + j;
            float4 r = make_float4(acc[i][j], acc[i][j+1], acc[i][j+2], acc[i][j+3]);
            if (epi == 1) {
                r.x = gelu_tanh(r.x + aux[col+0]);
                r.y = gelu_tanh(r.y + aux[col+1]);
                r.z = gelu_tanh(r.z + aux[col+2]);
                r.w = gelu_tanh(r.w + aux[col+3]);
            } else if (epi == 2) {
                float4 s = *(const float4*)&aux[(size_t)row*N + col];
                r.x += s.x; r.y += s.y; r.z += s.z; r.w += s.w;
            }
            *(float4*)&C[(size_t)row*N + col] = r;
        }
    }
}

// ---------------- K7: RoPE in place ----------------
__global__ void rope_kernel(float* __restrict__ buf, const int* __restrict__ idx) {
    int r = blockIdx.x;
    float pos = (float)idx[r];
    float* base = buf + (size_t)r * DD;
    for (int c = threadIdx.x; c < 512; c += 256) {
        int h = c >> 5, i = c & 31;
        float inv = powf(10000.f, -(float)i / 32.f);
        float ang = pos * inv;
        float s, co; sincosf(ang, &s, &co);
        float* p = base + h * 64;
        float x1 = p[i], x2 = p[i + 32];
        p[i]      = x1*co - x2*s;
        p[i + 32] = x2*co + x1*s;
    }
}

// ---------------- K8: S = scale * Q K^T with causal mask ----------------
__global__ __launch_bounds__(256)
void qk_kernel(const float* __restrict__ q, const float* __restrict__ k,
               float* __restrict__ att) {
    __shared__ float Qs[64][65];
    __shared__ float Ks[64][65];
    int kt = blockIdx.x, qt = blockIdx.y, bh = blockIdx.z;
    int b = bh >> 4, h = bh & 15;
    int tid = threadIdx.x;
    #pragma unroll
    for (int t = 0; t < 16; t++) {
        int e = t*256 + tid, row = e >> 6, col = e & 63;
        Qs[row][col] = q[((size_t)(b*KS + qt*64 + row))*DD + h*64 + col];
        Ks[row][col] = k[((size_t)(b*KS + kt*64 + row))*DD + h*64 + col];
    }
    __syncthreads();
    int ty = tid >> 4, tx = tid & 15;
    float acc[4][4];
    #pragma unroll
    for (int i = 0; i < 4; i++)
        #pragma unroll
        for (int j = 0; j < 4; j++) acc[i][j] = 0.f;
    #pragma unroll 4
    for (int d = 0; d < 64; d++) {
        float qa[4], kb[4];
        #pragma unroll
        for (int i = 0; i < 4; i++) { qa[i] = Qs[ty*4+i][d]; kb[i] = Ks[tx*4+i][d]; }
        #pragma unroll
        for (int i = 0; i < 4; i++)
            #pragma unroll
            for (int j = 0; j < 4; j++) acc[i][j] += qa[i] * kb[j];
    }
    const float scale = 0.125f;
    #pragma unroll
    for (int i = 0; i < 4; i++) {
        int qrow = qt*64 + ty*4 + i;
        #pragma unroll
        for (int j = 0; j < 4; j++) {
            int krow = kt*64 + tx*4 + j;
            float val = (krow <= qrow) ? acc[i][j] * scale : -1e9f;
            att[((size_t)bh*KS + qrow)*KS + krow] = val;
        }
    }
}

// ---------------- K9: softmax per row (512 wide) ----------------
__global__ void softmax_kernel(float* __restrict__ att) {
    int warp = (blockIdx.x * blockDim.x + threadIdx.x) >> 5;
    int lane = threadIdx.x & 31;
    float* p = att + (size_t)warp * KS;
    float v[16];
    float mx = -3.4e38f;
    #pragma unroll
    for (int l = 0; l < 16; l++) { v[l] = p[lane + l*32]; mx = fmaxf(mx, v[l]); }
    #pragma unroll
    for (int o = 16; o; o >>= 1) mx = fmaxf(mx, __shfl_xor_sync(0xffffffffu, mx, o));
    float sum = 0.f;
    #pragma unroll
    for (int l = 0; l < 16; l++) { v[l] = expf(v[l] - mx); sum += v[l]; }
    #pragma unroll
    for (int o = 16; o; o >>= 1) sum += __shfl_xor_sync(0xffffffffu, sum, o);
    float inv = 1.f / sum;
    #pragma unroll
    for (int l = 0; l < 16; l++) p[lane + l*32] = v[l] * inv;
}

// ---------------- K10: O = P @ V (skips fully masked tiles) ----------------
__global__ __launch_bounds__(256)
void pv_kernel(const float* __restrict__ att, const float* __restrict__ v,
               float* __restrict__ pv) {
    __shared__ float Ps[64][65];
    __shared__ float Vs[64][65];
    int qt = blockIdx.x, bh = blockIdx.y;
    int b = bh >> 4, h = bh & 15;
    int tid = threadIdx.x;
    int ty = tid >> 4, tx = tid & 15;
    float acc[4][4];
    #pragma unroll
    for (int i = 0; i < 4; i++)
        #pragma unroll
        for (int j = 0; j < 4; j++) acc[i][j] = 0.f;
    for (int kt = 0; kt <= qt; kt++) {
        __syncthreads();
        #pragma unroll
        for (int t = 0; t < 16; t++) {
            int e = t*256 + tid, row = e >> 6, col = e & 63;
            Ps[row][col] = att[((size_t)bh*KS + qt*64 + row)*KS + kt*64 + col];
            Vs[row][col] = v[((size_t)(b*KS + kt*64 + row))*DD + h*64 + col];
        }
        __syncthreads();
        #pragma unroll 4
        for (int d = 0; d < 64; d++) {
            float pa[4], vb[4];
            #pragma unroll
            for (int i = 0; i < 4; i++) { pa[i] = Ps[ty*4+i][d]; vb[i] = Vs[d][tx*4+i]; }
            #pragma unroll
            for (int i = 0; i < 4; i++)
                #pragma unroll
                for (int j = 0; j < 4; j++) acc[i][j] += pa[i] * vb[j];
        }
    }
    #pragma unroll
    for (int i = 0; i < 4; i++)
        #pragma unroll
        for (int j = 0; j < 4; j++)
            pv[((size_t)(b*KS + qt*64 + ty*4 + i))*DD + h*64 + tx*4 + j] = acc[i][j];
}

// ---------------- K11: silu(gate) * up in place ----------------
__global__ void silu_mul_kernel(float4* __restrict__ gb, const float4* __restrict__ ub, int n4) {
    int i = blockIdx.x * blockDim.x + threadIdx.x;
    if (i >= n4) return;
    float4 g = gb[i], u = ub[i];
    g.x = g.x / (1.f + expf(-g.x)) * u.x;
    g.y = g.y / (1.f + expf(-g.y)) * u.y;
    g.z = g.z / (1.f + expf(-g.z)) * u.z;
    g.w = g.w / (1.f + expf(-g.w)) * u.w;
    gb[i] = g;
}

// ---------------- K12: scatter updated rows into out ----------------
__global__ void scatter_kernel(const float* __restrict__ sel, const float* __restrict__ bo,
                               const int* __restrict__ idx, const float* __restrict__ gate,
                               float* __restrict__ out) {
    int r = blockIdx.x;
    int b = r / KS;
    int pos = idx[r];
    float ga = gate[r];
    const float4* s4 = (const float4*)(sel + (size_t)r * DD);
    const float4* b4 = (const float4*)(bo  + (size_t)r * DD);
    float4* o4 = (float4*)(out + ((size_t)b*TT + pos) * DD);
    float4 s = s4[threadIdx.x], bb = b4[threadIdx.x];
    float4 u = make_float4(s.x + ga*(bb.x - s.x), s.y + ga*(bb.y - s.y),
                           s.z + ga*(bb.z - s.z), s.w + ga*(bb.w - s.w));
    o4[threadIdx.x] = u;
}

// ---------------- K13: predictor logits + per-row BCE ----------------
__global__ void predrow_kernel(const float* __restrict__ h1, const float* __restrict__ fc2w,
                               const float* __restrict__ fc2b, const float* __restrict__ tgt,
                               float* __restrict__ pred) {
    int warp = (blockIdx.x * blockDim.x + threadIdx.x) >> 5;
    int lane = threadIdx.x & 31;
    if (warp >= NTOK) return;
    const float* row = h1 + (size_t)warp * DQ;
    float s = 0.f;
    #pragma unroll
    for (int i = lane; i < DQ; i += 32) s += row[i] * fc2w[i];
    #pragma unroll
    for (int o = 16; o; o >>= 1) s += __shfl_xor_sync(0xffffffffu, s, o);
    if (lane == 0) {
        float x = s + fc2b[0];
        pred[warp] = bce_term(x, tgt[warp]);
    }
}

// ---------------- K14: deterministic loss reduce ----------------
__global__ void loss_reduce(const float* __restrict__ scores, const float* __restrict__ tgt,
                            const float* __restrict__ pred, float* __restrict__ out_aux) {
    __shared__ float sm_main[1024];
    __shared__ float sm_pred[1024];
    int tid = threadIdx.x;
    float sm = 0.f, sp = 0.f;
    for (int i = tid; i < NTOK; i += 1024) {
        sm += bce_term(scores[i], tgt[i]);
        sp += pred[i];
    }
    sm_main[tid] = sm; sm_pred[tid] = sp;
    __syncthreads();
    for (int s = 512; s > 0; s >>= 1) {
        if (tid < s) { sm_main[tid] += sm_main[tid+s]; sm_pred[tid] += sm_pred[tid+s]; }
        __syncthreads();
    }
    if (tid == 0)
        out_aux[0] = 0.01f * (sm_main[0] + sm_pred[0]) / (float)NTOK;
}

// ---------------- host launch ----------------
extern "C" void kernel_launch(void* const* d_in, const int* in_sizes, int n_in,
                              void* d_out, int out_size) {
    const float* hs   = (const float*)d_in[0];
    const float* rw   = (const float*)d_in[1];
    const float* fc1w = (const float*)d_in[2];
    const float* fc1b = (const float*)d_in[3];
    const float* fc2w = (const float*)d_in[4];
    const float* fc2b = (const float*)d_in[5];
    const float* ln1  = (const float*)d_in[6];
    const float* ln2  = (const float*)d_in[7];
    const float* wq   = (const float*)d_in[8];
    const float* wk   = (const float*)d_in[9];
    const float* wv   = (const float*)d_in[10];
    const float* wo   = (const float*)d_in[11];
    const float* wg   = (const float*)d_in[12];
    const float* wu   = (const float*)d_in[13];
    const float* wd   = (const float*)d_in[14];
    float* out = (float*)d_out;

    float *scores, *tgt, *gate, *sel, *a, *q, *k, *v, *att, *pv, *h, *m, *gb, *ub, *bo, *h1, *pred;
    int* idx;
    cudaGetSymbolAddress((void**)&scores, g_scores);
    cudaGetSymbolAddress((void**)&tgt,    g_tgt);
    cudaGetSymbolAddress((void**)&idx,    g_idx);
    cudaGetSymbolAddress((void**)&gate,   g_gate);
    cudaGetSymbolAddress((void**)&sel,    g_sel);
    cudaGetSymbolAddress((void**)&a,      g_a);
    cudaGetSymbolAddress((void**)&q,      g_q);
    cudaGetSymbolAddress((void**)&k,      g_k);
    cudaGetSymbolAddress((void**)&v,      g_v);
    cudaGetSymbolAddress((void**)&att,    g_att);
    cudaGetSymbolAddress((void**)&pv,     g_pv);
    cudaGetSymbolAddress((void**)&h,      g_h);
    cudaGetSymbolAddress((void**)&m,      g_m);
    cudaGetSymbolAddress((void**)&gb,     g_gb);
    cudaGetSymbolAddress((void**)&ub,     g_ub);
    cudaGetSymbolAddress((void**)&bo,     g_bo);
    cudaGetSymbolAddress((void**)&h1,     g_h1);
    cudaGetSymbolAddress((void**)&pred,   g_pred);

    // router + top-k
    scores_kernel<<<NTOK/8, 256>>>(hs, rw, scores);
    topk_kernel<<<BB, 1024>>>(scores, tgt, idx, gate);

    // copy full hidden to output; gather selected rows
    copy_kernel<<<4096, 256>>>((const float4*)hs, (float4*)out, NTOK*DD/4);
    gather_kernel<<<ROWS, 256>>>(hs, idx, sel);

    // decoder block
    rmsnorm_kernel<<<ROWS, 256>>>(sel, ln1, a);
    sgemm128<<<dim3(DD/128, ROWS/128), 256>>>(a, wq, q, ROWS, DD, DD, nullptr, 0);
    sgemm128<<<dim3(DD/128, ROWS/128), 256>>>(a, wk, k, ROWS, DD, DD, nullptr, 0);
    sgemm128<<<dim3(DD/128, ROWS/128), 256>>>(a, wv, v, ROWS, DD, DD, nullptr, 0);
    rope_kernel<<<ROWS, 256>>>(q, idx);
    rope_kernel<<<ROWS, 256>>>(k, idx);
    qk_kernel<<<dim3(8, 8, BB*HH), 256>>>(q, k, att);
    softmax_kernel<<<BB*HH*KS/8, 256>>>(att);
    pv_kernel<<<dim3(8, BB*HH), 256>>>(att, v, pv);
    sgemm128<<<dim3(DD/128, ROWS/128), 256>>>(pv, wo, h, ROWS, DD, DD, sel, 2);   // h = sel + attn@wo

    rmsnorm_kernel<<<ROWS, 256>>>(h, ln2, m);
    sgemm128<<<dim3(FF/128, ROWS/128), 256>>>(m, wg, gb, ROWS, FF, DD, nullptr, 0);
    sgemm128<<<dim3(FF/128, ROWS/128), 256>>>(m, wu, ub, ROWS, FF, DD, nullptr, 0);
    silu_mul_kernel<<<(ROWS*FF/4 + 255)/256, 256>>>((float4*)gb, (const float4*)ub, ROWS*FF/4);
    sgemm128<<<dim3(DD/128, ROWS/128), 256>>>(gb, wd, bo, ROWS, DD, FF, h, 2);    // block_out = h + (..)@wd

    scatter_kernel<<<ROWS, 256>>>(sel, bo, idx, gate, out);

    // aux losses (predictor path)
    sgemm128<<<dim3(DQ/128, NTOK/128), 256>>>(hs, fc1w, h1, NTOK, DQ, DD, fc1b, 1);
    predrow_kernel<<<NTOK/8, 256>>>(h1, fc2w, fc2b, tgt, pred);
    loss_reduce<<<1, 1024>>>(scores, tgt, pred, out + (size_t)NTOK*DD);
}

// round 2
// speedup vs baseline: 2.2707x; 2.2707x over previous
#include <cuda_runtime.h>
#include <math.h>
#include <stdint.h>

// ---------------- problem constants ----------------
#define BB 4
#define TT 4096
#define DD 1024
#define FF 4096
#define HH 16
#define HD 64
#define KS 512                 // selected tokens per batch (T * 0.125)
#define DQ 256                 // D/4 predictor hidden
#define ROWS (BB*KS)           // 2048
#define NTOK (BB*TT)           // 16384

// ---------------- device scratch (static, no runtime alloc) ----------------
__device__ float g_scores[NTOK];
__device__ float g_tgt[NTOK];
__device__ int   g_idx[ROWS];
__device__ float g_gate[ROWS];
__device__ float g_sel[ROWS*DD];
__device__ float g_a[ROWS*DD];
__device__ float g_q[ROWS*DD];
__device__ float g_k[ROWS*DD];
__device__ float g_v[ROWS*DD];
__device__ float g_att[(size_t)BB*HH*KS*KS];
__device__ float g_pv[ROWS*DD];
__device__ float g_h[ROWS*DD];
__device__ float g_m[ROWS*DD];
__device__ float g_gb[ROWS*FF];
__device__ float g_ub[ROWS*FF];
__device__ float g_bo[ROWS*DD];
__device__ float g_h1[(size_t)NTOK*DQ];
__device__ float g_pred[NTOK];

// ---------------- helpers ----------------
__device__ __forceinline__ float gelu_tanh(float x) {
    float x3 = x*x*x;
    return 0.5f * x * (1.f + tanhf(0.7978845608028654f * (x + 0.044715f * x3)));
}
__device__ __forceinline__ float bce_term(float x, float t) {
    return fmaxf(x, 0.f) - x*t + log1pf(expf(-fabsf(x)));
}
__device__ __forceinline__ uint32_t f2tf32(float x) {
    uint32_t r;
    asm("cvt.rna.tf32.f32 %0, %1;" : "=r"(r) : "f"(x));
    return r;
}

// ---------------- K1: router scores = hs @ router_w ----------------
__global__ void scores_kernel(const float* __restrict__ hs, const float* __restrict__ rw,
                              float* __restrict__ scores) {
    int warp = (blockIdx.x * blockDim.x + threadIdx.x) >> 5;
    int lane = threadIdx.x & 31;
    if (warp >= NTOK) return;
    const float4* row = (const float4*)(hs + (size_t)warp * DD);
    const float4* w4  = (const float4*)rw;
    float s = 0.f;
    #pragma unroll 4
    for (int i = lane; i < DD/4; i += 32) {
        float4 a = row[i], b = w4[i];
        s += a.x*b.x + a.y*b.y + a.z*b.z + a.w*b.w;
    }
    #pragma unroll
    for (int o = 16; o; o >>= 1) s += __shfl_xor_sync(0xffffffffu, s, o);
    if (lane == 0) scores[warp] = s;
}

// ---------------- K2: per-batch top-k via bitonic sort ----------------
__device__ __forceinline__ bool desc_first(float v1, int i1, float v2, int i2) {
    return (v1 > v2) || (v1 == v2 && i1 < i2);
}
__global__ void topk_kernel(const float* __restrict__ scores, float* __restrict__ tgt,
                            int* __restrict__ idxo, float* __restrict__ gateo) {
    __shared__ float sv[TT];
    __shared__ int   si[TT];
    int b = blockIdx.x, tid = threadIdx.x;
    const float* sc = scores + (size_t)b * TT;
    for (int i = tid; i < TT; i += 1024) {
        sv[i] = sc[i]; si[i] = i; tgt[(size_t)b*TT + i] = 0.f;
    }
    __syncthreads();
    for (int kk = 2; kk <= TT; kk <<= 1) {
        for (int j = kk >> 1; j > 0; j >>= 1) {
            for (int i = tid; i < TT; i += 1024) {
                int ixj = i ^ j;
                if (ixj > i) {
                    bool dirDesc = ((i & kk) == 0);
                    float v1 = sv[i], v2 = sv[ixj];
                    int   i1 = si[i], i2 = si[ixj];
                    bool first = desc_first(v1, i1, v2, i2);
                    bool sw = dirDesc ? (!first) : first;
                    if (sw) { sv[i]=v2; sv[ixj]=v1; si[i]=i2; si[ixj]=i1; }
                }
            }
            __syncthreads();
        }
    }
    for (int i = tid; i < KS; i += 1024) tgt[(size_t)b*TT + si[i]] = 1.f;
    __syncthreads();
    for (int kk = 2; kk <= KS; kk <<= 1) {
        for (int j = kk >> 1; j > 0; j >>= 1) {
            if (tid < KS) {
                int i = tid, ixj = i ^ j;
                if (ixj > i) {
                    bool asc = ((i & kk) == 0);
                    int a = si[i], c = si[ixj];
                    bool sw = asc ? (a > c) : (a < c);
                    if (sw) { si[i] = c; si[ixj] = a; }
                }
            }
            __syncthreads();
        }
    }
    for (int i = tid; i < KS; i += 1024) {
        int ix = si[i];
        idxo[b*KS + i] = ix;
        float s = sc[ix];
        gateo[b*KS + i] = 1.f / (1.f + expf(-s));
    }
}

// ---------------- K3: copy hidden -> out ----------------
__global__ void copy_kernel(const float4* __restrict__ src, float4* __restrict__ dst, int n4) {
    int stride = gridDim.x * blockDim.x;
    for (int i = blockIdx.x * blockDim.x + threadIdx.x; i < n4; i += stride)
        dst[i] = src[i];
}

// ---------------- K4: gather selected rows ----------------
__global__ void gather_kernel(const float* __restrict__ hs, const int* __restrict__ idx,
                              float* __restrict__ sel) {
    int r = blockIdx.x;
    int b = r / KS;
    int pos = idx[r];
    const float4* src = (const float4*)(hs + ((size_t)b*TT + pos) * DD);
    float4* dst = (float4*)(sel + (size_t)r * DD);
    dst[threadIdx.x] = src[threadIdx.x];
}

// ---------------- K5: rmsnorm ----------------
__global__ void rmsnorm_kernel(const float* __restrict__ in, const float* __restrict__ g,
                               float* __restrict__ out) {
    __shared__ float red[8];
    int r = blockIdx.x, tid = threadIdx.x;
    const float4* x4 = (const float4*)(in + (size_t)r * DD);
    float4 x = x4[tid];
    float ss = x.x*x.x + x.y*x.y + x.z*x.z + x.w*x.w;
    #pragma unroll
    for (int o = 16; o; o >>= 1) ss += __shfl_xor_sync(0xffffffffu, ss, o);
    if ((tid & 31) == 0) red[tid >> 5] = ss;
    __syncthreads();
    if (tid < 8) {
        float v = red[tid];
        #pragma unroll
        for (int o = 4; o; o >>= 1) v += __shfl_xor_sync(0xffu, v, o);
        if (tid == 0) red[0] = v;
    }
    __syncthreads();
    float rs = rsqrtf(red[0] / (float)DD + 1e-6f);
    const float4* g4 = (const float4*)g;
    float4 gg = g4[tid];
    float4 o4 = make_float4(x.x*rs*gg.x, x.y*rs*gg.y, x.z*rs*gg.z, x.w*rs*gg.w);
    ((float4*)(out + (size_t)r * DD))[tid] = o4;
}

// ---------------- K6: TF32 tensor-core GEMM 128x128x32 ----------------
// C[M,N] = A[M,K] @ B[K,N], row-major. epi: 0 none, 1 gelu(acc+bias[col]), 2 acc+resid[row,col]
#define BM 128
#define BN 128
#define BKT 32
#define APAD 8
#define LDA_S (BM + APAD)   // 136
#define LDB_S (BN + APAD)   // 136

__global__ __launch_bounds__(256)
void mma_gemm(const float* __restrict__ A, const float* __restrict__ B, float* __restrict__ C,
              int M, int N, int K, const float* __restrict__ aux, int epi) {
    __shared__ uint32_t As[BKT][LDA_S];
    __shared__ uint32_t Bs[BKT][LDB_S];
    int tid = threadIdx.x;
    int m0 = blockIdx.y * BM, n0 = blockIdx.x * BN;
    int warp = tid >> 5, lane = tid & 31;
    int wm = (warp >> 2) * 64;   // 0 or 64
    int wn = (warp & 3) * 32;    // 0,32,64,96
    int g = lane >> 2, c = lane & 3;

    float acc[4][4][4];
    #pragma unroll
    for (int i = 0; i < 4; i++)
        #pragma unroll
        for (int j = 0; j < 4; j++)
            #pragma unroll
            for (int r = 0; r < 4; r++) acc[i][j][r] = 0.f;

    // global load mapping
    int aRow = tid >> 3;          // 0..31
    int aCol = (tid & 7) * 4;     // 0..28
    int bRow = tid >> 5;          // 0..7
    int bCol = (tid & 31) * 4;    // 0..124

    const float* Ag = A + (size_t)(m0 + aRow) * K + aCol;
    const float* Bg = B + (size_t)bRow * N + n0 + bCol;

    for (int kt = 0; kt < K; kt += BKT) {
        // load A tile (128x32) transposed into As[k][m]
        float4 av[4];
        #pragma unroll
        for (int p = 0; p < 4; p++)
            av[p] = *(const float4*)(Ag + (size_t)(p*32) * K);
        float4 bv[4];
        #pragma unroll
        for (int p = 0; p < 4; p++)
            bv[p] = *(const float4*)(Bg + (size_t)(p*8) * N);
        Ag += BKT; Bg += (size_t)BKT * N;
        __syncthreads();
        #pragma unroll
        for (int p = 0; p < 4; p++) {
            int m = aRow + p*32;
            As[aCol+0][m] = f2tf32(av[p].x);
            As[aCol+1][m] = f2tf32(av[p].y);
            As[aCol+2][m] = f2tf32(av[p].z);
            As[aCol+3][m] = f2tf32(av[p].w);
        }
        #pragma unroll
        for (int p = 0; p < 4; p++) {
            int r = bRow + p*8;
            Bs[r][bCol+0] = f2tf32(bv[p].x);
            Bs[r][bCol+1] = f2tf32(bv[p].y);
            Bs[r][bCol+2] = f2tf32(bv[p].z);
            Bs[r][bCol+3] = f2tf32(bv[p].w);
        }
        __syncthreads();

        #pragma unroll
        for (int ks = 0; ks < BKT; ks += 8) {
            uint32_t af[4][4];
            uint32_t bf[4][2];
            #pragma unroll
            for (int i = 0; i < 4; i++) {
                int mb = wm + i*16;
                af[i][0] = As[ks+c  ][mb+g];
                af[i][1] = As[ks+c  ][mb+g+8];
                af[i][2] = As[ks+c+4][mb+g];
                af[i][3] = As[ks+c+4][mb+g+8];
            }
            #pragma unroll
            for (int j = 0; j < 4; j++) {
                int nb = wn + j*8;
                bf[j][0] = Bs[ks+c  ][nb+g];
                bf[j][1] = Bs[ks+c+4][nb+g];
            }
            #pragma unroll
            for (int i = 0; i < 4; i++)
                #pragma unroll
                for (int j = 0; j < 4; j++) {
                    asm volatile(
                        "mma.sync.aligned.m16n8k8.row.col.f32.tf32.tf32.f32 "
                        "{%0,%1,%2,%3}, {%4,%5,%6,%7}, {%8,%9}, {%0,%1,%2,%3};"
                        : "+f"(acc[i][j][0]), "+f"(acc[i][j][1]),
                          "+f"(acc[i][j][2]), "+f"(acc[i][j][3])
                        : "r"(af[i][0]), "r"(af[i][1]), "r"(af[i][2]), "r"(af[i][3]),
                          "r"(bf[j][0]), "r"(bf[j][1]));
                }
        }
    }

    // epilogue
    #pragma unroll
    for (int i = 0; i < 4; i++) {
        int r0 = m0 + wm + i*16 + g;
        #pragma unroll
        for (int j = 0; j < 4; j++) {
            int col = n0 + wn + j*8 + c*2;
            float2 lo = make_float2(acc[i][j][0], acc[i][j][1]);
            float2 hi = make_float2(acc[i][j][2], acc[i][j][3]);
            if (epi == 1) {
                float b0 = aux[col], b1 = aux[col+1];
                lo.x = gelu_tanh(lo.x + b0); lo.y = gelu_tanh(lo.y + b1);
                hi.x = gelu_tanh(hi.x + b0); hi.y = gelu_tanh(hi.y + b1);
            } else if (epi == 2) {
                const float2 s0 = *(const float2*)&aux[(size_t)r0*N + col];
                const float2 s1 = *(const float2*)&aux[(size_t)(r0+8)*N + col];
                lo.x += s0.x; lo.y += s0.y; hi.x += s1.x; hi.y += s1.y;
            }
            *(float2*)&C[(size_t)r0*N + col] = lo;
            *(float2*)&C[(size_t)(r0+8)*N + col] = hi;
        }
    }
}

// ---------------- K7: RoPE in place ----------------
__global__ void rope_kernel(float* __restrict__ buf, const int* __restrict__ idx) {
    int r = blockIdx.x;
    float pos = (float)idx[r];
    float* base = buf + (size_t)r * DD;
    for (int c = threadIdx.x; c < 512; c += 256) {
        int h = c >> 5, i = c & 31;
        float inv = powf(10000.f, -(float)i / 32.f);
        float ang = pos * inv;
        float s, co; sincosf(ang, &s, &co);
        float* p = base + h * 64;
        float x1 = p[i], x2 = p[i + 32];
        p[i]      = x1*co - x2*s;
        p[i + 32] = x2*co + x1*s;
    }
}

// ---------------- K8: S = scale * Q K^T with causal mask ----------------
__global__ __launch_bounds__(256)
void qk_kernel(const float* __restrict__ q, const float* __restrict__ k,
               float* __restrict__ att) {
    __shared__ float Qs[64][65];
    __shared__ float Ks[64][65];
    int kt = blockIdx.x, qt = blockIdx.y, bh = blockIdx.z;
    int b = bh >> 4, h = bh & 15;
    int tid = threadIdx.x;
    #pragma unroll
    for (int t = 0; t < 16; t++) {
        int e = t*256 + tid, row = e >> 6, col = e & 63;
        Qs[row][col] = q[((size_t)(b*KS + qt*64 + row))*DD + h*64 + col];
        Ks[row][col] = k[((size_t)(b*KS + kt*64 + row))*DD + h*64 + col];
    }
    __syncthreads();
    int ty = tid >> 4, tx = tid & 15;
    float acc[4][4];
    #pragma unroll
    for (int i = 0; i < 4; i++)
        #pragma unroll
        for (int j = 0; j < 4; j++) acc[i][j] = 0.f;
    #pragma unroll 4
    for (int d = 0; d < 64; d++) {
        float qa[4], kb[4];
        #pragma unroll
        for (int i = 0; i < 4; i++) { qa[i] = Qs[ty*4+i][d]; kb[i] = Ks[tx*4+i][d]; }
        #pragma unroll
        for (int i = 0; i < 4; i++)
            #pragma unroll
            for (int j = 0; j < 4; j++) acc[i][j] += qa[i] * kb[j];
    }
    const float scale = 0.125f;
    #pragma unroll
    for (int i = 0; i < 4; i++) {
        int qrow = qt*64 + ty*4 + i;
        #pragma unroll
        for (int j = 0; j < 4; j++) {
            int krow = kt*64 + tx*4 + j;
            float val = (krow <= qrow) ? acc[i][j] * scale : -1e9f;
            att[((size_t)bh*KS + qrow)*KS + krow] = val;
        }
    }
}

// ---------------- K9: softmax per row (512 wide) ----------------
__global__ void softmax_kernel(float* __restrict__ att) {
    int warp = (blockIdx.x * blockDim.x + threadIdx.x) >> 5;
    int lane = threadIdx.x & 31;
    float* p = att + (size_t)warp * KS;
    float v[16];
    float mx = -3.4e38f;
    #pragma unroll
    for (int l = 0; l < 16; l++) { v[l] = p[lane + l*32]; mx = fmaxf(mx, v[l]); }
    #pragma unroll
    for (int o = 16; o; o >>= 1) mx = fmaxf(mx, __shfl_xor_sync(0xffffffffu, mx, o));
    float sum = 0.f;
    #pragma unroll
    for (int l = 0; l < 16; l++) { v[l] = expf(v[l] - mx); sum += v[l]; }
    #pragma unroll
    for (int o = 16; o; o >>= 1) sum += __shfl_xor_sync(0xffffffffu, sum, o);
    float inv = 1.f / sum;
    #pragma unroll
    for (int l = 0; l < 16; l++) p[lane + l*32] = v[l] * inv;
}

// ---------------- K10: O = P @ V (skips fully masked tiles) ----------------
__global__ __launch_bounds__(256)
void pv_kernel(const float* __restrict__ att, const float* __restrict__ v,
               float* __restrict__ pv) {
    __shared__ float Ps[64][65];
    __shared__ float Vs[64][65];
    int qt = blockIdx.x, bh = blockIdx.y;
    int b = bh >> 4, h = bh & 15;
    int tid = threadIdx.x;
    int ty = tid >> 4, tx = tid & 15;
    float acc[4][4];
    #pragma unroll
    for (int i = 0; i < 4; i++)
        #pragma unroll
        for (int j = 0; j < 4; j++) acc[i][j] = 0.f;
    for (int kt = 0; kt <= qt; kt++) {
        __syncthreads();
        #pragma unroll
        for (int t = 0; t < 16; t++) {
            int e = t*256 + tid, row = e >> 6, col = e & 63;
            Ps[row][col] = att[((size_t)bh*KS + qt*64 + row)*KS + kt*64 + col];
            Vs[row][col] = v[((size_t)(b*KS + kt*64 + row))*DD + h*64 + col];
        }
        __syncthreads();
        #pragma unroll 4
        for (int d = 0; d < 64; d++) {
            float pa[4], vb[4];
            #pragma unroll
            for (int i = 0; i < 4; i++) { pa[i] = Ps[ty*4+i][d]; vb[i] = Vs[d][tx*4+i]; }
            #pragma unroll
            for (int i = 0; i < 4; i++)
                #pragma unroll
                for (int j = 0; j < 4; j++) acc[i][j] += pa[i] * vb[j];
        }
    }
    #pragma unroll
    for (int i = 0; i < 4; i++)
        #pragma unroll
        for (int j = 0; j < 4; j++)
            pv[((size_t)(b*KS + qt*64 + ty*4 + i))*DD + h*64 + tx*4 + j] = acc[i][j];
}

// ---------------- K11: silu(gate) * up in place ----------------
__global__ void silu_mul_kernel(float4* __restrict__ gb, const float4* __restrict__ ub, int n4) {
    int i = blockIdx.x * blockDim.x + threadIdx.x;
    if (i >= n4) return;
    float4 g = gb[i], u = ub[i];
    g.x = g.x / (1.f + expf(-g.x)) * u.x;
    g.y = g.y / (1.f + expf(-g.y)) * u.y;
    g.z = g.z / (1.f + expf(-g.z)) * u.z;
    g.w = g.w / (1.f + expf(-g.w)) * u.w;
    gb[i] = g;
}

// ---------------- K12: scatter updated rows into out ----------------
__global__ void scatter_kernel(const float* __restrict__ sel, const float* __restrict__ bo,
                               const int* __restrict__ idx, const float* __restrict__ gate,
                               float* __restrict__ out) {
    int r = blockIdx.x;
    int b = r / KS;
    int pos = idx[r];
    float ga = gate[r];
    const float4* s4 = (const float4*)(sel + (size_t)r * DD);
    const float4* b4 = (const float4*)(bo  + (size_t)r * DD);
    float4* o4 = (float4*)(out + ((size_t)b*TT + pos) * DD);
    float4 s = s4[threadIdx.x], bb = b4[threadIdx.x];
    float4 u = make_float4(s.x + ga*(bb.x - s.x), s.y + ga*(bb.y - s.y),
                           s.z + ga*(bb.z - s.z), s.w + ga*(bb.w - s.w));
    o4[threadIdx.x] = u;
}

// ---------------- K13: predictor logits + per-row BCE ----------------
__global__ void predrow_kernel(const float* __restrict__ h1, const float* __restrict__ fc2w,
                               const float* __restrict__ fc2b, const float* __restrict__ tgt,
                               float* __restrict__ pred) {
    int warp = (blockIdx.x * blockDim.x + threadIdx.x) >> 5;
    int lane = threadIdx.x & 31;
    if (warp >= NTOK) return;
    const float* row = h1 + (size_t)warp * DQ;
    float s = 0.f;
    #pragma unroll
    for (int i = lane; i < DQ; i += 32) s += row[i] * fc2w[i];
    #pragma unroll
    for (int o = 16; o; o >>= 1) s += __shfl_xor_sync(0xffffffffu, s, o);
    if (lane == 0) {
        float x = s + fc2b[0];
        pred[warp] = bce_term(x, tgt[warp]);
    }
}

// ---------------- K14: deterministic loss reduce ----------------
__global__ void loss_reduce(const float* __restrict__ scores, const float* __restrict__ tgt,
                            const float* __restrict__ pred, float* __restrict__ out_aux) {
    __shared__ float sm_main[1024];
    __shared__ float sm_pred[1024];
    int tid = threadIdx.x;
    float sm = 0.f, sp = 0.f;
    for (int i = tid; i < NTOK; i += 1024) {
        sm += bce_term(scores[i], tgt[i]);
        sp += pred[i];
    }
    sm_main[tid] = sm; sm_pred[tid] = sp;
    __syncthreads();
    for (int s = 512; s > 0; s >>= 1) {
        if (tid < s) { sm_main[tid] += sm_main[tid+s]; sm_pred[tid] += sm_pred[tid+s]; }
        __syncthreads();
    }
    if (tid == 0)
        out_aux[0] = 0.01f * (sm_main[0] + sm_pred[0]) / (float)NTOK;
}

// ---------------- host launch ----------------
extern "C" void kernel_launch(void* const* d_in, const int* in_sizes, int n_in,
                              void* d_out, int out_size) {
    const float* hs   = (const float*)d_in[0];
    const float* rw   = (const float*)d_in[1];
    const float* fc1w = (const float*)d_in[2];
    const float* fc1b = (const float*)d_in[3];
    const float* fc2w = (const float*)d_in[4];
    const float* fc2b = (const float*)d_in[5];
    const float* ln1  = (const float*)d_in[6];
    const float* ln2  = (const float*)d_in[7];
    const float* wq   = (const float*)d_in[8];
    const float* wk   = (const float*)d_in[9];
    const float* wv   = (const float*)d_in[10];
    const float* wo   = (const float*)d_in[11];
    const float* wg   = (const float*)d_in[12];
    const float* wu   = (const float*)d_in[13];
    const float* wd   = (const float*)d_in[14];
    float* out = (float*)d_out;

    float *scores, *tgt, *gate, *sel, *a, *q, *k, *v, *att, *pv, *h, *m, *gb, *ub, *bo, *h1, *pred;
    int* idx;
    cudaGetSymbolAddress((void**)&scores, g_scores);
    cudaGetSymbolAddress((void**)&tgt,    g_tgt);
    cudaGetSymbolAddress((void**)&idx,    g_idx);
    cudaGetSymbolAddress((void**)&gate,   g_gate);
    cudaGetSymbolAddress((void**)&sel,    g_sel);
    cudaGetSymbolAddress((void**)&a,      g_a);
    cudaGetSymbolAddress((void**)&q,      g_q);
    cudaGetSymbolAddress((void**)&k,      g_k);
    cudaGetSymbolAddress((void**)&v,      g_v);
    cudaGetSymbolAddress((void**)&att,    g_att);
    cudaGetSymbolAddress((void**)&pv,     g_pv);
    cudaGetSymbolAddress((void**)&h,      g_h);
    cudaGetSymbolAddress((void**)&m,      g_m);
    cudaGetSymbolAddress((void**)&gb,     g_gb);
    cudaGetSymbolAddress((void**)&ub,     g_ub);
    cudaGetSymbolAddress((void**)&bo,     g_bo);
    cudaGetSymbolAddress((void**)&h1,     g_h1);
    cudaGetSymbolAddress((void**)&pred,   g_pred);

    // router + top-k
    scores_kernel<<<NTOK/8, 256>>>(hs, rw, scores);
    topk_kernel<<<BB, 1024>>>(scores, tgt, idx, gate);

    // copy full hidden to output; gather selected rows
    copy_kernel<<<4096, 256>>>((const float4*)hs, (float4*)out, NTOK*DD/4);
    gather_kernel<<<ROWS, 256>>>(hs, idx, sel);

    // decoder block
    rmsnorm_kernel<<<ROWS, 256>>>(sel, ln1, a);
    mma_gemm<<<dim3(DD/BN, ROWS/BM), 256>>>(a, wq, q, ROWS, DD, DD, nullptr, 0);
    mma_gemm<<<dim3(DD/BN, ROWS/BM), 256>>>(a, wk, k, ROWS, DD, DD, nullptr, 0);
    mma_gemm<<<dim3(DD/BN, ROWS/BM), 256>>>(a, wv, v, ROWS, DD, DD, nullptr, 0);
    rope_kernel<<<ROWS, 256>>>(q, idx);
    rope_kernel<<<ROWS, 256>>>(k, idx);
    qk_kernel<<<dim3(8, 8, BB*HH), 256>>>(q, k, att);
    softmax_kernel<<<BB*HH*KS/8, 256>>>(att);
    pv_kernel<<<dim3(8, BB*HH), 256>>>(att, v, pv);
    mma_gemm<<<dim3(DD/BN, ROWS/BM), 256>>>(pv, wo, h, ROWS, DD, DD, sel, 2);   // h = sel + attn@wo

    rmsnorm_kernel<<<ROWS, 256>>>(h, ln2, m);
    mma_gemm<<<dim3(FF/BN, ROWS/BM), 256>>>(m, wg, gb, ROWS, FF, DD, nullptr, 0);
    mma_gemm<<<dim3(FF/BN, ROWS/BM), 256>>>(m, wu, ub, ROWS, FF, DD, nullptr, 0);
    silu_mul_kernel<<<(ROWS*FF/4 + 255)/256, 256>>>((float4*)gb, (const float4*)ub, ROWS*FF/4);
    mma_gemm<<<dim3(DD/BN, ROWS/BM), 256>>>(gb, wd, bo, ROWS, DD, FF, h, 2);    // block_out = h + (..)@wd

    scatter_kernel<<<ROWS, 256>>>(sel, bo, idx, gate, out);

    // aux losses (predictor path)
    mma_gemm<<<dim3(DQ/BN, NTOK/BM), 256>>>(hs, fc1w, h1, NTOK, DQ, DD, fc1b, 1);
    predrow_kernel<<<NTOK/8, 256>>>(h1, fc2w, fc2b, tgt, pred);
    loss_reduce<<<1, 1024>>>(scores, tgt, pred, out + (size_t)NTOK*DD);
}

// round 3
// speedup vs baseline: 2.8730x; 1.2652x over previous
#include <cuda_runtime.h>
#include <math.h>
#include <stdint.h>

// ---------------- problem constants ----------------
#define BB 4
#define TT 4096
#define DD 1024
#define FF 4096
#define HH 16
#define HD 64
#define KS 512
#define DQ 256
#define ROWS (BB*KS)           // 2048
#define NTOK (BB*TT)           // 16384

// ---------------- device scratch ----------------
__device__ float g_scores[NTOK];
__device__ float g_tgt[NTOK];
__device__ int   g_idx[ROWS];
__device__ float g_gate[ROWS];
__device__ float g_sel[ROWS*DD];
__device__ float g_a[ROWS*DD];
__device__ float g_q[ROWS*DD];
__device__ float g_k[ROWS*DD];
__device__ float g_v[ROWS*DD];
__device__ float g_att[(size_t)BB*HH*KS*KS];
__device__ float g_pv[ROWS*DD];
__device__ float g_h[ROWS*DD];
__device__ float g_m[ROWS*DD];
__device__ float g_gb[ROWS*FF];
__device__ float g_ub[ROWS*FF];
__device__ float g_bo[ROWS*DD];
__device__ float g_h1[(size_t)NTOK*DQ];
__device__ float g_pred[NTOK];

// ---------------- helpers ----------------
__device__ __forceinline__ float gelu_tanh(float x) {
    float x3 = x*x*x;
    return 0.5f * x * (1.f + tanhf(0.7978845608028654f * (x + 0.044715f * x3)));
}
__device__ __forceinline__ float bce_term(float x, float t) {
    return fmaxf(x, 0.f) - x*t + log1pf(expf(-fabsf(x)));
}
__device__ __forceinline__ void cpa16(uint32_t s, const float* g) {
    asm volatile("cp.async.cg.shared.global [%0], [%1], 16;" :: "r"(s), "l"(g));
}
__device__ __forceinline__ void mma_tf32(float* d, uint32_t a0, uint32_t a1, uint32_t a2, uint32_t a3,
                                         uint32_t b0, uint32_t b1) {
    asm volatile(
        "mma.sync.aligned.m16n8k8.row.col.f32.tf32.tf32.f32 "
        "{%0,%1,%2,%3}, {%4,%5,%6,%7}, {%8,%9}, {%0,%1,%2,%3};"
        : "+f"(d[0]), "+f"(d[1]), "+f"(d[2]), "+f"(d[3])
        : "r"(a0), "r"(a1), "r"(a2), "r"(a3), "r"(b0), "r"(b1));
}

// ---------------- K1: router scores ----------------
__global__ void scores_kernel(const float* __restrict__ hs, const float* __restrict__ rw,
                              float* __restrict__ scores) {
    int warp = (blockIdx.x * blockDim.x + threadIdx.x) >> 5;
    int lane = threadIdx.x & 31;
    if (warp >= NTOK) return;
    const float4* row = (const float4*)(hs + (size_t)warp * DD);
    const float4* w4  = (const float4*)rw;
    float s = 0.f;
    #pragma unroll 4
    for (int i = lane; i < DD/4; i += 32) {
        float4 a = row[i], b = w4[i];
        s += a.x*b.x + a.y*b.y + a.z*b.z + a.w*b.w;
    }
    #pragma unroll
    for (int o = 16; o; o >>= 1) s += __shfl_xor_sync(0xffffffffu, s, o);
    if (lane == 0) scores[warp] = s;
}

// ---------------- K2: radix-select top-k + ascending compaction ----------------
__global__ void topk_radix(const float* __restrict__ scores, float* __restrict__ tgt,
                           int* __restrict__ idxo, float* __restrict__ gateo) {
    __shared__ unsigned su[TT];          // 16KB
    __shared__ int hist[256];
    __shared__ int wsum[32];
    __shared__ unsigned s_prefix;
    __shared__ int s_remain;
    int b = blockIdx.x, tid = threadIdx.x;   // 1024 threads
    const float* sc = scores + (size_t)b * TT;

    for (int i = tid; i < TT; i += 1024) {
        unsigned bits = __float_as_uint(sc[i]);
        unsigned mask = (unsigned)((int)bits >> 31) | 0x80000000u;
        su[i] = bits ^ mask;     // monotonic map: larger float -> larger uint
    }
    if (tid == 0) { s_prefix = 0u; s_remain = KS; }
    __syncthreads();

    #pragma unroll
    for (int p = 24; p >= 0; p -= 8) {
        if (tid < 256) hist[tid] = 0;
        __syncthreads();
        unsigned pref = s_prefix;
        for (int i = tid; i < TT; i += 1024) {
            unsigned u = su[i];
            if (p == 24 || (u >> (p + 8)) == (pref >> (p + 8)))
                atomicAdd(&hist[(u >> p) & 255], 1);
        }
        __syncthreads();
        if (tid == 0) {
            int rem = s_remain;
            int bin = 255;
            for (;;) {
                int c = hist[bin];
                if (rem <= c) break;
                rem -= c; bin--;
            }
            s_prefix = pref | ((unsigned)bin << p);
            s_remain = rem;
        }
        __syncthreads();
    }
    unsigned thr = s_prefix;   // exact kth-largest key (values distinct)

    // compaction: ascending index order preserved
    int base = tid * 4;
    int flg[4]; int cnt = 0;
    #pragma unroll
    for (int j = 0; j < 4; j++) { flg[j] = (su[base + j] >= thr) ? 1 : 0; cnt += flg[j]; }
    int lane = tid & 31, warp = tid >> 5;
    int inc = cnt;
    #pragma unroll
    for (int o = 1; o < 32; o <<= 1) {
        int n2 = __shfl_up_sync(0xffffffffu, inc, o);
        if (lane >= o) inc += n2;
    }
    if (lane == 31) wsum[warp] = inc;
    __syncthreads();
    if (tid < 32) {
        int v = wsum[tid];
        #pragma unroll
        for (int o = 1; o < 32; o <<= 1) {
            int n2 = __shfl_up_sync(0xffffffffu, v, o);
            if (tid >= o) v += n2;
        }
        wsum[tid] = v;
    }
    __syncthreads();
    int off = inc - cnt + (warp ? wsum[warp - 1] : 0);
    #pragma unroll
    for (int j = 0; j < 4; j++) {
        tgt[(size_t)b*TT + base + j] = flg[j] ? 1.f : 0.f;
        if (flg[j]) {
            idxo[b*KS + off] = base + j;
            float s = sc[base + j];
            gateo[b*KS + off] = 1.f / (1.f + expf(-s));
            off++;
        }
    }
}

// ---------------- K3: copy hidden -> out ----------------
__global__ void copy_kernel(const float4* __restrict__ src, float4* __restrict__ dst, int n4) {
    int stride = gridDim.x * blockDim.x;
    for (int i = blockIdx.x * blockDim.x + threadIdx.x; i < n4; i += stride)
        dst[i] = src[i];
}

// ---------------- K4: gather ----------------
__global__ void gather_kernel(const float* __restrict__ hs, const int* __restrict__ idx,
                              float* __restrict__ sel) {
    int r = blockIdx.x;
    int b = r / KS;
    int pos = idx[r];
    const float4* src = (const float4*)(hs + ((size_t)b*TT + pos) * DD);
    float4* dst = (float4*)(sel + (size_t)r * DD);
    dst[threadIdx.x] = src[threadIdx.x];
}

// ---------------- K5: rmsnorm ----------------
__global__ void rmsnorm_kernel(const float* __restrict__ in, const float* __restrict__ g,
                               float* __restrict__ out) {
    __shared__ float red[8];
    int r = blockIdx.x, tid = threadIdx.x;
    const float4* x4 = (const float4*)(in + (size_t)r * DD);
    float4 x = x4[tid];
    float ss = x.x*x.x + x.y*x.y + x.z*x.z + x.w*x.w;
    #pragma unroll
    for (int o = 16; o; o >>= 1) ss += __shfl_xor_sync(0xffffffffu, ss, o);
    if ((tid & 31) == 0) red[tid >> 5] = ss;
    __syncthreads();
    if (tid < 8) {
        float v = red[tid];
        #pragma unroll
        for (int o = 4; o; o >>= 1) v += __shfl_xor_sync(0xffu, v, o);
        if (tid == 0) red[0] = v;
    }
    __syncthreads();
    float rs = rsqrtf(red[0] / (float)DD + 1e-6f);
    const float4* g4 = (const float4*)g;
    float4 gg = g4[tid];
    float4 o4 = make_float4(x.x*rs*gg.x, x.y*rs*gg.y, x.z*rs*gg.z, x.w*rs*gg.w);
    ((float4*)(out + (size_t)r * DD))[tid] = o4;
}

// ---------------- K6: TF32 GEMM 128x128x32, cp.async double-buffered ----------------
#define AS_LD 36
#define BS_LD 136
#define A_TILE (128*AS_LD)   // 4608 floats
#define B_TILE (32*BS_LD)    // 4352 floats
#define GEMM_SMEM ((2*A_TILE + 2*B_TILE)*4)   // 71680 bytes

__global__ __launch_bounds__(256)
void mma_gemm(const float* __restrict__ A, const float* __restrict__ B, float* __restrict__ C,
              int M, int N, int K, const float* __restrict__ aux, int epi) {
    extern __shared__ float dynsm[];
    float* As = dynsm;                 // [2][128][36]
    float* Bs = dynsm + 2*A_TILE;      // [2][32][136]

    int tid = threadIdx.x;
    int m0 = blockIdx.y * 128, n0 = blockIdx.x * 128;
    int warp = tid >> 5, lane = tid & 31;
    int wm = (warp >> 2) * 64;
    int wn = (warp & 3) * 32;
    int g = lane >> 2, c = lane & 3;

    float acc[4][4][4];
    #pragma unroll
    for (int i = 0; i < 4; i++)
        #pragma unroll
        for (int j = 0; j < 4; j++)
            #pragma unroll
            for (int r = 0; r < 4; r++) acc[i][j][r] = 0.f;

    // cp.async mappings
    int aRow = tid >> 1;             // 0..127
    int aSeg = (tid & 1) * 16;       // 0 or 16
    int bRow = tid >> 3;             // 0..31
    int bSeg = (tid & 7) * 16;       // 0..112

    uint32_t asBase = (uint32_t)__cvta_generic_to_shared(As);
    uint32_t bsBase = (uint32_t)__cvta_generic_to_shared(Bs);

    int nk = K / 32;

    // prefetch stage 0
    {
        const float* Ag = A + (size_t)(m0 + aRow) * K + aSeg;
        uint32_t ad = asBase + (aRow*AS_LD + aSeg) * 4;
        #pragma unroll
        for (int i = 0; i < 4; i++) cpa16(ad + i*16, Ag + i*4);
        const float* Bg = B + (size_t)bRow * N + n0 + bSeg;
        uint32_t bd = bsBase + (bRow*BS_LD + bSeg) * 4;
        #pragma unroll
        for (int i = 0; i < 4; i++) cpa16(bd + i*16, Bg + i*4);
        asm volatile("cp.async.commit_group;" ::: "memory");
    }

    for (int kt = 0; kt < nk; kt++) {
        if (kt + 1 < nk) {
            int st = (kt + 1) & 1;
            const float* Ag = A + (size_t)(m0 + aRow) * K + (kt+1)*32 + aSeg;
            uint32_t ad = asBase + (st*A_TILE + aRow*AS_LD + aSeg) * 4;
            #pragma unroll
            for (int i = 0; i < 4; i++) cpa16(ad + i*16, Ag + i*4);
            const float* Bg = B + (size_t)((kt+1)*32 + bRow) * N + n0 + bSeg;
            uint32_t bd = bsBase + (st*B_TILE + bRow*BS_LD + bSeg) * 4;
            #pragma unroll
            for (int i = 0; i < 4; i++) cpa16(bd + i*16, Bg + i*4);
            asm volatile("cp.async.commit_group;" ::: "memory");
            asm volatile("cp.async.wait_group 1;" ::: "memory");
        } else {
            asm volatile("cp.async.wait_group 0;" ::: "memory");
        }
        __syncthreads();

        const float* as = As + (kt & 1) * A_TILE;
        const float* bs = Bs + (kt & 1) * B_TILE;
        #pragma unroll
        for (int ks = 0; ks < 32; ks += 8) {
            uint32_t af[4][4], bf[4][2];
            #pragma unroll
            for (int i = 0; i < 4; i++) {
                int mb = wm + i*16;
                af[i][0] = *(const uint32_t*)&as[(mb+g  )*AS_LD + ks + c];
                af[i][1] = *(const uint32_t*)&as[(mb+g+8)*AS_LD + ks + c];
                af[i][2] = *(const uint32_t*)&as[(mb+g  )*AS_LD + ks + c + 4];
                af[i][3] = *(const uint32_t*)&as[(mb+g+8)*AS_LD + ks + c + 4];
            }
            #pragma unroll
            for (int j = 0; j < 4; j++) {
                int nb = wn + j*8;
                bf[j][0] = *(const uint32_t*)&bs[(ks+c  )*BS_LD + nb + g];
                bf[j][1] = *(const uint32_t*)&bs[(ks+c+4)*BS_LD + nb + g];
            }
            #pragma unroll
            for (int i = 0; i < 4; i++)
                #pragma unroll
                for (int j = 0; j < 4; j++)
                    mma_tf32(acc[i][j], af[i][0], af[i][1], af[i][2], af[i][3],
                             bf[j][0], bf[j][1]);
        }
        __syncthreads();
    }

    #pragma unroll
    for (int i = 0; i < 4; i++) {
        int r0 = m0 + wm + i*16 + g;
        #pragma unroll
        for (int j = 0; j < 4; j++) {
            int col = n0 + wn + j*8 + c*2;
            float2 lo = make_float2(acc[i][j][0], acc[i][j][1]);
            float2 hi = make_float2(acc[i][j][2], acc[i][j][3]);
            if (epi == 1) {
                float b0 = aux[col], b1 = aux[col+1];
                lo.x = gelu_tanh(lo.x + b0); lo.y = gelu_tanh(lo.y + b1);
                hi.x = gelu_tanh(hi.x + b0); hi.y = gelu_tanh(hi.y + b1);
            } else if (epi == 2) {
                const float2 s0 = *(const float2*)&aux[(size_t)r0*N + col];
                const float2 s1 = *(const float2*)&aux[(size_t)(r0+8)*N + col];
                lo.x += s0.x; lo.y += s0.y; hi.x += s1.x; hi.y += s1.y;
            }
            *(float2*)&C[(size_t)r0*N + col] = lo;
            *(float2*)&C[(size_t)(r0+8)*N + col] = hi;
        }
    }
}

// ---------------- K7: RoPE ----------------
__global__ void rope_kernel(float* __restrict__ buf, const int* __restrict__ idx) {
    int r = blockIdx.x;
    float pos = (float)idx[r];
    float* base = buf + (size_t)r * DD;
    for (int c = threadIdx.x; c < 512; c += 256) {
        int h = c >> 5, i = c & 31;
        float inv = powf(10000.f, -(float)i / 32.f);
        float ang = pos * inv;
        float s, co; sincosf(ang, &s, &co);
        float* p = base + h * 64;
        float x1 = p[i], x2 = p[i + 32];
        p[i]      = x1*co - x2*s;
        p[i + 32] = x2*co + x1*s;
    }
}

// ---------------- K8: QK^T (tf32 mma), causal tiles only ----------------
__global__ __launch_bounds__(256)
void qk_mma(const float* __restrict__ q, const float* __restrict__ k,
            float* __restrict__ att) {
    __shared__ float Qs[64][68];
    __shared__ float Ks[64][68];
    int kt = blockIdx.x, qt = blockIdx.y;
    if (kt > qt) return;
    int bh = blockIdx.z, b = bh >> 4, h = bh & 15;
    int tid = threadIdx.x;
    #pragma unroll
    for (int pch = 0; pch < 4; pch++) {
        int e = pch*256 + tid;
        int row = e >> 4, col = (e & 15) * 4;
        *(float4*)&Qs[row][col] = *(const float4*)&q[((size_t)(b*KS + qt*64 + row))*DD + h*64 + col];
        *(float4*)&Ks[row][col] = *(const float4*)&k[((size_t)(b*KS + kt*64 + row))*DD + h*64 + col];
    }
    __syncthreads();
    int warp = tid >> 5, lane = tid & 31, g = lane >> 2, c = lane & 3;
    int wm = (warp & 3) * 16, wn = (warp >> 2) * 32;
    float acc[4][4];
    #pragma unroll
    for (int j = 0; j < 4; j++)
        #pragma unroll
        for (int r = 0; r < 4; r++) acc[j][r] = 0.f;
    #pragma unroll
    for (int d = 0; d < 64; d += 8) {
        uint32_t a0 = *(const uint32_t*)&Qs[wm+g  ][d+c];
        uint32_t a1 = *(const uint32_t*)&Qs[wm+g+8][d+c];
        uint32_t a2 = *(const uint32_t*)&Qs[wm+g  ][d+c+4];
        uint32_t a3 = *(const uint32_t*)&Qs[wm+g+8][d+c+4];
        #pragma unroll
        for (int j = 0; j < 4; j++) {
            uint32_t b0 = *(const uint32_t*)&Ks[wn+j*8+g][d+c];
            uint32_t b1 = *(const uint32_t*)&Ks[wn+j*8+g][d+c+4];
            mma_tf32(acc[j], a0, a1, a2, a3, b0, b1);
        }
    }
    const float scale = 0.125f;
    int q0 = qt*64 + wm + g;
    #pragma unroll
    for (int j = 0; j < 4; j++) {
        int kc = kt*64 + wn + j*8 + c*2;
        float2 lo, hi;
        lo.x = (kc   <= q0  ) ? acc[j][0]*scale : -1e9f;
        lo.y = (kc+1 <= q0  ) ? acc[j][1]*scale : -1e9f;
        hi.x = (kc   <= q0+8) ? acc[j][2]*scale : -1e9f;
        hi.y = (kc+1 <= q0+8) ? acc[j][3]*scale : -1e9f;
        *(float2*)&att[((size_t)bh*KS + q0  )*KS + kc] = lo;
        *(float2*)&att[((size_t)bh*KS + q0+8)*KS + kc] = hi;
    }
}

// ---------------- K9: variable-length softmax ----------------
__global__ void softmax_kernel(float* __restrict__ att) {
    int warp = (blockIdx.x * blockDim.x + threadIdx.x) >> 5;
    int lane = threadIdx.x & 31;
    int q = warp & (KS - 1);
    int L32 = ((q >> 6) + 1) * 2;          // chunks of 32, covers kt<=qt tiles
    float* p = att + (size_t)warp * KS;
    float v[16];
    float mx = -3.4e38f;
    for (int l = 0; l < L32; l++) { v[l] = p[lane + l*32]; mx = fmaxf(mx, v[l]); }
    #pragma unroll
    for (int o = 16; o; o >>= 1) mx = fmaxf(mx, __shfl_xor_sync(0xffffffffu, mx, o));
    float sum = 0.f;
    for (int l = 0; l < L32; l++) { v[l] = expf(v[l] - mx); sum += v[l]; }
    #pragma unroll
    for (int o = 16; o; o >>= 1) sum += __shfl_xor_sync(0xffffffffu, sum, o);
    float inv = 1.f / sum;
    for (int l = 0; l < L32; l++) p[lane + l*32] = v[l] * inv;
}

// ---------------- K10: PV (tf32 mma), causal tiles only ----------------
__global__ __launch_bounds__(256)
void pv_mma(const float* __restrict__ att, const float* __restrict__ v,
            float* __restrict__ pv) {
    __shared__ float Ps[64][68];
    __shared__ float Vs[64][72];
    int qt = blockIdx.x, bh = blockIdx.y, b = bh >> 4, h = bh & 15;
    int tid = threadIdx.x;
    int warp = tid >> 5, lane = tid & 31, g = lane >> 2, c = lane & 3;
    int wm = (warp & 3) * 16, wn = (warp >> 2) * 32;
    float acc[4][4];
    #pragma unroll
    for (int j = 0; j < 4; j++)
        #pragma unroll
        for (int r = 0; r < 4; r++) acc[j][r] = 0.f;

    for (int kt = 0; kt <= qt; kt++) {
        __syncthreads();
        #pragma unroll
        for (int pch = 0; pch < 4; pch++) {
            int e = pch*256 + tid;
            int row = e >> 4, col = (e & 15) * 4;
            *(float4*)&Ps[row][col] = *(const float4*)&att[((size_t)bh*KS + qt*64 + row)*KS + kt*64 + col];
            *(float4*)&Vs[row][col] = *(const float4*)&v[((size_t)(b*KS + kt*64 + row))*DD + h*64 + col];
        }
        __syncthreads();
        #pragma unroll
        for (int d = 0; d < 64; d += 8) {
            uint32_t a0 = *(const uint32_t*)&Ps[wm+g  ][d+c];
            uint32_t a1 = *(const uint32_t*)&Ps[wm+g+8][d+c];
            uint32_t a2 = *(const uint32_t*)&Ps[wm+g  ][d+c+4];
            uint32_t a3 = *(const uint32_t*)&Ps[wm+g+8][d+c+4];
            #pragma unroll
            for (int j = 0; j < 4; j++) {
                uint32_t b0 = *(const uint32_t*)&Vs[d+c  ][wn+j*8+g];
                uint32_t b1 = *(const uint32_t*)&Vs[d+c+4][wn+j*8+g];
                mma_tf32(acc[j], a0, a1, a2, a3, b0, b1);
            }
        }
    }
    int q0 = qt*64 + wm + g;
    #pragma unroll
    for (int j = 0; j < 4; j++) {
        int col = h*64 + wn + j*8 + c*2;
        *(float2*)&pv[((size_t)(b*KS + q0  ))*DD + col] = make_float2(acc[j][0], acc[j][1]);
        *(float2*)&pv[((size_t)(b*KS + q0+8))*DD + col] = make_float2(acc[j][2], acc[j][3]);
    }
}

// ---------------- K11: silu(gate)*up ----------------
__global__ void silu_mul_kernel(float4* __restrict__ gb, const float4* __restrict__ ub, int n4) {
    int i = blockIdx.x * blockDim.x + threadIdx.x;
    if (i >= n4) return;
    float4 g = gb[i], u = ub[i];
    g.x = g.x / (1.f + expf(-g.x)) * u.x;
    g.y = g.y / (1.f + expf(-g.y)) * u.y;
    g.z = g.z / (1.f + expf(-g.z)) * u.z;
    g.w = g.w / (1.f + expf(-g.w)) * u.w;
    gb[i] = g;
}

// ---------------- K12: scatter ----------------
__global__ void scatter_kernel(const float* __restrict__ sel, const float* __restrict__ bo,
                               const int* __restrict__ idx, const float* __restrict__ gate,
                               float* __restrict__ out) {
    int r = blockIdx.x;
    int b = r / KS;
    int pos = idx[r];
    float ga = gate[r];
    const float4* s4 = (const float4*)(sel + (size_t)r * DD);
    const float4* b4 = (const float4*)(bo  + (size_t)r * DD);
    float4* o4 = (float4*)(out + ((size_t)b*TT + pos) * DD);
    float4 s = s4[threadIdx.x], bb = b4[threadIdx.x];
    float4 u = make_float4(s.x + ga*(bb.x - s.x), s.y + ga*(bb.y - s.y),
                           s.z + ga*(bb.z - s.z), s.w + ga*(bb.w - s.w));
    o4[threadIdx.x] = u;
}

// ---------------- K13: predictor logits + per-row BCE ----------------
__global__ void predrow_kernel(const float* __restrict__ h1, const float* __restrict__ fc2w,
                               const float* __restrict__ fc2b, const float* __restrict__ tgt,
                               float* __restrict__ pred) {
    int warp = (blockIdx.x * blockDim.x + threadIdx.x) >> 5;
    int lane = threadIdx.x & 31;
    if (warp >= NTOK) return;
    const float* row = h1 + (size_t)warp * DQ;
    float s = 0.f;
    #pragma unroll
    for (int i = lane; i < DQ; i += 32) s += row[i] * fc2w[i];
    #pragma unroll
    for (int o = 16; o; o >>= 1) s += __shfl_xor_sync(0xffffffffu, s, o);
    if (lane == 0) {
        float x = s + fc2b[0];
        pred[warp] = bce_term(x, tgt[warp]);
    }
}

// ---------------- K14: loss reduce ----------------
__global__ void loss_reduce(const float* __restrict__ scores, const float* __restrict__ tgt,
                            const float* __restrict__ pred, float* __restrict__ out_aux) {
    __shared__ float sm_main[1024];
    __shared__ float sm_pred[1024];
    int tid = threadIdx.x;
    float sm = 0.f, sp = 0.f;
    for (int i = tid; i < NTOK; i += 1024) {
        sm += bce_term(scores[i], tgt[i]);
        sp += pred[i];
    }
    sm_main[tid] = sm; sm_pred[tid] = sp;
    __syncthreads();
    for (int s = 512; s > 0; s >>= 1) {
        if (tid < s) { sm_main[tid] += sm_main[tid+s]; sm_pred[tid] += sm_pred[tid+s]; }
        __syncthreads();
    }
    if (tid == 0)
        out_aux[0] = 0.01f * (sm_main[0] + sm_pred[0]) / (float)NTOK;
}

// ---------------- host launch ----------------
extern "C" void kernel_launch(void* const* d_in, const int* in_sizes, int n_in,
                              void* d_out, int out_size) {
    const float* hs   = (const float*)d_in[0];
    const float* rw   = (const float*)d_in[1];
    const float* fc1w = (const float*)d_in[2];
    const float* fc1b = (const float*)d_in[3];
    const float* fc2w = (const float*)d_in[4];
    const float* fc2b = (const float*)d_in[5];
    const float* ln1  = (const float*)d_in[6];
    const float* ln2  = (const float*)d_in[7];
    const float* wq   = (const float*)d_in[8];
    const float* wk   = (const float*)d_in[9];
    const float* wv   = (const float*)d_in[10];
    const float* wo   = (const float*)d_in[11];
    const float* wg   = (const float*)d_in[12];
    const float* wu   = (const float*)d_in[13];
    const float* wd   = (const float*)d_in[14];
    float* out = (float*)d_out;

    float *scores, *tgt, *gate, *sel, *a, *q, *k, *v, *att, *pv, *h, *m, *gb, *ub, *bo, *h1, *pred;
    int* idx;
    cudaGetSymbolAddress((void**)&scores, g_scores);
    cudaGetSymbolAddress((void**)&tgt,    g_tgt);
    cudaGetSymbolAddress((void**)&idx,    g_idx);
    cudaGetSymbolAddress((void**)&gate,   g_gate);
    cudaGetSymbolAddress((void**)&sel,    g_sel);
    cudaGetSymbolAddress((void**)&a,      g_a);
    cudaGetSymbolAddress((void**)&q,      g_q);
    cudaGetSymbolAddress((void**)&k,      g_k);
    cudaGetSymbolAddress((void**)&v,      g_v);
    cudaGetSymbolAddress((void**)&att,    g_att);
    cudaGetSymbolAddress((void**)&pv,     g_pv);
    cudaGetSymbolAddress((void**)&h,      g_h);
    cudaGetSymbolAddress((void**)&m,      g_m);
    cudaGetSymbolAddress((void**)&gb,     g_gb);
    cudaGetSymbolAddress((void**)&ub,     g_ub);
    cudaGetSymbolAddress((void**)&bo,     g_bo);
    cudaGetSymbolAddress((void**)&h1,     g_h1);
    cudaGetSymbolAddress((void**)&pred,   g_pred);

    cudaFuncSetAttribute(mma_gemm, cudaFuncAttributeMaxDynamicSharedMemorySize, GEMM_SMEM);

    // router + top-k
    scores_kernel<<<NTOK/8, 256>>>(hs, rw, scores);
    topk_radix<<<BB, 1024>>>(scores, tgt, idx, gate);

    // copy full hidden to output; gather selected rows
    copy_kernel<<<4096, 256>>>((const float4*)hs, (float4*)out, NTOK*DD/4);
    gather_kernel<<<ROWS, 256>>>(hs, idx, sel);

    // decoder block
    rmsnorm_kernel<<<ROWS, 256>>>(sel, ln1, a);
    mma_gemm<<<dim3(DD/128, ROWS/128), 256, GEMM_SMEM>>>(a, wq, q, ROWS, DD, DD, nullptr, 0);
    mma_gemm<<<dim3(DD/128, ROWS/128), 256, GEMM_SMEM>>>(a, wk, k, ROWS, DD, DD, nullptr, 0);
    mma_gemm<<<dim3(DD/128, ROWS/128), 256, GEMM_SMEM>>>(a, wv, v, ROWS, DD, DD, nullptr, 0);
    rope_kernel<<<ROWS, 256>>>(q, idx);
    rope_kernel<<<ROWS, 256>>>(k, idx);
    qk_mma<<<dim3(8, 8, BB*HH), 256>>>(q, k, att);
    softmax_kernel<<<BB*HH*KS/8, 256>>>(att);
    pv_mma<<<dim3(8, BB*HH), 256>>>(att, v, pv);
    mma_gemm<<<dim3(DD/128, ROWS/128), 256, GEMM_SMEM>>>(pv, wo, h, ROWS, DD, DD, sel, 2);

    rmsnorm_kernel<<<ROWS, 256>>>(h, ln2, m);
    mma_gemm<<<dim3(FF/128, ROWS/128), 256, GEMM_SMEM>>>(m, wg, gb, ROWS, FF, DD, nullptr, 0);
    mma_gemm<<<dim3(FF/128, ROWS/128), 256, GEMM_SMEM>>>(m, wu, ub, ROWS, FF, DD, nullptr, 0);
    silu_mul_kernel<<<(ROWS*FF/4 + 255)/256, 256>>>((float4*)gb, (const float4*)ub, ROWS*FF/4);
    mma_gemm<<<dim3(DD/128, ROWS/128), 256, GEMM_SMEM>>>(gb, wd, bo, ROWS, DD, FF, h, 2);

    scatter_kernel<<<ROWS, 256>>>(sel, bo, idx, gate, out);

    // aux losses (predictor path)
    mma_gemm<<<dim3(DQ/128, NTOK/128), 256, GEMM_SMEM>>>(hs, fc1w, h1, NTOK, DQ, DD, fc1b, 1);
    predrow_kernel<<<NTOK/8, 256>>>(h1, fc2w, fc2b, tgt, pred);
    loss_reduce<<<1, 1024>>>(scores, tgt, pred, out + (size_t)NTOK*DD);
}

// round 4
// speedup vs baseline: 2.9288x; 1.0194x over previous
#include <cuda_runtime.h>
#include <math.h>
#include <stdint.h>

// ---------------- problem constants ----------------
#define BB 4
#define TT 4096
#define DD 1024
#define FF 4096
#define HH 16
#define HD 64
#define KS 512
#define DQ 256
#define ROWS (BB*KS)           // 2048
#define NTOK (BB*TT)           // 16384

// ---------------- device scratch ----------------
__device__ float g_scores[NTOK];
__device__ float g_tgt[NTOK];
__device__ int   g_idx[ROWS];
__device__ float g_gate[ROWS];
__device__ float g_sel[ROWS*DD];
__device__ float g_a[ROWS*DD];
__device__ float g_q[ROWS*DD];
__device__ float g_k[ROWS*DD];
__device__ float g_v[ROWS*DD];
__device__ float g_att[(size_t)BB*HH*KS*KS];
__device__ float g_pv[ROWS*DD];
__device__ float g_h[ROWS*DD];
__device__ float g_m[ROWS*DD];
__device__ float g_gb[ROWS*FF];
__device__ float g_ub[ROWS*FF];
__device__ float g_bo[ROWS*DD];
__device__ float g_h1[(size_t)NTOK*DQ];
__device__ float g_pred[NTOK];

// ---------------- static streams/events for graph-level concurrency ----------------
static cudaStream_t s1, s2, s3;
static cudaEvent_t eStart, eTopk, eA, eK, eV, eP, eC;
static struct StreamInit {
    StreamInit() {
        cudaStreamCreateWithFlags(&s1, cudaStreamNonBlocking);
        cudaStreamCreateWithFlags(&s2, cudaStreamNonBlocking);
        cudaStreamCreateWithFlags(&s3, cudaStreamNonBlocking);
        cudaEventCreateWithFlags(&eStart, cudaEventDisableTiming);
        cudaEventCreateWithFlags(&eTopk,  cudaEventDisableTiming);
        cudaEventCreateWithFlags(&eA,     cudaEventDisableTiming);
        cudaEventCreateWithFlags(&eK,     cudaEventDisableTiming);
        cudaEventCreateWithFlags(&eV,     cudaEventDisableTiming);
        cudaEventCreateWithFlags(&eP,     cudaEventDisableTiming);
        cudaEventCreateWithFlags(&eC,     cudaEventDisableTiming);
    }
} s_init;

// ---------------- helpers ----------------
__device__ __forceinline__ float gelu_tanh(float x) {
    float x3 = x*x*x;
    return 0.5f * x * (1.f + tanhf(0.7978845608028654f * (x + 0.044715f * x3)));
}
__device__ __forceinline__ float bce_term(float x, float t) {
    return fmaxf(x, 0.f) - x*t + log1pf(expf(-fabsf(x)));
}
__device__ __forceinline__ void cpa16(uint32_t s, const float* g) {
    asm volatile("cp.async.cg.shared.global [%0], [%1], 16;" :: "r"(s), "l"(g));
}
__device__ __forceinline__ void mma_tf32(float* d, uint32_t a0, uint32_t a1, uint32_t a2, uint32_t a3,
                                         uint32_t b0, uint32_t b1) {
    asm volatile(
        "mma.sync.aligned.m16n8k8.row.col.f32.tf32.tf32.f32 "
        "{%0,%1,%2,%3}, {%4,%5,%6,%7}, {%8,%9}, {%0,%1,%2,%3};"
        : "+f"(d[0]), "+f"(d[1]), "+f"(d[2]), "+f"(d[3])
        : "r"(a0), "r"(a1), "r"(a2), "r"(a3), "r"(b0), "r"(b1));
}

// ---------------- K1: router scores ----------------
__global__ void scores_kernel(const float* __restrict__ hs, const float* __restrict__ rw,
                              float* __restrict__ scores) {
    int warp = (blockIdx.x * blockDim.x + threadIdx.x) >> 5;
    int lane = threadIdx.x & 31;
    if (warp >= NTOK) return;
    const float4* row = (const float4*)(hs + (size_t)warp * DD);
    const float4* w4  = (const float4*)rw;
    float s = 0.f;
    #pragma unroll 4
    for (int i = lane; i < DD/4; i += 32) {
        float4 a = row[i], b = w4[i];
        s += a.x*b.x + a.y*b.y + a.z*b.z + a.w*b.w;
    }
    #pragma unroll
    for (int o = 16; o; o >>= 1) s += __shfl_xor_sync(0xffffffffu, s, o);
    if (lane == 0) scores[warp] = s;
}

// ---------------- K2: radix-select top-k + ascending compaction ----------------
__global__ void topk_radix(const float* __restrict__ scores, float* __restrict__ tgt,
                           int* __restrict__ idxo, float* __restrict__ gateo) {
    __shared__ unsigned su[TT];
    __shared__ int hist[256];
    __shared__ int wsum[32];
    __shared__ unsigned s_prefix;
    __shared__ int s_remain;
    int b = blockIdx.x, tid = threadIdx.x;   // 1024 threads
    const float* sc = scores + (size_t)b * TT;

    for (int i = tid; i < TT; i += 1024) {
        unsigned bits = __float_as_uint(sc[i]);
        unsigned mask = (unsigned)((int)bits >> 31) | 0x80000000u;
        su[i] = bits ^ mask;
    }
    if (tid == 0) { s_prefix = 0u; s_remain = KS; }
    __syncthreads();

    #pragma unroll
    for (int p = 24; p >= 0; p -= 8) {
        if (tid < 256) hist[tid] = 0;
        __syncthreads();
        unsigned pref = s_prefix;
        for (int i = tid; i < TT; i += 1024) {
            unsigned u = su[i];
            if (p == 24 || (u >> (p + 8)) == (pref >> (p + 8)))
                atomicAdd(&hist[(u >> p) & 255], 1);
        }
        __syncthreads();
        if (tid == 0) {
            int rem = s_remain;
            int bin = 255;
            for (;;) {
                int c = hist[bin];
                if (rem <= c) break;
                rem -= c; bin--;
            }
            s_prefix = pref | ((unsigned)bin << p);
            s_remain = rem;
        }
        __syncthreads();
    }
    unsigned thr = s_prefix;

    int base = tid * 4;
    int flg[4]; int cnt = 0;
    #pragma unroll
    for (int j = 0; j < 4; j++) { flg[j] = (su[base + j] >= thr) ? 1 : 0; cnt += flg[j]; }
    int lane = tid & 31, warp = tid >> 5;
    int inc = cnt;
    #pragma unroll
    for (int o = 1; o < 32; o <<= 1) {
        int n2 = __shfl_up_sync(0xffffffffu, inc, o);
        if (lane >= o) inc += n2;
    }
    if (lane == 31) wsum[warp] = inc;
    __syncthreads();
    if (tid < 32) {
        int v = wsum[tid];
        #pragma unroll
        for (int o = 1; o < 32; o <<= 1) {
            int n2 = __shfl_up_sync(0xffffffffu, v, o);
            if (tid >= o) v += n2;
        }
        wsum[tid] = v;
    }
    __syncthreads();
    int off = inc - cnt + (warp ? wsum[warp - 1] : 0);
    #pragma unroll
    for (int j = 0; j < 4; j++) {
        tgt[(size_t)b*TT + base + j] = flg[j] ? 1.f : 0.f;
        if (flg[j]) {
            idxo[b*KS + off] = base + j;
            float s = sc[base + j];
            gateo[b*KS + off] = 1.f / (1.f + expf(-s));
            off++;
        }
    }
}

// ---------------- K3: copy hidden -> out ----------------
__global__ void copy_kernel(const float4* __restrict__ src, float4* __restrict__ dst, int n4) {
    int stride = gridDim.x * blockDim.x;
    for (int i = blockIdx.x * blockDim.x + threadIdx.x; i < n4; i += stride)
        dst[i] = src[i];
}

// ---------------- K4: fused gather + rmsnorm(ln1) ----------------
__global__ void gather_rms_kernel(const float* __restrict__ hs, const int* __restrict__ idx,
                                  const float* __restrict__ g,
                                  float* __restrict__ sel, float* __restrict__ a) {
    __shared__ float red[8];
    int r = blockIdx.x, tid = threadIdx.x;
    int b = r / KS;
    int pos = idx[r];
    const float4* src = (const float4*)(hs + ((size_t)b*TT + pos) * DD);
    float4 x = src[tid];
    ((float4*)(sel + (size_t)r * DD))[tid] = x;
    float ss = x.x*x.x + x.y*x.y + x.z*x.z + x.w*x.w;
    #pragma unroll
    for (int o = 16; o; o >>= 1) ss += __shfl_xor_sync(0xffffffffu, ss, o);
    if ((tid & 31) == 0) red[tid >> 5] = ss;
    __syncthreads();
    if (tid < 8) {
        float v = red[tid];
        #pragma unroll
        for (int o = 4; o; o >>= 1) v += __shfl_xor_sync(0xffu, v, o);
        if (tid == 0) red[0] = v;
    }
    __syncthreads();
    float rs = rsqrtf(red[0] / (float)DD + 1e-6f);
    const float4* g4 = (const float4*)g;
    float4 gg = g4[tid];
    ((float4*)(a + (size_t)r * DD))[tid] =
        make_float4(x.x*rs*gg.x, x.y*rs*gg.y, x.z*rs*gg.z, x.w*rs*gg.w);
}

// ---------------- K5: rmsnorm ----------------
__global__ void rmsnorm_kernel(const float* __restrict__ in, const float* __restrict__ g,
                               float* __restrict__ out) {
    __shared__ float red[8];
    int r = blockIdx.x, tid = threadIdx.x;
    const float4* x4 = (const float4*)(in + (size_t)r * DD);
    float4 x = x4[tid];
    float ss = x.x*x.x + x.y*x.y + x.z*x.z + x.w*x.w;
    #pragma unroll
    for (int o = 16; o; o >>= 1) ss += __shfl_xor_sync(0xffffffffu, ss, o);
    if ((tid & 31) == 0) red[tid >> 5] = ss;
    __syncthreads();
    if (tid < 8) {
        float v = red[tid];
        #pragma unroll
        for (int o = 4; o; o >>= 1) v += __shfl_xor_sync(0xffu, v, o);
        if (tid == 0) red[0] = v;
    }
    __syncthreads();
    float rs = rsqrtf(red[0] / (float)DD + 1e-6f);
    const float4* g4 = (const float4*)g;
    float4 gg = g4[tid];
    float4 o4 = make_float4(x.x*rs*gg.x, x.y*rs*gg.y, x.z*rs*gg.z, x.w*rs*gg.w);
    ((float4*)(out + (size_t)r * DD))[tid] = o4;
}

// ---------------- K6: TF32 GEMM 128x128x32, cp.async double-buffered ----------------
// epi: 0 none, 1 gelu(acc+bias[col]), 2 acc+resid[row,col], 3 silu(acc)*aux[row,col]
#define AS_LD 36
#define BS_LD 136
#define A_TILE (128*AS_LD)
#define B_TILE (32*BS_LD)
#define GEMM_SMEM ((2*A_TILE + 2*B_TILE)*4)

__global__ __launch_bounds__(256)
void mma_gemm(const float* __restrict__ A, const float* __restrict__ B, float* __restrict__ C,
              int M, int N, int K, const float* __restrict__ aux, int epi) {
    extern __shared__ float dynsm[];
    float* As = dynsm;
    float* Bs = dynsm + 2*A_TILE;

    int tid = threadIdx.x;
    int m0 = blockIdx.y * 128, n0 = blockIdx.x * 128;
    int warp = tid >> 5, lane = tid & 31;
    int wm = (warp >> 2) * 64;
    int wn = (warp & 3) * 32;
    int g = lane >> 2, c = lane & 3;

    float acc[4][4][4];
    #pragma unroll
    for (int i = 0; i < 4; i++)
        #pragma unroll
        for (int j = 0; j < 4; j++)
            #pragma unroll
            for (int r = 0; r < 4; r++) acc[i][j][r] = 0.f;

    int aRow = tid >> 1;
    int aSeg = (tid & 1) * 16;
    int bRow = tid >> 3;
    int bSeg = (tid & 7) * 16;

    uint32_t asBase = (uint32_t)__cvta_generic_to_shared(As);
    uint32_t bsBase = (uint32_t)__cvta_generic_to_shared(Bs);

    int nk = K / 32;

    {
        const float* Ag = A + (size_t)(m0 + aRow) * K + aSeg;
        uint32_t ad = asBase + (aRow*AS_LD + aSeg) * 4;
        #pragma unroll
        for (int i = 0; i < 4; i++) cpa16(ad + i*16, Ag + i*4);
        const float* Bg = B + (size_t)bRow * N + n0 + bSeg;
        uint32_t bd = bsBase + (bRow*BS_LD + bSeg) * 4;
        #pragma unroll
        for (int i = 0; i < 4; i++) cpa16(bd + i*16, Bg + i*4);
        asm volatile("cp.async.commit_group;" ::: "memory");
    }

    for (int kt = 0; kt < nk; kt++) {
        if (kt + 1 < nk) {
            int st = (kt + 1) & 1;
            const float* Ag = A + (size_t)(m0 + aRow) * K + (kt+1)*32 + aSeg;
            uint32_t ad = asBase + (st*A_TILE + aRow*AS_LD + aSeg) * 4;
            #pragma unroll
            for (int i = 0; i < 4; i++) cpa16(ad + i*16, Ag + i*4);
            const float* Bg = B + (size_t)((kt+1)*32 + bRow) * N + n0 + bSeg;
            uint32_t bd = bsBase + (st*B_TILE + bRow*BS_LD + bSeg) * 4;
            #pragma unroll
            for (int i = 0; i < 4; i++) cpa16(bd + i*16, Bg + i*4);
            asm volatile("cp.async.commit_group;" ::: "memory");
            asm volatile("cp.async.wait_group 1;" ::: "memory");
        } else {
            asm volatile("cp.async.wait_group 0;" ::: "memory");
        }
        __syncthreads();

        const float* as = As + (kt & 1) * A_TILE;
        const float* bs = Bs + (kt & 1) * B_TILE;
        #pragma unroll
        for (int ks = 0; ks < 32; ks += 8) {
            uint32_t af[4][4], bf[4][2];
            #pragma unroll
            for (int i = 0; i < 4; i++) {
                int mb = wm + i*16;
                af[i][0] = *(const uint32_t*)&as[(mb+g  )*AS_LD + ks + c];
                af[i][1] = *(const uint32_t*)&as[(mb+g+8)*AS_LD + ks + c];
                af[i][2] = *(const uint32_t*)&as[(mb+g  )*AS_LD + ks + c + 4];
                af[i][3] = *(const uint32_t*)&as[(mb+g+8)*AS_LD + ks + c + 4];
            }
            #pragma unroll
            for (int j = 0; j < 4; j++) {
                int nb = wn + j*8;
                bf[j][0] = *(const uint32_t*)&bs[(ks+c  )*BS_LD + nb + g];
                bf[j][1] = *(const uint32_t*)&bs[(ks+c+4)*BS_LD + nb + g];
            }
            #pragma unroll
            for (int i = 0; i < 4; i++)
                #pragma unroll
                for (int j = 0; j < 4; j++)
                    mma_tf32(acc[i][j], af[i][0], af[i][1], af[i][2], af[i][3],
                             bf[j][0], bf[j][1]);
        }
        __syncthreads();
    }

    #pragma unroll
    for (int i = 0; i < 4; i++) {
        int r0 = m0 + wm + i*16 + g;
        #pragma unroll
        for (int j = 0; j < 4; j++) {
            int col = n0 + wn + j*8 + c*2;
            float2 lo = make_float2(acc[i][j][0], acc[i][j][1]);
            float2 hi = make_float2(acc[i][j][2], acc[i][j][3]);
            if (epi == 1) {
                float b0 = aux[col], b1 = aux[col+1];
                lo.x = gelu_tanh(lo.x + b0); lo.y = gelu_tanh(lo.y + b1);
                hi.x = gelu_tanh(hi.x + b0); hi.y = gelu_tanh(hi.y + b1);
            } else if (epi == 2) {
                const float2 s0 = *(const float2*)&aux[(size_t)r0*N + col];
                const float2 s1 = *(const float2*)&aux[(size_t)(r0+8)*N + col];
                lo.x += s0.x; lo.y += s0.y; hi.x += s1.x; hi.y += s1.y;
            } else if (epi == 3) {
                const float2 u0 = *(const float2*)&aux[(size_t)r0*N + col];
                const float2 u1 = *(const float2*)&aux[(size_t)(r0+8)*N + col];
                lo.x = lo.x / (1.f + expf(-lo.x)) * u0.x;
                lo.y = lo.y / (1.f + expf(-lo.y)) * u0.y;
                hi.x = hi.x / (1.f + expf(-hi.x)) * u1.x;
                hi.y = hi.y / (1.f + expf(-hi.y)) * u1.y;
            }
            *(float2*)&C[(size_t)r0*N + col] = lo;
            *(float2*)&C[(size_t)(r0+8)*N + col] = hi;
        }
    }
}

// ---------------- K7: RoPE (q and k in one launch) ----------------
__global__ void rope2_kernel(float* __restrict__ q, float* __restrict__ k,
                             const int* __restrict__ idx) {
    int blk = blockIdx.x;
    float* buf = (blk < ROWS) ? q : k;
    int r = (blk < ROWS) ? blk : blk - ROWS;
    float pos = (float)idx[r];
    float* base = buf + (size_t)r * DD;
    for (int c = threadIdx.x; c < 512; c += 256) {
        int h = c >> 5, i = c & 31;
        float inv = powf(10000.f, -(float)i / 32.f);
        float ang = pos * inv;
        float s, co; sincosf(ang, &s, &co);
        float* p = base + h * 64;
        float x1 = p[i], x2 = p[i + 32];
        p[i]      = x1*co - x2*s;
        p[i + 32] = x2*co + x1*s;
    }
}

// ---------------- K8: QK^T (tf32 mma), causal tiles only ----------------
__global__ __launch_bounds__(256)
void qk_mma(const float* __restrict__ q, const float* __restrict__ k,
            float* __restrict__ att) {
    __shared__ float Qs[64][68];
    __shared__ float Ks[64][68];
    int kt = blockIdx.x, qt = blockIdx.y;
    if (kt > qt) return;
    int bh = blockIdx.z, b = bh >> 4, h = bh & 15;
    int tid = threadIdx.x;
    #pragma unroll
    for (int pch = 0; pch < 4; pch++) {
        int e = pch*256 + tid;
        int row = e >> 4, col = (e & 15) * 4;
        *(float4*)&Qs[row][col] = *(const float4*)&q[((size_t)(b*KS + qt*64 + row))*DD + h*64 + col];
        *(float4*)&Ks[row][col] = *(const float4*)&k[((size_t)(b*KS + kt*64 + row))*DD + h*64 + col];
    }
    __syncthreads();
    int warp = tid >> 5, lane = tid & 31, g = lane >> 2, c = lane & 3;
    int wm = (warp & 3) * 16, wn = (warp >> 2) * 32;
    float acc[4][4];
    #pragma unroll
    for (int j = 0; j < 4; j++)
        #pragma unroll
        for (int r = 0; r < 4; r++) acc[j][r] = 0.f;
    #pragma unroll
    for (int d = 0; d < 64; d += 8) {
        uint32_t a0 = *(const uint32_t*)&Qs[wm+g  ][d+c];
        uint32_t a1 = *(const uint32_t*)&Qs[wm+g+8][d+c];
        uint32_t a2 = *(const uint32_t*)&Qs[wm+g  ][d+c+4];
        uint32_t a3 = *(const uint32_t*)&Qs[wm+g+8][d+c+4];
        #pragma unroll
        for (int j = 0; j < 4; j++) {
            uint32_t b0 = *(const uint32_t*)&Ks[wn+j*8+g][d+c];
            uint32_t b1 = *(const uint32_t*)&Ks[wn+j*8+g][d+c+4];
            mma_tf32(acc[j], a0, a1, a2, a3, b0, b1);
        }
    }
    const float scale = 0.125f;
    int q0 = qt*64 + wm + g;
    #pragma unroll
    for (int j = 0; j < 4; j++) {
        int kc = kt*64 + wn + j*8 + c*2;
        float2 lo, hi;
        lo.x = (kc   <= q0  ) ? acc[j][0]*scale : -1e9f;
        lo.y = (kc+1 <= q0  ) ? acc[j][1]*scale : -1e9f;
        hi.x = (kc   <= q0+8) ? acc[j][2]*scale : -1e9f;
        hi.y = (kc+1 <= q0+8) ? acc[j][3]*scale : -1e9f;
        *(float2*)&att[((size_t)bh*KS + q0  )*KS + kc] = lo;
        *(float2*)&att[((size_t)bh*KS + q0+8)*KS + kc] = hi;
    }
}

// ---------------- K9: variable-length softmax ----------------
__global__ void softmax_kernel(float* __restrict__ att) {
    int warp = (blockIdx.x * blockDim.x + threadIdx.x) >> 5;
    int lane = threadIdx.x & 31;
    int q = warp & (KS - 1);
    int L32 = ((q >> 6) + 1) * 2;
    float* p = att + (size_t)warp * KS;
    float v[16];
    float mx = -3.4e38f;
    for (int l = 0; l < L32; l++) { v[l] = p[lane + l*32]; mx = fmaxf(mx, v[l]); }
    #pragma unroll
    for (int o = 16; o; o >>= 1) mx = fmaxf(mx, __shfl_xor_sync(0xffffffffu, mx, o));
    float sum = 0.f;
    for (int l = 0; l < L32; l++) { v[l] = expf(v[l] - mx); sum += v[l]; }
    #pragma unroll
    for (int o = 16; o; o >>= 1) sum += __shfl_xor_sync(0xffffffffu, sum, o);
    float inv = 1.f / sum;
    for (int l = 0; l < L32; l++) p[lane + l*32] = v[l] * inv;
}

// ---------------- K10: PV (tf32 mma), causal tiles only ----------------
__global__ __launch_bounds__(256)
void pv_mma(const float* __restrict__ att, const float* __restrict__ v,
            float* __restrict__ pv) {
    __shared__ float Ps[64][68];
    __shared__ float Vs[64][72];
    int qt = blockIdx.x, bh = blockIdx.y, b = bh >> 4, h = bh & 15;
    int tid = threadIdx.x;
    int warp = tid >> 5, lane = tid & 31, g = lane >> 2, c = lane & 3;
    int wm = (warp & 3) * 16, wn = (warp >> 2) * 32;
    float acc[4][4];
    #pragma unroll
    for (int j = 0; j < 4; j++)
        #pragma unroll
        for (int r = 0; r < 4; r++) acc[j][r] = 0.f;

    for (int kt = 0; kt <= qt; kt++) {
        __syncthreads();
        #pragma unroll
        for (int pch = 0; pch < 4; pch++) {
            int e = pch*256 + tid;
            int row = e >> 4, col = (e & 15) * 4;
            *(float4*)&Ps[row][col] = *(const float4*)&att[((size_t)bh*KS + qt*64 + row)*KS + kt*64 + col];
            *(float4*)&Vs[row][col] = *(const float4*)&v[((size_t)(b*KS + kt*64 + row))*DD + h*64 + col];
        }
        __syncthreads();
        #pragma unroll
        for (int d = 0; d < 64; d += 8) {
            uint32_t a0 = *(const uint32_t*)&Ps[wm+g  ][d+c];
            uint32_t a1 = *(const uint32_t*)&Ps[wm+g+8][d+c];
            uint32_t a2 = *(const uint32_t*)&Ps[wm+g  ][d+c+4];
            uint32_t a3 = *(const uint32_t*)&Ps[wm+g+8][d+c+4];
            #pragma unroll
            for (int j = 0; j < 4; j++) {
                uint32_t b0 = *(const uint32_t*)&Vs[d+c  ][wn+j*8+g];
                uint32_t b1 = *(const uint32_t*)&Vs[d+c+4][wn+j*8+g];
                mma_tf32(acc[j], a0, a1, a2, a3, b0, b1);
            }
        }
    }
    int q0 = qt*64 + wm + g;
    #pragma unroll
    for (int j = 0; j < 4; j++) {
        int col = h*64 + wn + j*8 + c*2;
        *(float2*)&pv[((size_t)(b*KS + q0  ))*DD + col] = make_float2(acc[j][0], acc[j][1]);
        *(float2*)&pv[((size_t)(b*KS + q0+8))*DD + col] = make_float2(acc[j][2], acc[j][3]);
    }
}

// ---------------- K12: scatter ----------------
__global__ void scatter_kernel(const float* __restrict__ sel, const float* __restrict__ bo,
                               const int* __restrict__ idx, const float* __restrict__ gate,
                               float* __restrict__ out) {
    int r = blockIdx.x;
    int b = r / KS;
    int pos = idx[r];
    float ga = gate[r];
    const float4* s4 = (const float4*)(sel + (size_t)r * DD);
    const float4* b4 = (const float4*)(bo  + (size_t)r * DD);
    float4* o4 = (float4*)(out + ((size_t)b*TT + pos) * DD);
    float4 s = s4[threadIdx.x], bb = b4[threadIdx.x];
    float4 u = make_float4(s.x + ga*(bb.x - s.x), s.y + ga*(bb.y - s.y),
                           s.z + ga*(bb.z - s.z), s.w + ga*(bb.w - s.w));
    o4[threadIdx.x] = u;
}

// ---------------- K13: predictor logits + per-row BCE ----------------
__global__ void predrow_kernel(const float* __restrict__ h1, const float* __restrict__ fc2w,
                               const float* __restrict__ fc2b, const float* __restrict__ tgt,
                               float* __restrict__ pred) {
    int warp = (blockIdx.x * blockDim.x + threadIdx.x) >> 5;
    int lane = threadIdx.x & 31;
    if (warp >= NTOK) return;
    const float* row = h1 + (size_t)warp * DQ;
    float s = 0.f;
    #pragma unroll
    for (int i = lane; i < DQ; i += 32) s += row[i] * fc2w[i];
    #pragma unroll
    for (int o = 16; o; o >>= 1) s += __shfl_xor_sync(0xffffffffu, s, o);
    if (lane == 0) {
        float x = s + fc2b[0];
        pred[warp] = bce_term(x, tgt[warp]);
    }
}

// ---------------- K14: loss reduce ----------------
__global__ void loss_reduce(const float* __restrict__ scores, const float* __restrict__ tgt,
                            const float* __restrict__ pred, float* __restrict__ out_aux) {
    __shared__ float sm_main[1024];
    __shared__ float sm_pred[1024];
    int tid = threadIdx.x;
    float sm = 0.f, sp = 0.f;
    for (int i = tid; i < NTOK; i += 1024) {
        sm += bce_term(scores[i], tgt[i]);
        sp += pred[i];
    }
    sm_main[tid] = sm; sm_pred[tid] = sp;
    __syncthreads();
    for (int s = 512; s > 0; s >>= 1) {
        if (tid < s) { sm_main[tid] += sm_main[tid+s]; sm_pred[tid] += sm_pred[tid+s]; }
        __syncthreads();
    }
    if (tid == 0)
        out_aux[0] = 0.01f * (sm_main[0] + sm_pred[0]) / (float)NTOK;
}

// ---------------- host launch ----------------
extern "C" void kernel_launch(void* const* d_in, const int* in_sizes, int n_in,
                              void* d_out, int out_size) {
    const float* hs   = (const float*)d_in[0];
    const float* rw   = (const float*)d_in[1];
    const float* fc1w = (const float*)d_in[2];
    const float* fc1b = (const float*)d_in[3];
    const float* fc2w = (const float*)d_in[4];
    const float* fc2b = (const float*)d_in[5];
    const float* ln1  = (const float*)d_in[6];
    const float* ln2  = (const float*)d_in[7];
    const float* wq   = (const float*)d_in[8];
    const float* wk   = (const float*)d_in[9];
    const float* wv   = (const float*)d_in[10];
    const float* wo   = (const float*)d_in[11];
    const float* wg   = (const float*)d_in[12];
    const float* wu   = (const float*)d_in[13];
    const float* wd   = (const float*)d_in[14];
    float* out = (float*)d_out;

    float *scores, *tgt, *gate, *sel, *a, *q, *k, *v, *att, *pv, *h, *m, *gb, *ub, *bo, *h1, *pred;
    int* idx;
    cudaGetSymbolAddress((void**)&scores, g_scores);
    cudaGetSymbolAddress((void**)&tgt,    g_tgt);
    cudaGetSymbolAddress((void**)&idx,    g_idx);
    cudaGetSymbolAddress((void**)&gate,   g_gate);
    cudaGetSymbolAddress((void**)&sel,    g_sel);
    cudaGetSymbolAddress((void**)&a,      g_a);
    cudaGetSymbolAddress((void**)&q,      g_q);
    cudaGetSymbolAddress((void**)&k,      g_k);
    cudaGetSymbolAddress((void**)&v,      g_v);
    cudaGetSymbolAddress((void**)&att,    g_att);
    cudaGetSymbolAddress((void**)&pv,     g_pv);
    cudaGetSymbolAddress((void**)&h,      g_h);
    cudaGetSymbolAddress((void**)&m,      g_m);
    cudaGetSymbolAddress((void**)&gb,     g_gb);
    cudaGetSymbolAddress((void**)&ub,     g_ub);
    cudaGetSymbolAddress((void**)&bo,     g_bo);
    cudaGetSymbolAddress((void**)&h1,     g_h1);
    cudaGetSymbolAddress((void**)&pred,   g_pred);

    cudaFuncSetAttribute(mma_gemm, cudaFuncAttributeMaxDynamicSharedMemorySize, GEMM_SMEM);

    // ---- fork: copy runs on s2 concurrently with router/topk ----
    cudaEventRecord(eStart, 0);
    cudaStreamWaitEvent(s2, eStart, 0);
    copy_kernel<<<4096, 256, 0, s2>>>((const float4*)hs, (float4*)out, NTOK*DD/4);
    cudaEventRecord(eC, s2);

    // ---- router + top-k on main stream ----
    scores_kernel<<<NTOK/8, 256>>>(hs, rw, scores);
    topk_radix<<<BB, 1024>>>(scores, tgt, idx, gate);
    cudaEventRecord(eTopk, 0);

    // ---- predictor path on s1 (needs tgt) ----
    cudaStreamWaitEvent(s1, eTopk, 0);
    mma_gemm<<<dim3(DQ/128, NTOK/128), 256, GEMM_SMEM, s1>>>(hs, fc1w, h1, NTOK, DQ, DD, fc1b, 1);
    predrow_kernel<<<NTOK/8, 256, 0, s1>>>(h1, fc2w, fc2b, tgt, pred);
    cudaEventRecord(eP, s1);

    // ---- decoder block on main stream ----
    gather_rms_kernel<<<ROWS, 256>>>(hs, idx, ln1, sel, a);
    cudaEventRecord(eA, 0);
    // wk on s2 (after copy), wv on s3, wq on main — fills the chip
    cudaStreamWaitEvent(s2, eA, 0);
    cudaStreamWaitEvent(s3, eA, 0);
    mma_gemm<<<dim3(DD/128, ROWS/128), 256, GEMM_SMEM, s2>>>(a, wk, k, ROWS, DD, DD, nullptr, 0);
    cudaEventRecord(eK, s2);
    mma_gemm<<<dim3(DD/128, ROWS/128), 256, GEMM_SMEM, s3>>>(a, wv, v, ROWS, DD, DD, nullptr, 0);
    cudaEventRecord(eV, s3);
    mma_gemm<<<dim3(DD/128, ROWS/128), 256, GEMM_SMEM>>>(a, wq, q, ROWS, DD, DD, nullptr, 0);
    cudaStreamWaitEvent(0, eK, 0);
    rope2_kernel<<<2*ROWS, 256>>>(q, k, idx);
    qk_mma<<<dim3(8, 8, BB*HH), 256>>>(q, k, att);
    softmax_kernel<<<BB*HH*KS/8, 256>>>(att);
    cudaStreamWaitEvent(0, eV, 0);
    pv_mma<<<dim3(8, BB*HH), 256>>>(att, v, pv);
    mma_gemm<<<dim3(DD/128, ROWS/128), 256, GEMM_SMEM>>>(pv, wo, h, ROWS, DD, DD, sel, 2);

    rmsnorm_kernel<<<ROWS, 256>>>(h, ln2, m);
    mma_gemm<<<dim3(FF/128, ROWS/128), 256, GEMM_SMEM>>>(m, wu, ub, ROWS, FF, DD, nullptr, 0);
    mma_gemm<<<dim3(FF/128, ROWS/128), 256, GEMM_SMEM>>>(m, wg, gb, ROWS, FF, DD, ub, 3);  // silu(m@wg)*ub
    mma_gemm<<<dim3(DD/128, ROWS/128), 256, GEMM_SMEM>>>(gb, wd, bo, ROWS, DD, FF, h, 2);

    // scatter needs out fully copied
    cudaStreamWaitEvent(0, eC, 0);
    scatter_kernel<<<ROWS, 256>>>(sel, bo, idx, gate, out);

    // aux loss (join predictor path)
    cudaStreamWaitEvent(0, eP, 0);
    loss_reduce<<<1, 1024>>>(scores, tgt, pred, out + (size_t)NTOK*DD);
}

// round 5
// speedup vs baseline: 3.0504x; 1.0415x over previous
#include <cuda_runtime.h>
#include <math.h>
#include <stdint.h>

// ---------------- problem constants ----------------
#define BB 4
#define TT 4096
#define DD 1024
#define FF 4096
#define HH 16
#define HD 64
#define KS 512
#define DQ 256
#define ROWS (BB*KS)           // 2048
#define NTOK (BB*TT)           // 16384

// ---------------- device scratch ----------------
__device__ float g_scores[NTOK];
__device__ float g_tgt[NTOK];
__device__ int   g_idx[ROWS];
__device__ float g_gate[ROWS];
__device__ float g_sel[ROWS*DD];
__device__ float g_a[ROWS*DD];
__device__ float g_q[ROWS*DD];
__device__ float g_k[ROWS*DD];
__device__ float g_v[ROWS*DD];
__device__ float g_pv[ROWS*DD];
__device__ float g_h[ROWS*DD];
__device__ float g_m[ROWS*DD];
__device__ float g_gb[ROWS*FF];
__device__ float g_ub[ROWS*FF];
__device__ float g_bo[ROWS*DD];
__device__ float g_h1[(size_t)NTOK*DQ];
__device__ float g_pred[NTOK];

// ---------------- static streams/events ----------------
static cudaStream_t s1, s2, s3;
static cudaEvent_t eStart, eTopk, eA, eK, eV, eP, eC;
static struct StreamInit {
    StreamInit() {
        cudaStreamCreateWithFlags(&s1, cudaStreamNonBlocking);
        cudaStreamCreateWithFlags(&s2, cudaStreamNonBlocking);
        cudaStreamCreateWithFlags(&s3, cudaStreamNonBlocking);
        cudaEventCreateWithFlags(&eStart, cudaEventDisableTiming);
        cudaEventCreateWithFlags(&eTopk,  cudaEventDisableTiming);
        cudaEventCreateWithFlags(&eA,     cudaEventDisableTiming);
        cudaEventCreateWithFlags(&eK,     cudaEventDisableTiming);
        cudaEventCreateWithFlags(&eV,     cudaEventDisableTiming);
        cudaEventCreateWithFlags(&eP,     cudaEventDisableTiming);
        cudaEventCreateWithFlags(&eC,     cudaEventDisableTiming);
    }
} s_init;

// ---------------- helpers ----------------
__device__ __forceinline__ float gelu_tanh(float x) {
    float x3 = x*x*x;
    return 0.5f * x * (1.f + tanhf(0.7978845608028654f * (x + 0.044715f * x3)));
}
__device__ __forceinline__ float bce_term(float x, float t) {
    return fmaxf(x, 0.f) - x*t + log1pf(expf(-fabsf(x)));
}
__device__ __forceinline__ void cpa16(uint32_t s, const float* g) {
    asm volatile("cp.async.cg.shared.global [%0], [%1], 16;" :: "r"(s), "l"(g));
}
__device__ __forceinline__ void mma_tf32(float* d, uint32_t a0, uint32_t a1, uint32_t a2, uint32_t a3,
                                         uint32_t b0, uint32_t b1) {
    asm volatile(
        "mma.sync.aligned.m16n8k8.row.col.f32.tf32.tf32.f32 "
        "{%0,%1,%2,%3}, {%4,%5,%6,%7}, {%8,%9}, {%0,%1,%2,%3};"
        : "+f"(d[0]), "+f"(d[1]), "+f"(d[2]), "+f"(d[3])
        : "r"(a0), "r"(a1), "r"(a2), "r"(a3), "r"(b0), "r"(b1));
}

// ---------------- K1: router scores ----------------
__global__ void scores_kernel(const float* __restrict__ hs, const float* __restrict__ rw,
                              float* __restrict__ scores) {
    int warp = (blockIdx.x * blockDim.x + threadIdx.x) >> 5;
    int lane = threadIdx.x & 31;
    if (warp >= NTOK) return;
    const float4* row = (const float4*)(hs + (size_t)warp * DD);
    const float4* w4  = (const float4*)rw;
    float s = 0.f;
    #pragma unroll 4
    for (int i = lane; i < DD/4; i += 32) {
        float4 a = row[i], b = w4[i];
        s += a.x*b.x + a.y*b.y + a.z*b.z + a.w*b.w;
    }
    #pragma unroll
    for (int o = 16; o; o >>= 1) s += __shfl_xor_sync(0xffffffffu, s, o);
    if (lane == 0) scores[warp] = s;
}

// ---------------- K2: radix-select top-k + ascending compaction ----------------
__global__ void topk_radix(const float* __restrict__ scores, float* __restrict__ tgt,
                           int* __restrict__ idxo, float* __restrict__ gateo) {
    __shared__ unsigned su[TT];
    __shared__ int hist[256];
    __shared__ int wsum[32];
    __shared__ unsigned s_prefix;
    __shared__ int s_remain;
    int b = blockIdx.x, tid = threadIdx.x;
    const float* sc = scores + (size_t)b * TT;

    for (int i = tid; i < TT; i += 1024) {
        unsigned bits = __float_as_uint(sc[i]);
        unsigned mask = (unsigned)((int)bits >> 31) | 0x80000000u;
        su[i] = bits ^ mask;
    }
    if (tid == 0) { s_prefix = 0u; s_remain = KS; }
    __syncthreads();

    #pragma unroll
    for (int p = 24; p >= 0; p -= 8) {
        if (tid < 256) hist[tid] = 0;
        __syncthreads();
        unsigned pref = s_prefix;
        for (int i = tid; i < TT; i += 1024) {
            unsigned u = su[i];
            if (p == 24 || (u >> (p + 8)) == (pref >> (p + 8)))
                atomicAdd(&hist[(u >> p) & 255], 1);
        }
        __syncthreads();
        if (tid == 0) {
            int rem = s_remain;
            int bin = 255;
            for (;;) {
                int c = hist[bin];
                if (rem <= c) break;
                rem -= c; bin--;
            }
            s_prefix = pref | ((unsigned)bin << p);
            s_remain = rem;
        }
        __syncthreads();
    }
    unsigned thr = s_prefix;

    int base = tid * 4;
    int flg[4]; int cnt = 0;
    #pragma unroll
    for (int j = 0; j < 4; j++) { flg[j] = (su[base + j] >= thr) ? 1 : 0; cnt += flg[j]; }
    int lane = tid & 31, warp = tid >> 5;
    int inc = cnt;
    #pragma unroll
    for (int o = 1; o < 32; o <<= 1) {
        int n2 = __shfl_up_sync(0xffffffffu, inc, o);
        if (lane >= o) inc += n2;
    }
    if (lane == 31) wsum[warp] = inc;
    __syncthreads();
    if (tid < 32) {
        int v = wsum[tid];
        #pragma unroll
        for (int o = 1; o < 32; o <<= 1) {
            int n2 = __shfl_up_sync(0xffffffffu, v, o);
            if (tid >= o) v += n2;
        }
        wsum[tid] = v;
    }
    __syncthreads();
    int off = inc - cnt + (warp ? wsum[warp - 1] : 0);
    #pragma unroll
    for (int j = 0; j < 4; j++) {
        tgt[(size_t)b*TT + base + j] = flg[j] ? 1.f : 0.f;
        if (flg[j]) {
            idxo[b*KS + off] = base + j;
            float s = sc[base + j];
            gateo[b*KS + off] = 1.f / (1.f + expf(-s));
            off++;
        }
    }
}

// ---------------- K3: copy hidden -> out ----------------
__global__ void copy_kernel(const float4* __restrict__ src, float4* __restrict__ dst, int n4) {
    int stride = gridDim.x * blockDim.x;
    for (int i = blockIdx.x * blockDim.x + threadIdx.x; i < n4; i += stride)
        dst[i] = src[i];
}

// ---------------- K4: fused gather + rmsnorm(ln1) ----------------
__global__ void gather_rms_kernel(const float* __restrict__ hs, const int* __restrict__ idx,
                                  const float* __restrict__ g,
                                  float* __restrict__ sel, float* __restrict__ a) {
    __shared__ float red[8];
    int r = blockIdx.x, tid = threadIdx.x;
    int b = r / KS;
    int pos = idx[r];
    const float4* src = (const float4*)(hs + ((size_t)b*TT + pos) * DD);
    float4 x = src[tid];
    ((float4*)(sel + (size_t)r * DD))[tid] = x;
    float ss = x.x*x.x + x.y*x.y + x.z*x.z + x.w*x.w;
    #pragma unroll
    for (int o = 16; o; o >>= 1) ss += __shfl_xor_sync(0xffffffffu, ss, o);
    if ((tid & 31) == 0) red[tid >> 5] = ss;
    __syncthreads();
    if (tid < 8) {
        float v = red[tid];
        #pragma unroll
        for (int o = 4; o; o >>= 1) v += __shfl_xor_sync(0xffu, v, o);
        if (tid == 0) red[0] = v;
    }
    __syncthreads();
    float rs = rsqrtf(red[0] / (float)DD + 1e-6f);
    const float4* g4 = (const float4*)g;
    float4 gg = g4[tid];
    ((float4*)(a + (size_t)r * DD))[tid] =
        make_float4(x.x*rs*gg.x, x.y*rs*gg.y, x.z*rs*gg.z, x.w*rs*gg.w);
}

// ---------------- K5: rmsnorm ----------------
__global__ void rmsnorm_kernel(const float* __restrict__ in, const float* __restrict__ g,
                               float* __restrict__ out) {
    __shared__ float red[8];
    int r = blockIdx.x, tid = threadIdx.x;
    const float4* x4 = (const float4*)(in + (size_t)r * DD);
    float4 x = x4[tid];
    float ss = x.x*x.x + x.y*x.y + x.z*x.z + x.w*x.w;
    #pragma unroll
    for (int o = 16; o; o >>= 1) ss += __shfl_xor_sync(0xffffffffu, ss, o);
    if ((tid & 31) == 0) red[tid >> 5] = ss;
    __syncthreads();
    if (tid < 8) {
        float v = red[tid];
        #pragma unroll
        for (int o = 4; o; o >>= 1) v += __shfl_xor_sync(0xffu, v, o);
        if (tid == 0) red[0] = v;
    }
    __syncthreads();
    float rs = rsqrtf(red[0] / (float)DD + 1e-6f);
    const float4* g4 = (const float4*)g;
    float4 gg = g4[tid];
    float4 o4 = make_float4(x.x*rs*gg.x, x.y*rs*gg.y, x.z*rs*gg.z, x.w*rs*gg.w);
    ((float4*)(out + (size_t)r * DD))[tid] = o4;
}

// ---------------- K6: TF32 GEMM 128x128x32, 3-stage cp.async, 1 sync/iter ----------------
// epi: 0 none, 1 gelu(acc+bias[col]), 2 acc+resid[row,col], 3 silu(acc)*aux[row,col]
#define AS_LD 36
#define BS_LD 136
#define A_TILE (128*AS_LD)
#define B_TILE (32*BS_LD)
#define GEMM_SMEM (3*(A_TILE + B_TILE)*4)   // 107520 bytes

__global__ __launch_bounds__(256)
void mma_gemm(const float* __restrict__ A, const float* __restrict__ B, float* __restrict__ C,
              int M, int N, int K, const float* __restrict__ aux, int epi) {
    extern __shared__ float dynsm[];
    float* As = dynsm;                 // [3][128][36]
    float* Bs = dynsm + 3*A_TILE;      // [3][32][136]

    int tid = threadIdx.x;
    int m0 = blockIdx.y * 128, n0 = blockIdx.x * 128;
    int warp = tid >> 5, lane = tid & 31;
    int wm = (warp >> 2) * 64;
    int wn = (warp & 3) * 32;
    int g = lane >> 2, c = lane & 3;

    float acc[4][4][4];
    #pragma unroll
    for (int i = 0; i < 4; i++)
        #pragma unroll
        for (int j = 0; j < 4; j++)
            #pragma unroll
            for (int r = 0; r < 4; r++) acc[i][j][r] = 0.f;

    int aRow = tid >> 1;
    int aSeg = (tid & 1) * 16;
    int bRow = tid >> 3;
    int bSeg = (tid & 7) * 16;

    uint32_t asBase = (uint32_t)__cvta_generic_to_shared(As);
    uint32_t bsBase = (uint32_t)__cvta_generic_to_shared(Bs);

    int nk = K / 32;

    auto prefetch = [&](int kt) {
        int st = kt % 3;
        const float* Ag = A + (size_t)(m0 + aRow) * K + kt*32 + aSeg;
        uint32_t ad = asBase + (st*A_TILE + aRow*AS_LD + aSeg) * 4;
        #pragma unroll
        for (int i = 0; i < 4; i++) cpa16(ad + i*16, Ag + i*4);
        const float* Bg = B + (size_t)(kt*32 + bRow) * N + n0 + bSeg;
        uint32_t bd = bsBase + (st*B_TILE + bRow*BS_LD + bSeg) * 4;
        #pragma unroll
        for (int i = 0; i < 4; i++) cpa16(bd + i*16, Bg + i*4);
        asm volatile("cp.async.commit_group;" ::: "memory");
    };

    prefetch(0);
    prefetch(1);

    for (int kt = 0; kt < nk; kt++) {
        if (kt + 1 < nk) {
            asm volatile("cp.async.wait_group 1;" ::: "memory");
        } else {
            asm volatile("cp.async.wait_group 0;" ::: "memory");
        }
        __syncthreads();
        if (kt + 2 < nk) prefetch(kt + 2);

        int st = kt % 3;
        const float* as = As + st * A_TILE;
        const float* bs = Bs + st * B_TILE;
        #pragma unroll
        for (int ks = 0; ks < 32; ks += 8) {
            uint32_t af[4][4], bf[4][2];
            #pragma unroll
            for (int i = 0; i < 4; i++) {
                int mb = wm + i*16;
                af[i][0] = *(const uint32_t*)&as[(mb+g  )*AS_LD + ks + c];
                af[i][1] = *(const uint32_t*)&as[(mb+g+8)*AS_LD + ks + c];
                af[i][2] = *(const uint32_t*)&as[(mb+g  )*AS_LD + ks + c + 4];
                af[i][3] = *(const uint32_t*)&as[(mb+g+8)*AS_LD + ks + c + 4];
            }
            #pragma unroll
            for (int j = 0; j < 4; j++) {
                int nb = wn + j*8;
                bf[j][0] = *(const uint32_t*)&bs[(ks+c  )*BS_LD + nb + g];
                bf[j][1] = *(const uint32_t*)&bs[(ks+c+4)*BS_LD + nb + g];
            }
            #pragma unroll
            for (int i = 0; i < 4; i++)
                #pragma unroll
                for (int j = 0; j < 4; j++)
                    mma_tf32(acc[i][j], af[i][0], af[i][1], af[i][2], af[i][3],
                             bf[j][0], bf[j][1]);
        }
    }

    #pragma unroll
    for (int i = 0; i < 4; i++) {
        int r0 = m0 + wm + i*16 + g;
        #pragma unroll
        for (int j = 0; j < 4; j++) {
            int col = n0 + wn + j*8 + c*2;
            float2 lo = make_float2(acc[i][j][0], acc[i][j][1]);
            float2 hi = make_float2(acc[i][j][2], acc[i][j][3]);
            if (epi == 1) {
                float b0 = aux[col], b1 = aux[col+1];
                lo.x = gelu_tanh(lo.x + b0); lo.y = gelu_tanh(lo.y + b1);
                hi.x = gelu_tanh(hi.x + b0); hi.y = gelu_tanh(hi.y + b1);
            } else if (epi == 2) {
                const float2 s0 = *(const float2*)&aux[(size_t)r0*N + col];
                const float2 s1 = *(const float2*)&aux[(size_t)(r0+8)*N + col];
                lo.x += s0.x; lo.y += s0.y; hi.x += s1.x; hi.y += s1.y;
            } else if (epi == 3) {
                const float2 u0 = *(const float2*)&aux[(size_t)r0*N + col];
                const float2 u1 = *(const float2*)&aux[(size_t)(r0+8)*N + col];
                lo.x = lo.x / (1.f + expf(-lo.x)) * u0.x;
                lo.y = lo.y / (1.f + expf(-lo.y)) * u0.y;
                hi.x = hi.x / (1.f + expf(-hi.x)) * u1.x;
                hi.y = hi.y / (1.f + expf(-hi.y)) * u1.y;
            }
            *(float2*)&C[(size_t)r0*N + col] = lo;
            *(float2*)&C[(size_t)(r0+8)*N + col] = hi;
        }
    }
}

// ---------------- K7: RoPE (q and k in one launch) ----------------
__global__ void rope2_kernel(float* __restrict__ q, float* __restrict__ k,
                             const int* __restrict__ idx) {
    int blk = blockIdx.x;
    float* buf = (blk < ROWS) ? q : k;
    int r = (blk < ROWS) ? blk : blk - ROWS;
    float pos = (float)idx[r];
    float* base = buf + (size_t)r * DD;
    const float C = -0.415241011861f;   // -log2(10000)/32
    for (int c = threadIdx.x; c < 512; c += 256) {
        int h = c >> 5, i = c & 31;
        float inv = exp2f((float)i * C);
        float ang = pos * inv;
        float s, co; sincosf(ang, &s, &co);
        float* p = base + h * 64;
        float x1 = p[i], x2 = p[i + 32];
        p[i]      = x1*co - x2*s;
        p[i + 32] = x2*co + x1*s;
    }
}

// ---------------- K8: fused flash attention (replaces qk/softmax/pv) ----------------
// grid (4, BB*HH); block 256; each block = 128 q-rows of one (b,h)
#define FLASH_SMEM ((64*68 + 64*72 + 128*68)*4)   // Ks, Vs, Ps = 70656 bytes

__global__ __launch_bounds__(256)
void flash_kernel(const float* __restrict__ q, const float* __restrict__ k,
                  const float* __restrict__ v, float* __restrict__ pv) {
    extern __shared__ float fsm[];
    float* Ks = fsm;                       // [64][68]
    float* Vs = fsm + 64*68;               // [64][72]
    float* Ps = fsm + 64*68 + 64*72;       // [128][68]

    int qp = 3 - blockIdx.x;               // heavy blocks first
    int bh = blockIdx.y, b = bh >> 4, h = bh & 15;
    int tid = threadIdx.x;
    int w = tid >> 5, lane = tid & 31, g = lane >> 2, c = lane & 3;

    // stage Q tile (128x64) through Ps, extract a-fragments into registers
    #pragma unroll
    for (int p = 0; p < 8; p++) {
        int e = p*256 + tid;
        int row = e >> 4, col = (e & 15) * 4;
        *(float4*)&Ps[row*68 + col] =
            *(const float4*)&q[((size_t)(b*KS + qp*128 + row))*DD + h*64 + col];
    }
    __syncthreads();
    uint32_t qa[8][4];
    {
        const float* pr0 = &Ps[(w*16 + g)*68];
        const float* pr1 = &Ps[(w*16 + g + 8)*68];
        #pragma unroll
        for (int d8 = 0; d8 < 8; d8++) {
            qa[d8][0] = *(const uint32_t*)&pr0[d8*8 + c];
            qa[d8][1] = *(const uint32_t*)&pr1[d8*8 + c];
            qa[d8][2] = *(const uint32_t*)&pr0[d8*8 + c + 4];
            qa[d8][3] = *(const uint32_t*)&pr1[d8*8 + c + 4];
        }
    }

    float o[8][4];
    #pragma unroll
    for (int j = 0; j < 8; j++)
        #pragma unroll
        for (int r = 0; r < 4; r++) o[j][r] = 0.f;
    float m0 = -1e38f, m1 = -1e38f, l0 = 0.f, l1 = 0.f;

    int q0 = qp*128 + w*16 + g;
    int q1 = q0 + 8;
    const float SC = 0.125f;
    int ktmax = 2*qp + 1;

    for (int kt = 0; kt <= ktmax; kt++) {
        __syncthreads();   // previous iteration's Ks/Vs reads done
        #pragma unroll
        for (int p = 0; p < 4; p++) {
            int e = p*256 + tid;
            int row = e >> 4, col = (e & 15) * 4;
            *(float4*)&Ks[row*68 + col] =
                *(const float4*)&k[((size_t)(b*KS + kt*64 + row))*DD + h*64 + col];
            *(float4*)&Vs[row*72 + col] =
                *(const float4*)&v[((size_t)(b*KS + kt*64 + row))*DD + h*64 + col];
        }
        __syncthreads();

        // S = Q K^T
        float s[8][4];
        #pragma unroll
        for (int j = 0; j < 8; j++)
            #pragma unroll
            for (int r = 0; r < 4; r++) s[j][r] = 0.f;
        #pragma unroll
        for (int d8 = 0; d8 < 8; d8++) {
            #pragma unroll
            for (int j = 0; j < 8; j++) {
                uint32_t b0 = *(const uint32_t*)&Ks[(j*8+g)*68 + d8*8 + c];
                uint32_t b1 = *(const uint32_t*)&Ks[(j*8+g)*68 + d8*8 + c + 4];
                mma_tf32(s[j], qa[d8][0], qa[d8][1], qa[d8][2], qa[d8][3], b0, b1);
            }
        }

        // scale + causal mask + row max
        float mx0 = m0, mx1 = m1;
        #pragma unroll
        for (int j = 0; j < 8; j++) {
            int kc = kt*64 + j*8 + c*2;
            s[j][0] = (kc   <= q0) ? s[j][0]*SC : -1e30f;
            s[j][1] = (kc+1 <= q0) ? s[j][1]*SC : -1e30f;
            s[j][2] = (kc   <= q1) ? s[j][2]*SC : -1e30f;
            s[j][3] = (kc+1 <= q1) ? s[j][3]*SC : -1e30f;
            mx0 = fmaxf(mx0, fmaxf(s[j][0], s[j][1]));
            mx1 = fmaxf(mx1, fmaxf(s[j][2], s[j][3]));
        }
        mx0 = fmaxf(mx0, __shfl_xor_sync(0xffffffffu, mx0, 1));
        mx0 = fmaxf(mx0, __shfl_xor_sync(0xffffffffu, mx0, 2));
        mx1 = fmaxf(mx1, __shfl_xor_sync(0xffffffffu, mx1, 1));
        mx1 = fmaxf(mx1, __shfl_xor_sync(0xffffffffu, mx1, 2));

        float al0 = expf(m0 - mx0), al1 = expf(m1 - mx1);
        m0 = mx0; m1 = mx1;
        float sum0 = 0.f, sum1 = 0.f;
        #pragma unroll
        for (int j = 0; j < 8; j++) {
            s[j][0] = expf(s[j][0] - mx0);
            s[j][1] = expf(s[j][1] - mx0);
            s[j][2] = expf(s[j][2] - mx1);
            s[j][3] = expf(s[j][3] - mx1);
            sum0 += s[j][0] + s[j][1];
            sum1 += s[j][2] + s[j][3];
        }
        sum0 += __shfl_xor_sync(0xffffffffu, sum0, 1);
        sum0 += __shfl_xor_sync(0xffffffffu, sum0, 2);
        sum1 += __shfl_xor_sync(0xffffffffu, sum1, 1);
        sum1 += __shfl_xor_sync(0xffffffffu, sum1, 2);
        l0 = l0*al0 + sum0;
        l1 = l1*al1 + sum1;
        #pragma unroll
        for (int j = 0; j < 8; j++) {
            o[j][0] *= al0; o[j][1] *= al0;
            o[j][2] *= al1; o[j][3] *= al1;
        }

        // P -> smem (own rows only), reload as a-frags
        {
            float* pr0 = &Ps[(w*16 + g)*68];
            float* pr1 = &Ps[(w*16 + g + 8)*68];
            #pragma unroll
            for (int j = 0; j < 8; j++) {
                *(float2*)&pr0[j*8 + c*2] = make_float2(s[j][0], s[j][1]);
                *(float2*)&pr1[j*8 + c*2] = make_float2(s[j][2], s[j][3]);
            }
        }
        __syncwarp();

        // O += P V
        {
            const float* pr0 = &Ps[(w*16 + g)*68];
            const float* pr1 = &Ps[(w*16 + g + 8)*68];
            #pragma unroll
            for (int k8 = 0; k8 < 8; k8++) {
                uint32_t pa0 = *(const uint32_t*)&pr0[k8*8 + c];
                uint32_t pa1 = *(const uint32_t*)&pr1[k8*8 + c];
                uint32_t pa2 = *(const uint32_t*)&pr0[k8*8 + c + 4];
                uint32_t pa3 = *(const uint32_t*)&pr1[k8*8 + c + 4];
                #pragma unroll
                for (int j = 0; j < 8; j++) {
                    uint32_t b0 = *(const uint32_t*)&Vs[(k8*8+c  )*72 + j*8 + g];
                    uint32_t b1 = *(const uint32_t*)&Vs[(k8*8+c+4)*72 + j*8 + g];
                    mma_tf32(o[j], pa0, pa1, pa2, pa3, b0, b1);
                }
            }
        }
    }

    float inv0 = 1.f / l0, inv1 = 1.f / l1;
    size_t r0 = (size_t)(b*KS + q0) * DD + h*64;
    size_t r1 = (size_t)(b*KS + q1) * DD + h*64;
    #pragma unroll
    for (int j = 0; j < 8; j++) {
        *(float2*)&pv[r0 + j*8 + c*2] = make_float2(o[j][0]*inv0, o[j][1]*inv0);
        *(float2*)&pv[r1 + j*8 + c*2] = make_float2(o[j][2]*inv1, o[j][3]*inv1);
    }
}

// ---------------- K12: scatter ----------------
__global__ void scatter_kernel(const float* __restrict__ sel, const float* __restrict__ bo,
                               const int* __restrict__ idx, const float* __restrict__ gate,
                               float* __restrict__ out) {
    int r = blockIdx.x;
    int b = r / KS;
    int pos = idx[r];
    float ga = gate[r];
    const float4* s4 = (const float4*)(sel + (size_t)r * DD);
    const float4* b4 = (const float4*)(bo  + (size_t)r * DD);
    float4* o4 = (float4*)(out + ((size_t)b*TT + pos) * DD);
    float4 s = s4[threadIdx.x], bb = b4[threadIdx.x];
    float4 u = make_float4(s.x + ga*(bb.x - s.x), s.y + ga*(bb.y - s.y),
                           s.z + ga*(bb.z - s.z), s.w + ga*(bb.w - s.w));
    o4[threadIdx.x] = u;
}

// ---------------- K13: predictor logits + per-row BCE ----------------
__global__ void predrow_kernel(const float* __restrict__ h1, const float* __restrict__ fc2w,
                               const float* __restrict__ fc2b, const float* __restrict__ tgt,
                               float* __restrict__ pred) {
    int warp = (blockIdx.x * blockDim.x + threadIdx.x) >> 5;
    int lane = threadIdx.x & 31;
    if (warp >= NTOK) return;
    const float* row = h1 + (size_t)warp * DQ;
    float s = 0.f;
    #pragma unroll
    for (int i = lane; i < DQ; i += 32) s += row[i] * fc2w[i];
    #pragma unroll
    for (int o = 16; o; o >>= 1) s += __shfl_xor_sync(0xffffffffu, s, o);
    if (lane == 0) {
        float x = s + fc2b[0];
        pred[warp] = bce_term(x, tgt[warp]);
    }
}

// ---------------- K14: loss reduce ----------------
__global__ void loss_reduce(const float* __restrict__ scores, const float* __restrict__ tgt,
                            const float* __restrict__ pred, float* __restrict__ out_aux) {
    __shared__ float sm_main[1024];
    __shared__ float sm_pred[1024];
    int tid = threadIdx.x;
    float sm = 0.f, sp = 0.f;
    for (int i = tid; i < NTOK; i += 1024) {
        sm += bce_term(scores[i], tgt[i]);
        sp += pred[i];
    }
    sm_main[tid] = sm; sm_pred[tid] = sp;
    __syncthreads();
    for (int s = 512; s > 0; s >>= 1) {
        if (tid < s) { sm_main[tid] += sm_main[tid+s]; sm_pred[tid] += sm_pred[tid+s]; }
        __syncthreads();
    }
    if (tid == 0)
        out_aux[0] = 0.01f * (sm_main[0] + sm_pred[0]) / (float)NTOK;
}

// ---------------- host launch ----------------
extern "C" void kernel_launch(void* const* d_in, const int* in_sizes, int n_in,
                              void* d_out, int out_size) {
    const float* hs   = (const float*)d_in[0];
    const float* rw   = (const float*)d_in[1];
    const float* fc1w = (const float*)d_in[2];
    const float* fc1b = (const float*)d_in[3];
    const float* fc2w = (const float*)d_in[4];
    const float* fc2b = (const float*)d_in[5];
    const float* ln1  = (const float*)d_in[6];
    const float* ln2  = (const float*)d_in[7];
    const float* wq   = (const float*)d_in[8];
    const float* wk   = (const float*)d_in[9];
    const float* wv   = (const float*)d_in[10];
    const float* wo   = (const float*)d_in[11];
    const float* wg   = (const float*)d_in[12];
    const float* wu   = (const float*)d_in[13];
    const float* wd   = (const float*)d_in[14];
    float* out = (float*)d_out;

    float *scores, *tgt, *gate, *sel, *a, *q, *k, *v, *pv, *h, *m, *gb, *ub, *bo, *h1, *pred;
    int* idx;
    cudaGetSymbolAddress((void**)&scores, g_scores);
    cudaGetSymbolAddress((void**)&tgt,    g_tgt);
    cudaGetSymbolAddress((void**)&idx,    g_idx);
    cudaGetSymbolAddress((void**)&gate,   g_gate);
    cudaGetSymbolAddress((void**)&sel,    g_sel);
    cudaGetSymbolAddress((void**)&a,      g_a);
    cudaGetSymbolAddress((void**)&q,      g_q);
    cudaGetSymbolAddress((void**)&k,      g_k);
    cudaGetSymbolAddress((void**)&v,      g_v);
    cudaGetSymbolAddress((void**)&pv,     g_pv);
    cudaGetSymbolAddress((void**)&h,      g_h);
    cudaGetSymbolAddress((void**)&m,      g_m);
    cudaGetSymbolAddress((void**)&gb,     g_gb);
    cudaGetSymbolAddress((void**)&ub,     g_ub);
    cudaGetSymbolAddress((void**)&bo,     g_bo);
    cudaGetSymbolAddress((void**)&h1,     g_h1);
    cudaGetSymbolAddress((void**)&pred,   g_pred);

    cudaFuncSetAttribute(mma_gemm, cudaFuncAttributeMaxDynamicSharedMemorySize, GEMM_SMEM);
    cudaFuncSetAttribute(flash_kernel, cudaFuncAttributeMaxDynamicSharedMemorySize, FLASH_SMEM);

    // ---- fork: copy runs on s2 concurrently with router/topk ----
    cudaEventRecord(eStart, 0);
    cudaStreamWaitEvent(s2, eStart, 0);
    copy_kernel<<<4096, 256, 0, s2>>>((const float4*)hs, (float4*)out, NTOK*DD/4);
    cudaEventRecord(eC, s2);

    // ---- router + top-k on main stream ----
    scores_kernel<<<NTOK/8, 256>>>(hs, rw, scores);
    topk_radix<<<BB, 1024>>>(scores, tgt, idx, gate);
    cudaEventRecord(eTopk, 0);

    // ---- predictor path on s1 ----
    cudaStreamWaitEvent(s1, eTopk, 0);
    mma_gemm<<<dim3(DQ/128, NTOK/128), 256, GEMM_SMEM, s1>>>(hs, fc1w, h1, NTOK, DQ, DD, fc1b, 1);
    predrow_kernel<<<NTOK/8, 256, 0, s1>>>(h1, fc2w, fc2b, tgt, pred);
    cudaEventRecord(eP, s1);

    // ---- decoder block ----
    gather_rms_kernel<<<ROWS, 256>>>(hs, idx, ln1, sel, a);
    cudaEventRecord(eA, 0);
    cudaStreamWaitEvent(s2, eA, 0);
    cudaStreamWaitEvent(s3, eA, 0);
    mma_gemm<<<dim3(DD/128, ROWS/128), 256, GEMM_SMEM, s2>>>(a, wk, k, ROWS, DD, DD, nullptr, 0);
    cudaEventRecord(eK, s2);
    mma_gemm<<<dim3(DD/128, ROWS/128), 256, GEMM_SMEM, s3>>>(a, wv, v, ROWS, DD, DD, nullptr, 0);
    cudaEventRecord(eV, s3);
    mma_gemm<<<dim3(DD/128, ROWS/128), 256, GEMM_SMEM>>>(a, wq, q, ROWS, DD, DD, nullptr, 0);
    cudaStreamWaitEvent(0, eK, 0);
    rope2_kernel<<<2*ROWS, 256>>>(q, k, idx);
    cudaStreamWaitEvent(0, eV, 0);
    flash_kernel<<<dim3(4, BB*HH), 256, FLASH_SMEM>>>(q, k, v, pv);
    mma_gemm<<<dim3(DD/128, ROWS/128), 256, GEMM_SMEM>>>(pv, wo, h, ROWS, DD, DD, sel, 2);

    rmsnorm_kernel<<<ROWS, 256>>>(h, ln2, m);
    mma_gemm<<<dim3(FF/128, ROWS/128), 256, GEMM_SMEM>>>(m, wu, ub, ROWS, FF, DD, nullptr, 0);
    mma_gemm<<<dim3(FF/128, ROWS/128), 256, GEMM_SMEM>>>(m, wg, gb, ROWS, FF, DD, ub, 3);
    mma_gemm<<<dim3(DD/128, ROWS/128), 256, GEMM_SMEM>>>(gb, wd, bo, ROWS, DD, FF, h, 2);

    cudaStreamWaitEvent(0, eC, 0);
    scatter_kernel<<<ROWS, 256>>>(sel, bo, idx, gate, out);

    cudaStreamWaitEvent(0, eP, 0);
    loss_reduce<<<1, 1024>>>(scores, tgt, pred, out + (size_t)NTOK*DD);
}

// round 6
// speedup vs baseline: 5.3858x; 1.7656x over previous
#include <cuda_runtime.h>
#include <cuda_fp16.h>
#include <math.h>
#include <stdint.h>

// ---------------- problem constants ----------------
#define BB 4
#define TT 4096
#define DD 1024
#define FF 4096
#define HH 16
#define HD 64
#define KS 512
#define DQ 256
#define ROWS (BB*KS)           // 2048
#define NTOK (BB*TT)           // 16384

// ---------------- device scratch ----------------
__device__ float  g_scores[NTOK];
__device__ float  g_tgt[NTOK];
__device__ int    g_idx[ROWS];
__device__ float  g_gate[ROWS];
__device__ float  g_sel[ROWS*DD];
__device__ __half g_a16[ROWS*DD];
__device__ __half g_q16[ROWS*DD];
__device__ __half g_k16[ROWS*DD];
__device__ __half g_v16[ROWS*DD];
__device__ __half g_pv16[ROWS*DD];
__device__ float  g_h[ROWS*DD];
__device__ __half g_m16[ROWS*DD];
__device__ float  g_ub[ROWS*FF];
__device__ __half g_gb16[ROWS*FF];
__device__ float  g_bo[ROWS*DD];
__device__ __half g_hs16[(size_t)NTOK*DD];
__device__ float  g_h1[(size_t)NTOK*DQ];
__device__ float  g_pred[NTOK];
// transposed fp16 weights [N][K]
__device__ __half g_wqT[DD*DD];
__device__ __half g_wkT[DD*DD];
__device__ __half g_wvT[DD*DD];
__device__ __half g_woT[DD*DD];
__device__ __half g_wuT[(size_t)FF*DD];
__device__ __half g_wgT[(size_t)FF*DD];
__device__ __half g_wdT[(size_t)DD*FF];
__device__ __half g_fc1T[DQ*DD];

// ---------------- static streams/events ----------------
static cudaStream_t s1, s2, s3;
static cudaEvent_t eStart, eTopk, eA, eK, eV, eP, eC, eW;
static struct StreamInit {
    StreamInit() {
        cudaStreamCreateWithFlags(&s1, cudaStreamNonBlocking);
        cudaStreamCreateWithFlags(&s2, cudaStreamNonBlocking);
        cudaStreamCreateWithFlags(&s3, cudaStreamNonBlocking);
        cudaEventCreateWithFlags(&eStart, cudaEventDisableTiming);
        cudaEventCreateWithFlags(&eTopk,  cudaEventDisableTiming);
        cudaEventCreateWithFlags(&eA,     cudaEventDisableTiming);
        cudaEventCreateWithFlags(&eK,     cudaEventDisableTiming);
        cudaEventCreateWithFlags(&eV,     cudaEventDisableTiming);
        cudaEventCreateWithFlags(&eP,     cudaEventDisableTiming);
        cudaEventCreateWithFlags(&eC,     cudaEventDisableTiming);
        cudaEventCreateWithFlags(&eW,     cudaEventDisableTiming);
    }
} s_init;

// ---------------- helpers ----------------
__device__ __forceinline__ float gelu_tanh(float x) {
    float x3 = x*x*x;
    return 0.5f * x * (1.f + tanhf(0.7978845608028654f * (x + 0.044715f * x3)));
}
__device__ __forceinline__ float bce_term(float x, float t) {
    return fmaxf(x, 0.f) - x*t + log1pf(expf(-fabsf(x)));
}
__device__ __forceinline__ void cpa16(uint32_t s, const void* g) {
    asm volatile("cp.async.cg.shared.global [%0], [%1], 16;" :: "r"(s), "l"(g));
}
__device__ __forceinline__ void mma_f16(float* d, uint32_t a0, uint32_t a1, uint32_t a2, uint32_t a3,
                                        uint32_t b0, uint32_t b1) {
    asm volatile(
        "mma.sync.aligned.m16n8k16.row.col.f32.f16.f16.f32 "
        "{%0,%1,%2,%3}, {%4,%5,%6,%7}, {%8,%9}, {%0,%1,%2,%3};"
        : "+f"(d[0]), "+f"(d[1]), "+f"(d[2]), "+f"(d[3])
        : "r"(a0), "r"(a1), "r"(a2), "r"(a3), "r"(b0), "r"(b1));
}
__device__ __forceinline__ void ldsm_x4_t(uint32_t& r0, uint32_t& r1, uint32_t& r2, uint32_t& r3,
                                          uint32_t addr) {
    asm volatile("ldmatrix.sync.aligned.m8n8.x4.trans.shared.b16 {%0,%1,%2,%3}, [%4];"
        : "=r"(r0), "=r"(r1), "=r"(r2), "=r"(r3) : "r"(addr));
}

// ---------------- W0: weight transpose + f32->f16: w[K][N] -> wt[N][K] ----------------
__global__ void wconv_kernel(const float* __restrict__ w, __half* __restrict__ wt, int K, int N) {
    __shared__ float t[32][33];
    int k0 = blockIdx.y * 32, n0 = blockIdx.x * 32;
    int tx = threadIdx.x & 31, ty = threadIdx.x >> 5;   // 32 x 8
    #pragma unroll
    for (int i = 0; i < 32; i += 8)
        t[ty + i][tx] = w[(size_t)(k0 + ty + i) * N + n0 + tx];
    __syncthreads();
    #pragma unroll
    for (int i = 0; i < 32; i += 8)
        wt[(size_t)(n0 + ty + i) * K + k0 + tx] = __float2half_rn(t[tx][ty + i]);
}

// ---------------- W1: elementwise f32->f16 ----------------
__global__ void f2h_kernel(const float4* __restrict__ src, uint2* __restrict__ dst, int n4) {
    int stride = gridDim.x * blockDim.x;
    for (int i = blockIdx.x * blockDim.x + threadIdx.x; i < n4; i += stride) {
        float4 v = src[i];
        __half2 a = __float22half2_rn(make_float2(v.x, v.y));
        __half2 b = __float22half2_rn(make_float2(v.z, v.w));
        dst[i] = make_uint2(*(uint32_t*)&a, *(uint32_t*)&b);
    }
}

// ---------------- K1: router scores ----------------
__global__ void scores_kernel(const float* __restrict__ hs, const float* __restrict__ rw,
                              float* __restrict__ scores) {
    int warp = (blockIdx.x * blockDim.x + threadIdx.x) >> 5;
    int lane = threadIdx.x & 31;
    if (warp >= NTOK) return;
    const float4* row = (const float4*)(hs + (size_t)warp * DD);
    const float4* w4  = (const float4*)rw;
    float s = 0.f;
    #pragma unroll 4
    for (int i = lane; i < DD/4; i += 32) {
        float4 a = row[i], b = w4[i];
        s += a.x*b.x + a.y*b.y + a.z*b.z + a.w*b.w;
    }
    #pragma unroll
    for (int o = 16; o; o >>= 1) s += __shfl_xor_sync(0xffffffffu, s, o);
    if (lane == 0) scores[warp] = s;
}

// ---------------- K2: radix-select top-k + ascending compaction ----------------
__global__ void topk_radix(const float* __restrict__ scores, float* __restrict__ tgt,
                           int* __restrict__ idxo, float* __restrict__ gateo) {
    __shared__ unsigned su[TT];
    __shared__ int hist[256];
    __shared__ int wsum[32];
    __shared__ unsigned s_prefix;
    __shared__ int s_remain;
    int b = blockIdx.x, tid = threadIdx.x;
    const float* sc = scores + (size_t)b * TT;

    for (int i = tid; i < TT; i += 1024) {
        unsigned bits = __float_as_uint(sc[i]);
        unsigned mask = (unsigned)((int)bits >> 31) | 0x80000000u;
        su[i] = bits ^ mask;
    }
    if (tid == 0) { s_prefix = 0u; s_remain = KS; }
    __syncthreads();

    #pragma unroll
    for (int p = 24; p >= 0; p -= 8) {
        if (tid < 256) hist[tid] = 0;
        __syncthreads();
        unsigned pref = s_prefix;
        for (int i = tid; i < TT; i += 1024) {
            unsigned u = su[i];
            if (p == 24 || (u >> (p + 8)) == (pref >> (p + 8)))
                atomicAdd(&hist[(u >> p) & 255], 1);
        }
        __syncthreads();
        if (tid == 0) {
            int rem = s_remain;
            int bin = 255;
            for (;;) {
                int c = hist[bin];
                if (rem <= c) break;
                rem -= c; bin--;
            }
            s_prefix = pref | ((unsigned)bin << p);
            s_remain = rem;
        }
        __syncthreads();
    }
    unsigned thr = s_prefix;

    int base = tid * 4;
    int flg[4]; int cnt = 0;
    #pragma unroll
    for (int j = 0; j < 4; j++) { flg[j] = (su[base + j] >= thr) ? 1 : 0; cnt += flg[j]; }
    int lane = tid & 31, warp = tid >> 5;
    int inc = cnt;
    #pragma unroll
    for (int o = 1; o < 32; o <<= 1) {
        int n2 = __shfl_up_sync(0xffffffffu, inc, o);
        if (lane >= o) inc += n2;
    }
    if (lane == 31) wsum[warp] = inc;
    __syncthreads();
    if (tid < 32) {
        int v = wsum[tid];
        #pragma unroll
        for (int o = 1; o < 32; o <<= 1) {
            int n2 = __shfl_up_sync(0xffffffffu, v, o);
            if (tid >= o) v += n2;
        }
        wsum[tid] = v;
    }
    __syncthreads();
    int off = inc - cnt + (warp ? wsum[warp - 1] : 0);
    #pragma unroll
    for (int j = 0; j < 4; j++) {
        tgt[(size_t)b*TT + base + j] = flg[j] ? 1.f : 0.f;
        if (flg[j]) {
            idxo[b*KS + off] = base + j;
            float s = sc[base + j];
            gateo[b*KS + off] = 1.f / (1.f + expf(-s));
            off++;
        }
    }
}

// ---------------- K3: copy hidden -> out ----------------
__global__ void copy_kernel(const float4* __restrict__ src, float4* __restrict__ dst, int n4) {
    int stride = gridDim.x * blockDim.x;
    for (int i = blockIdx.x * blockDim.x + threadIdx.x; i < n4; i += stride)
        dst[i] = src[i];
}

// ---------------- K4: fused gather + rmsnorm(ln1) -> sel f32, a f16 ----------------
__global__ void gather_rms_kernel(const float* __restrict__ hs, const int* __restrict__ idx,
                                  const float* __restrict__ g,
                                  float* __restrict__ sel, __half* __restrict__ a16) {
    __shared__ float red[8];
    int r = blockIdx.x, tid = threadIdx.x;
    int b = r / KS;
    int pos = idx[r];
    const float4* src = (const float4*)(hs + ((size_t)b*TT + pos) * DD);
    float4 x = src[tid];
    ((float4*)(sel + (size_t)r * DD))[tid] = x;
    float ss = x.x*x.x + x.y*x.y + x.z*x.z + x.w*x.w;
    #pragma unroll
    for (int o = 16; o; o >>= 1) ss += __shfl_xor_sync(0xffffffffu, ss, o);
    if ((tid & 31) == 0) red[tid >> 5] = ss;
    __syncthreads();
    if (tid < 8) {
        float v = red[tid];
        #pragma unroll
        for (int o = 4; o; o >>= 1) v += __shfl_xor_sync(0xffu, v, o);
        if (tid == 0) red[0] = v;
    }
    __syncthreads();
    float rs = rsqrtf(red[0] / (float)DD + 1e-6f);
    const float4* g4 = (const float4*)g;
    float4 gg = g4[tid];
    __half2 h0 = __float22half2_rn(make_float2(x.x*rs*gg.x, x.y*rs*gg.y));
    __half2 h1 = __float22half2_rn(make_float2(x.z*rs*gg.z, x.w*rs*gg.w));
    uint2* dst = (uint2*)(a16 + (size_t)r * DD);
    dst[tid] = make_uint2(*(uint32_t*)&h0, *(uint32_t*)&h1);
}

// ---------------- K5: rmsnorm f32 -> f16 ----------------
__global__ void rmsnorm_h_kernel(const float* __restrict__ in, const float* __restrict__ g,
                                 __half* __restrict__ out) {
    __shared__ float red[8];
    int r = blockIdx.x, tid = threadIdx.x;
    const float4* x4 = (const float4*)(in + (size_t)r * DD);
    float4 x = x4[tid];
    float ss = x.x*x.x + x.y*x.y + x.z*x.z + x.w*x.w;
    #pragma unroll
    for (int o = 16; o; o >>= 1) ss += __shfl_xor_sync(0xffffffffu, ss, o);
    if ((tid & 31) == 0) red[tid >> 5] = ss;
    __syncthreads();
    if (tid < 8) {
        float v = red[tid];
        #pragma unroll
        for (int o = 4; o; o >>= 1) v += __shfl_xor_sync(0xffu, v, o);
        if (tid == 0) red[0] = v;
    }
    __syncthreads();
    float rs = rsqrtf(red[0] / (float)DD + 1e-6f);
    const float4* g4 = (const float4*)g;
    float4 gg = g4[tid];
    __half2 h0 = __float22half2_rn(make_float2(x.x*rs*gg.x, x.y*rs*gg.y));
    __half2 h1 = __float22half2_rn(make_float2(x.z*rs*gg.z, x.w*rs*gg.w));
    uint2* dst = (uint2*)(out + (size_t)r * DD);
    dst[tid] = make_uint2(*(uint32_t*)&h0, *(uint32_t*)&h1);
}

// ---------------- K6: FP16 GEMM 128x128x32, 3-stage cp.async ----------------
// A[M,K] f16 row-major, Bt[N,K] f16 row-major. epi: 0 none, 1 gelu(+bias), 2 +resid, 3 silu*aux
// ohalf: write C as f16 (else f32)
#define LDH 40                       // halfs per smem row (32 + 8 pad)
#define T_ST (128*LDH)               // halfs per tile stage
#define GEMM_SMEM (3*2*T_ST*2)       // 61440 bytes

__global__ __launch_bounds__(256)
void mma_gemm(const __half* __restrict__ A, const __half* __restrict__ Bt, void* __restrict__ Cv,
              int M, int N, int K, const float* __restrict__ aux, int epi, int ohalf) {
    extern __shared__ __half dynh[];
    __half* As = dynh;                // [3][128][40]
    __half* Bs = dynh + 3*T_ST;       // [3][128][40]

    int tid = threadIdx.x;
    int m0 = blockIdx.y * 128, n0 = blockIdx.x * 128;
    int warp = tid >> 5, lane = tid & 31;
    int wm = (warp >> 2) * 64;
    int wn = (warp & 3) * 32;
    int g = lane >> 2, c = lane & 3;

    float acc[4][4][4];
    #pragma unroll
    for (int i = 0; i < 4; i++)
        #pragma unroll
        for (int j = 0; j < 4; j++)
            #pragma unroll
            for (int r = 0; r < 4; r++) acc[i][j][r] = 0.f;

    // cp.async: 2 16B chunks per thread per tile; 512 chunks = 128 rows x 4
    int ch0 = tid * 2;
    int ldRow = ch0 >> 2;            // 0..127
    int ldOff = (ch0 & 3) * 8;       // halfs: 0,16 (two chunks cover +0,+8 and +16,+24)

    uint32_t asBase = (uint32_t)__cvta_generic_to_shared(As);
    uint32_t bsBase = (uint32_t)__cvta_generic_to_shared(Bs);

    int nk = K / 32;

    auto prefetch = [&](int kt) {
        int st = kt % 3;
        const __half* Ag = A + (size_t)(m0 + ldRow) * K + kt*32 + ldOff;
        uint32_t ad = asBase + (st*T_ST + ldRow*LDH + ldOff) * 2;
        cpa16(ad,      Ag);
        cpa16(ad + 16, Ag + 8);
        const __half* Bg = Bt + (size_t)(n0 + ldRow) * K + kt*32 + ldOff;
        uint32_t bd = bsBase + (st*T_ST + ldRow*LDH + ldOff) * 2;
        cpa16(bd,      Bg);
        cpa16(bd + 16, Bg + 8);
        asm volatile("cp.async.commit_group;" ::: "memory");
    };

    prefetch(0);
    if (nk > 1) prefetch(1);

    for (int kt = 0; kt < nk; kt++) {
        if (kt + 1 < nk) {
            asm volatile("cp.async.wait_group 1;" ::: "memory");
        } else {
            asm volatile("cp.async.wait_group 0;" ::: "memory");
        }
        __syncthreads();
        if (kt + 2 < nk) prefetch(kt + 2);

        int st = kt % 3;
        const __half* as = As + st * T_ST;
        const __half* bs = Bs + st * T_ST;
        #pragma unroll
        for (int ks = 0; ks < 2; ks++) {          // two k16 slices
            int ko = ks * 16;
            uint32_t af[4][4], bf[4][2];
            #pragma unroll
            for (int i = 0; i < 4; i++) {
                int mb = wm + i*16;
                af[i][0] = *(const uint32_t*)&as[(mb+g  )*LDH + ko + c*2];
                af[i][1] = *(const uint32_t*)&as[(mb+g+8)*LDH + ko + c*2];
                af[i][2] = *(const uint32_t*)&as[(mb+g  )*LDH + ko + c*2 + 8];
                af[i][3] = *(const uint32_t*)&as[(mb+g+8)*LDH + ko + c*2 + 8];
            }
            #pragma unroll
            for (int j = 0; j < 4; j++) {
                int nb = wn + j*8;
                bf[j][0] = *(const uint32_t*)&bs[(nb+g)*LDH + ko + c*2];
                bf[j][1] = *(const uint32_t*)&bs[(nb+g)*LDH + ko + c*2 + 8];
            }
            #pragma unroll
            for (int i = 0; i < 4; i++)
                #pragma unroll
                for (int j = 0; j < 4; j++)
                    mma_f16(acc[i][j], af[i][0], af[i][1], af[i][2], af[i][3],
                            bf[j][0], bf[j][1]);
        }
    }

    float* C = (float*)Cv;
    __half* C16 = (__half*)Cv;
    #pragma unroll
    for (int i = 0; i < 4; i++) {
        int r0 = m0 + wm + i*16 + g;
        #pragma unroll
        for (int j = 0; j < 4; j++) {
            int col = n0 + wn + j*8 + c*2;
            float2 lo = make_float2(acc[i][j][0], acc[i][j][1]);
            float2 hi = make_float2(acc[i][j][2], acc[i][j][3]);
            if (epi == 1) {
                float b0 = aux[col], b1 = aux[col+1];
                lo.x = gelu_tanh(lo.x + b0); lo.y = gelu_tanh(lo.y + b1);
                hi.x = gelu_tanh(hi.x + b0); hi.y = gelu_tanh(hi.y + b1);
            } else if (epi == 2) {
                const float2 s0 = *(const float2*)&aux[(size_t)r0*N + col];
                const float2 s1 = *(const float2*)&aux[(size_t)(r0+8)*N + col];
                lo.x += s0.x; lo.y += s0.y; hi.x += s1.x; hi.y += s1.y;
            } else if (epi == 3) {
                const float2 u0 = *(const float2*)&aux[(size_t)r0*N + col];
                const float2 u1 = *(const float2*)&aux[(size_t)(r0+8)*N + col];
                lo.x = lo.x / (1.f + expf(-lo.x)) * u0.x;
                lo.y = lo.y / (1.f + expf(-lo.y)) * u0.y;
                hi.x = hi.x / (1.f + expf(-hi.x)) * u1.x;
                hi.y = hi.y / (1.f + expf(-hi.y)) * u1.y;
            }
            if (ohalf) {
                __half2 l2 = __float22half2_rn(lo);
                __half2 h2 = __float22half2_rn(hi);
                *(__half2*)&C16[(size_t)r0*N + col] = l2;
                *(__half2*)&C16[(size_t)(r0+8)*N + col] = h2;
            } else {
                *(float2*)&C[(size_t)r0*N + col] = lo;
                *(float2*)&C[(size_t)(r0+8)*N + col] = hi;
            }
        }
    }
}

// ---------------- K7: RoPE fp16 (q and k in one launch) ----------------
__global__ void rope2h_kernel(__half* __restrict__ q, __half* __restrict__ k,
                              const int* __restrict__ idx) {
    int blk = blockIdx.x;
    __half* buf = (blk < ROWS) ? q : k;
    int r = (blk < ROWS) ? blk : blk - ROWS;
    float pos = (float)idx[r];
    __half* base = buf + (size_t)r * DD;
    const float C = -0.415241011861f;   // -log2(10000)/32
    for (int c = threadIdx.x; c < 512; c += 256) {
        int h = c >> 5, i = c & 31;
        float inv = exp2f((float)i * C);
        float ang = pos * inv;
        float s, co; sincosf(ang, &s, &co);
        __half* p = base + h * 64;
        float x1 = __half2float(p[i]), x2 = __half2float(p[i + 32]);
        p[i]      = __float2half_rn(x1*co - x2*s);
        p[i + 32] = __float2half_rn(x2*co + x1*s);
    }
}

// ---------------- K8: fused flash attention fp16 ----------------
// grid (4, BB*HH); block 256; each block = 128 q-rows of one (b,h)
__global__ __launch_bounds__(256)
void flash_kernel(const __half* __restrict__ q, const __half* __restrict__ k,
                  const __half* __restrict__ v, __half* __restrict__ pv) {
    __shared__ __half Ks[64*72];
    __shared__ __half Vs[64*72];
    __shared__ __half Ps[128*72];

    int qp = 3 - blockIdx.x;               // heavy blocks first
    int bh = blockIdx.y, b = bh >> 4, h = bh & 15;
    int tid = threadIdx.x;
    int w = tid >> 5, lane = tid & 31, g = lane >> 2, c = lane & 3;

    // stage Q tile (128x64 halfs) through Ps, extract a-fragments
    #pragma unroll
    for (int p = 0; p < 4; p++) {
        int e = p*256 + tid;
        int row = e >> 3, col = (e & 7) * 8;
        *(float4*)&Ps[row*72 + col] =
            *(const float4*)&q[((size_t)(b*KS + qp*128 + row))*DD + h*64 + col];
    }
    __syncthreads();
    uint32_t qa[4][4];
    {
        const __half* pr0 = &Ps[(w*16 + g)*72];
        const __half* pr1 = &Ps[(w*16 + g + 8)*72];
        #pragma unroll
        for (int d = 0; d < 4; d++) {
            qa[d][0] = *(const uint32_t*)&pr0[d*16 + c*2];
            qa[d][1] = *(const uint32_t*)&pr1[d*16 + c*2];
            qa[d][2] = *(const uint32_t*)&pr0[d*16 + c*2 + 8];
            qa[d][3] = *(const uint32_t*)&pr1[d*16 + c*2 + 8];
        }
    }

    float o[8][4];
    #pragma unroll
    for (int j = 0; j < 8; j++)
        #pragma unroll
        for (int r = 0; r < 4; r++) o[j][r] = 0.f;
    float m0 = -1e38f, m1 = -1e38f, l0 = 0.f, l1 = 0.f;

    int q0 = qp*128 + w*16 + g;
    int q1 = q0 + 8;
    const float SC = 0.125f;
    int ktmax = 2*qp + 1;
    uint32_t vsBase = (uint32_t)__cvta_generic_to_shared(Vs);

    for (int kt = 0; kt <= ktmax; kt++) {
        __syncthreads();
        #pragma unroll
        for (int p = 0; p < 2; p++) {
            int e = p*256 + tid;
            int row = e >> 3, col = (e & 7) * 8;
            *(float4*)&Ks[row*72 + col] =
                *(const float4*)&k[((size_t)(b*KS + kt*64 + row))*DD + h*64 + col];
            *(float4*)&Vs[row*72 + col] =
                *(const float4*)&v[((size_t)(b*KS + kt*64 + row))*DD + h*64 + col];
        }
        __syncthreads();

        // S = Q K^T
        float s[8][4];
        #pragma unroll
        for (int j = 0; j < 8; j++)
            #pragma unroll
            for (int r = 0; r < 4; r++) s[j][r] = 0.f;
        #pragma unroll
        for (int d = 0; d < 4; d++) {
            #pragma unroll
            for (int j = 0; j < 8; j++) {
                uint32_t b0 = *(const uint32_t*)&Ks[(j*8+g)*72 + d*16 + c*2];
                uint32_t b1 = *(const uint32_t*)&Ks[(j*8+g)*72 + d*16 + c*2 + 8];
                mma_f16(s[j], qa[d][0], qa[d][1], qa[d][2], qa[d][3], b0, b1);
            }
        }

        // scale + causal mask + online softmax
        float mx0 = m0, mx1 = m1;
        #pragma unroll
        for (int j = 0; j < 8; j++) {
            int kc = kt*64 + j*8 + c*2;
            s[j][0] = (kc   <= q0) ? s[j][0]*SC : -1e30f;
            s[j][1] = (kc+1 <= q0) ? s[j][1]*SC : -1e30f;
            s[j][2] = (kc   <= q1) ? s[j][2]*SC : -1e30f;
            s[j][3] = (kc+1 <= q1) ? s[j][3]*SC : -1e30f;
            mx0 = fmaxf(mx0, fmaxf(s[j][0], s[j][1]));
            mx1 = fmaxf(mx1, fmaxf(s[j][2], s[j][3]));
        }
        mx0 = fmaxf(mx0, __shfl_xor_sync(0xffffffffu, mx0, 1));
        mx0 = fmaxf(mx0, __shfl_xor_sync(0xffffffffu, mx0, 2));
        mx1 = fmaxf(mx1, __shfl_xor_sync(0xffffffffu, mx1, 1));
        mx1 = fmaxf(mx1, __shfl_xor_sync(0xffffffffu, mx1, 2));

        float al0 = expf(m0 - mx0), al1 = expf(m1 - mx1);
        m0 = mx0; m1 = mx1;
        float sum0 = 0.f, sum1 = 0.f;
        #pragma unroll
        for (int j = 0; j < 8; j++) {
            s[j][0] = expf(s[j][0] - mx0);
            s[j][1] = expf(s[j][1] - mx0);
            s[j][2] = expf(s[j][2] - mx1);
            s[j][3] = expf(s[j][3] - mx1);
            sum0 += s[j][0] + s[j][1];
            sum1 += s[j][2] + s[j][3];
        }
        sum0 += __shfl_xor_sync(0xffffffffu, sum0, 1);
        sum0 += __shfl_xor_sync(0xffffffffu, sum0, 2);
        sum1 += __shfl_xor_sync(0xffffffffu, sum1, 1);
        sum1 += __shfl_xor_sync(0xffffffffu, sum1, 2);
        l0 = l0*al0 + sum0;
        l1 = l1*al1 + sum1;
        #pragma unroll
        for (int j = 0; j < 8; j++) {
            o[j][0] *= al0; o[j][1] *= al0;
            o[j][2] *= al1; o[j][3] *= al1;
        }

        // P (fp16) -> own rows of Ps
        {
            __half* pr0 = &Ps[(w*16 + g)*72];
            __half* pr1 = &Ps[(w*16 + g + 8)*72];
            #pragma unroll
            for (int j = 0; j < 8; j++) {
                *(__half2*)&pr0[j*8 + c*2] = __float22half2_rn(make_float2(s[j][0], s[j][1]));
                *(__half2*)&pr1[j*8 + c*2] = __float22half2_rn(make_float2(s[j][2], s[j][3]));
            }
        }
        __syncwarp();

        // O += P V   (V b-frags via ldmatrix.trans)
        {
            const __half* pr0 = &Ps[(w*16 + g)*72];
            const __half* pr1 = &Ps[(w*16 + g + 8)*72];
            #pragma unroll
            for (int ksl = 0; ksl < 4; ksl++) {
                uint32_t pa0 = *(const uint32_t*)&pr0[ksl*16 + c*2];
                uint32_t pa1 = *(const uint32_t*)&pr1[ksl*16 + c*2];
                uint32_t pa2 = *(const uint32_t*)&pr0[ksl*16 + c*2 + 8];
                uint32_t pa3 = *(const uint32_t*)&pr1[ksl*16 + c*2 + 8];
                #pragma unroll
                for (int jp = 0; jp < 4; jp++) {
                    int mrow = ksl*16 + (lane & 8) + (lane & 7);     // (m&1)*8 + r
                    int mcol = jp*16 + ((lane >> 4) << 3);           // (m>>1)*8
                    uint32_t addr = vsBase + (mrow*72 + mcol) * 2;
                    uint32_t b0e, b1e, b0o, b1o;
                    ldsm_x4_t(b0e, b1e, b0o, b1o, addr);
                    mma_f16(o[jp*2  ], pa0, pa1, pa2, pa3, b0e, b1e);
                    mma_f16(o[jp*2+1], pa0, pa1, pa2, pa3, b0o, b1o);
                }
            }
        }
    }

    float inv0 = 1.f / l0, inv1 = 1.f / l1;
    size_t r0 = (size_t)(b*KS + q0) * DD + h*64;
    size_t r1 = (size_t)(b*KS + q1) * DD + h*64;
    #pragma unroll
    for (int j = 0; j < 8; j++) {
        *(__half2*)&pv[r0 + j*8 + c*2] = __float22half2_rn(make_float2(o[j][0]*inv0, o[j][1]*inv0));
        *(__half2*)&pv[r1 + j*8 + c*2] = __float22half2_rn(make_float2(o[j][2]*inv1, o[j][3]*inv1));
    }
}

// ---------------- K12: scatter ----------------
__global__ void scatter_kernel(const float* __restrict__ sel, const float* __restrict__ bo,
                               const int* __restrict__ idx, const float* __restrict__ gate,
                               float* __restrict__ out) {
    int r = blockIdx.x;
    int b = r / KS;
    int pos = idx[r];
    float ga = gate[r];
    const float4* s4 = (const float4*)(sel + (size_t)r * DD);
    const float4* b4 = (const float4*)(bo  + (size_t)r * DD);
    float4* o4 = (float4*)(out + ((size_t)b*TT + pos) * DD);
    float4 s = s4[threadIdx.x], bb = b4[threadIdx.x];
    float4 u = make_float4(s.x + ga*(bb.x - s.x), s.y + ga*(bb.y - s.y),
                           s.z + ga*(bb.z - s.z), s.w + ga*(bb.w - s.w));
    o4[threadIdx.x] = u;
}

// ---------------- K13: predictor logits + per-row BCE ----------------
__global__ void predrow_kernel(const float* __restrict__ h1, const float* __restrict__ fc2w,
                               const float* __restrict__ fc2b, const float* __restrict__ tgt,
                               float* __restrict__ pred) {
    int warp = (blockIdx.x * blockDim.x + threadIdx.x) >> 5;
    int lane = threadIdx.x & 31;
    if (warp >= NTOK) return;
    const float* row = h1 + (size_t)warp * DQ;
    float s = 0.f;
    #pragma unroll
    for (int i = lane; i < DQ; i += 32) s += row[i] * fc2w[i];
    #pragma unroll
    for (int o = 16; o; o >>= 1) s += __shfl_xor_sync(0xffffffffu, s, o);
    if (lane == 0) {
        float x = s + fc2b[0];
        pred[warp] = bce_term(x, tgt[warp]);
    }
}

// ---------------- K14: loss reduce ----------------
__global__ void loss_reduce(const float* __restrict__ scores, const float* __restrict__ tgt,
                            const float* __restrict__ pred, float* __restrict__ out_aux) {
    __shared__ float sm_main[1024];
    __shared__ float sm_pred[1024];
    int tid = threadIdx.x;
    float sm = 0.f, sp = 0.f;
    for (int i = tid; i < NTOK; i += 1024) {
        sm += bce_term(scores[i], tgt[i]);
        sp += pred[i];
    }
    sm_main[tid] = sm; sm_pred[tid] = sp;
    __syncthreads();
    for (int s = 512; s > 0; s >>= 1) {
        if (tid < s) { sm_main[tid] += sm_main[tid+s]; sm_pred[tid] += sm_pred[tid+s]; }
        __syncthreads();
    }
    if (tid == 0)
        out_aux[0] = 0.01f * (sm_main[0] + sm_pred[0]) / (float)NTOK;
}

// ---------------- host launch ----------------
extern "C" void kernel_launch(void* const* d_in, const int* in_sizes, int n_in,
                              void* d_out, int out_size) {
    const float* hs   = (const float*)d_in[0];
    const float* rw   = (const float*)d_in[1];
    const float* fc1w = (const float*)d_in[2];
    const float* fc1b = (const float*)d_in[3];
    const float* fc2w = (const float*)d_in[4];
    const float* fc2b = (const float*)d_in[5];
    const float* ln1  = (const float*)d_in[6];
    const float* ln2  = (const float*)d_in[7];
    const float* wq   = (const float*)d_in[8];
    const float* wk   = (const float*)d_in[9];
    const float* wv   = (const float*)d_in[10];
    const float* wo   = (const float*)d_in[11];
    const float* wg   = (const float*)d_in[12];
    const float* wu   = (const float*)d_in[13];
    const float* wd   = (const float*)d_in[14];
    float* out = (float*)d_out;

    float *scores, *tgt, *gate, *sel, *h, *ub, *bo, *h1, *pred;
    __half *a16, *q16, *k16, *v16, *pv16, *m16, *gb16, *hs16;
    __half *wqT, *wkT, *wvT, *woT, *wuT, *wgT, *wdT, *fc1T;
    int* idx;
    cudaGetSymbolAddress((void**)&scores, g_scores);
    cudaGetSymbolAddress((void**)&tgt,    g_tgt);
    cudaGetSymbolAddress((void**)&idx,    g_idx);
    cudaGetSymbolAddress((void**)&gate,   g_gate);
    cudaGetSymbolAddress((void**)&sel,    g_sel);
    cudaGetSymbolAddress((void**)&a16,    g_a16);
    cudaGetSymbolAddress((void**)&q16,    g_q16);
    cudaGetSymbolAddress((void**)&k16,    g_k16);
    cudaGetSymbolAddress((void**)&v16,    g_v16);
    cudaGetSymbolAddress((void**)&pv16,   g_pv16);
    cudaGetSymbolAddress((void**)&h,      g_h);
    cudaGetSymbolAddress((void**)&m16,    g_m16);
    cudaGetSymbolAddress((void**)&ub,     g_ub);
    cudaGetSymbolAddress((void**)&gb16,   g_gb16);
    cudaGetSymbolAddress((void**)&bo,     g_bo);
    cudaGetSymbolAddress((void**)&hs16,   g_hs16);
    cudaGetSymbolAddress((void**)&h1,     g_h1);
    cudaGetSymbolAddress((void**)&pred,   g_pred);
    cudaGetSymbolAddress((void**)&wqT,    g_wqT);
    cudaGetSymbolAddress((void**)&wkT,    g_wkT);
    cudaGetSymbolAddress((void**)&wvT,    g_wvT);
    cudaGetSymbolAddress((void**)&woT,    g_woT);
    cudaGetSymbolAddress((void**)&wuT,    g_wuT);
    cudaGetSymbolAddress((void**)&wgT,    g_wgT);
    cudaGetSymbolAddress((void**)&wdT,    g_wdT);
    cudaGetSymbolAddress((void**)&fc1T,   g_fc1T);

    cudaFuncSetAttribute(mma_gemm, cudaFuncAttributeMaxDynamicSharedMemorySize, GEMM_SMEM);

    // ---- weight transpose+convert on s3 ----
    cudaEventRecord(eStart, 0);
    cudaStreamWaitEvent(s3, eStart, 0);
    cudaStreamWaitEvent(s2, eStart, 0);
    cudaStreamWaitEvent(s1, eStart, 0);
    wconv_kernel<<<dim3(32, 32), 256, 0, s3>>>(wq, wqT, DD, DD);
    wconv_kernel<<<dim3(32, 32), 256, 0, s3>>>(wk, wkT, DD, DD);
    wconv_kernel<<<dim3(32, 32), 256, 0, s3>>>(wv, wvT, DD, DD);
    wconv_kernel<<<dim3(32, 32), 256, 0, s3>>>(wo, woT, DD, DD);
    wconv_kernel<<<dim3(128, 32), 256, 0, s3>>>(wu, wuT, DD, FF);
    wconv_kernel<<<dim3(128, 32), 256, 0, s3>>>(wg, wgT, DD, FF);
    wconv_kernel<<<dim3(32, 128), 256, 0, s3>>>(wd, wdT, FF, DD);
    wconv_kernel<<<dim3(8, 32), 256, 0, s3>>>(fc1w, fc1T, DD, DQ);
    cudaEventRecord(eW, s3);

    // ---- copy hidden -> out on s2 ----
    copy_kernel<<<4096, 256, 0, s2>>>((const float4*)hs, (float4*)out, NTOK*DD/4);
    cudaEventRecord(eC, s2);

    // ---- hs -> f16 on s1, then fc1 GEMM + predrow ----
    f2h_kernel<<<4096, 256, 0, s1>>>((const float4*)hs, (uint2*)hs16, NTOK*DD/4);
    cudaStreamWaitEvent(s1, eW, 0);
    mma_gemm<<<dim3(DQ/128, NTOK/128), 256, GEMM_SMEM, s1>>>(hs16, fc1T, h1, NTOK, DQ, DD, fc1b, 1, 0);

    // ---- router + top-k on main ----
    scores_kernel<<<NTOK/8, 256>>>(hs, rw, scores);
    topk_radix<<<BB, 1024>>>(scores, tgt, idx, gate);
    cudaEventRecord(eTopk, 0);

    cudaStreamWaitEvent(s1, eTopk, 0);
    predrow_kernel<<<NTOK/8, 256, 0, s1>>>(h1, fc2w, fc2b, tgt, pred);
    cudaEventRecord(eP, s1);

    // ---- decoder block ----
    gather_rms_kernel<<<ROWS, 256>>>(hs, idx, ln1, sel, a16);
    cudaEventRecord(eA, 0);
    cudaStreamWaitEvent(s2, eA, 0);
    cudaStreamWaitEvent(s2, eW, 0);
    cudaStreamWaitEvent(s3, eA, 0);
    mma_gemm<<<dim3(DD/128, ROWS/128), 256, GEMM_SMEM, s2>>>(a16, wkT, k16, ROWS, DD, DD, nullptr, 0, 1);
    cudaEventRecord(eK, s2);
    mma_gemm<<<dim3(DD/128, ROWS/128), 256, GEMM_SMEM, s3>>>(a16, wvT, v16, ROWS, DD, DD, nullptr, 0, 1);
    cudaEventRecord(eV, s3);
    cudaStreamWaitEvent(0, eW, 0);
    mma_gemm<<<dim3(DD/128, ROWS/128), 256, GEMM_SMEM>>>(a16, wqT, q16, ROWS, DD, DD, nullptr, 0, 1);
    cudaStreamWaitEvent(0, eK, 0);
    rope2h_kernel<<<2*ROWS, 256>>>(q16, k16, idx);
    cudaStreamWaitEvent(0, eV, 0);
    flash_kernel<<<dim3(4, BB*HH), 256>>>(q16, k16, v16, pv16);
    mma_gemm<<<dim3(DD/128, ROWS/128), 256, GEMM_SMEM>>>(pv16, woT, h, ROWS, DD, DD, sel, 2, 0);

    rmsnorm_h_kernel<<<ROWS, 256>>>(h, ln2, m16);
    mma_gemm<<<dim3(FF/128, ROWS/128), 256, GEMM_SMEM>>>(m16, wuT, ub, ROWS, FF, DD, nullptr, 0, 0);
    mma_gemm<<<dim3(FF/128, ROWS/128), 256, GEMM_SMEM>>>(m16, wgT, gb16, ROWS, FF, DD, ub, 3, 1);
    mma_gemm<<<dim3(DD/128, ROWS/128), 256, GEMM_SMEM>>>(gb16, wdT, bo, ROWS, DD, FF, h, 2, 0);

    cudaStreamWaitEvent(0, eC, 0);
    scatter_kernel<<<ROWS, 256>>>(sel, bo, idx, gate, out);

    cudaStreamWaitEvent(0, eP, 0);
    loss_reduce<<<1, 1024>>>(scores, tgt, pred, out + (size_t)NTOK*DD);
}

// round 7
// speedup vs baseline: 5.4875x; 1.0189x over previous
#include <cuda_runtime.h>
#include <cuda_fp16.h>
#include <math.h>
#include <stdint.h>

// ---------------- problem constants ----------------
#define BB 4
#define TT 4096
#define DD 1024
#define FF 4096
#define HH 16
#define HD 64
#define KS 512
#define DQ 256
#define ROWS (BB*KS)           // 2048
#define NTOK (BB*TT)           // 16384

// ---------------- device scratch ----------------
__device__ float  g_scores[NTOK];
__device__ float  g_tgt[NTOK];
__device__ int    g_idx[ROWS];
__device__ float  g_gate[ROWS];
__device__ float  g_sel[ROWS*DD];
__device__ __half g_a16[ROWS*DD];
__device__ __half g_q16[ROWS*DD];
__device__ __half g_k16[ROWS*DD];
__device__ __half g_v16[ROWS*DD];
__device__ __half g_pv16[ROWS*DD];
__device__ float  g_h[ROWS*DD];
__device__ __half g_m16[ROWS*DD];
__device__ float  g_ub[ROWS*FF];
__device__ __half g_gb16[ROWS*FF];
__device__ float  g_bo[ROWS*DD];
__device__ __half g_hs16[(size_t)NTOK*DD];
__device__ float  g_h1[(size_t)NTOK*DQ];
__device__ float  g_pred[NTOK];
// transposed fp16 weights [N][K]
__device__ __half g_wqT[DD*DD];
__device__ __half g_wkT[DD*DD];
__device__ __half g_wvT[DD*DD];
__device__ __half g_woT[DD*DD];
__device__ __half g_wuT[(size_t)FF*DD];
__device__ __half g_wgT[(size_t)FF*DD];
__device__ __half g_wdT[(size_t)DD*FF];
__device__ __half g_fc1T[DQ*DD];

// ---------------- static streams/events ----------------
static cudaStream_t s1, s2, s3;
static cudaEvent_t eStart, eTopk, eA, eK, eV, eP, eC, eW;
static struct StreamInit {
    StreamInit() {
        cudaStreamCreateWithFlags(&s1, cudaStreamNonBlocking);
        cudaStreamCreateWithFlags(&s2, cudaStreamNonBlocking);
        cudaStreamCreateWithFlags(&s3, cudaStreamNonBlocking);
        cudaEventCreateWithFlags(&eStart, cudaEventDisableTiming);
        cudaEventCreateWithFlags(&eTopk,  cudaEventDisableTiming);
        cudaEventCreateWithFlags(&eA,     cudaEventDisableTiming);
        cudaEventCreateWithFlags(&eK,     cudaEventDisableTiming);
        cudaEventCreateWithFlags(&eV,     cudaEventDisableTiming);
        cudaEventCreateWithFlags(&eP,     cudaEventDisableTiming);
        cudaEventCreateWithFlags(&eC,     cudaEventDisableTiming);
        cudaEventCreateWithFlags(&eW,     cudaEventDisableTiming);
    }
} s_init;

// ---------------- helpers ----------------
__device__ __forceinline__ float gelu_tanh(float x) {
    float x3 = x*x*x;
    return 0.5f * x * (1.f + tanhf(0.7978845608028654f * (x + 0.044715f * x3)));
}
__device__ __forceinline__ float bce_term(float x, float t) {
    return fmaxf(x, 0.f) - x*t + log1pf(expf(-fabsf(x)));
}
__device__ __forceinline__ void cpa16(uint32_t s, const void* g) {
    asm volatile("cp.async.cg.shared.global [%0], [%1], 16;" :: "r"(s), "l"(g));
}
__device__ __forceinline__ void mma_f16(float* d, uint32_t a0, uint32_t a1, uint32_t a2, uint32_t a3,
                                        uint32_t b0, uint32_t b1) {
    asm volatile(
        "mma.sync.aligned.m16n8k16.row.col.f32.f16.f16.f32 "
        "{%0,%1,%2,%3}, {%4,%5,%6,%7}, {%8,%9}, {%0,%1,%2,%3};"
        : "+f"(d[0]), "+f"(d[1]), "+f"(d[2]), "+f"(d[3])
        : "r"(a0), "r"(a1), "r"(a2), "r"(a3), "r"(b0), "r"(b1));
}
__device__ __forceinline__ void ldsm_x4(uint32_t& r0, uint32_t& r1, uint32_t& r2, uint32_t& r3,
                                        uint32_t addr) {
    asm volatile("ldmatrix.sync.aligned.m8n8.x4.shared.b16 {%0,%1,%2,%3}, [%4];"
        : "=r"(r0), "=r"(r1), "=r"(r2), "=r"(r3) : "r"(addr));
}
__device__ __forceinline__ void ldsm_x4_t(uint32_t& r0, uint32_t& r1, uint32_t& r2, uint32_t& r3,
                                          uint32_t addr) {
    asm volatile("ldmatrix.sync.aligned.m8n8.x4.trans.shared.b16 {%0,%1,%2,%3}, [%4];"
        : "=r"(r0), "=r"(r1), "=r"(r2), "=r"(r3) : "r"(addr));
}

// ---------------- W0: weight transpose + f32->f16: w[K][N] -> wt[N][K] ----------------
__global__ void wconv_kernel(const float* __restrict__ w, __half* __restrict__ wt, int K, int N) {
    __shared__ float t[32][33];
    int k0 = blockIdx.y * 32, n0 = blockIdx.x * 32;
    int tx = threadIdx.x & 31, ty = threadIdx.x >> 5;   // 32 x 8
    #pragma unroll
    for (int i = 0; i < 32; i += 8)
        t[ty + i][tx] = w[(size_t)(k0 + ty + i) * N + n0 + tx];
    __syncthreads();
    #pragma unroll
    for (int i = 0; i < 32; i += 8)
        wt[(size_t)(n0 + ty + i) * K + k0 + tx] = __float2half_rn(t[tx][ty + i]);
}

// ---------------- W1: elementwise f32->f16 ----------------
__global__ void f2h_kernel(const float4* __restrict__ src, uint2* __restrict__ dst, int n4) {
    int stride = gridDim.x * blockDim.x;
    for (int i = blockIdx.x * blockDim.x + threadIdx.x; i < n4; i += stride) {
        float4 v = src[i];
        __half2 a = __float22half2_rn(make_float2(v.x, v.y));
        __half2 b = __float22half2_rn(make_float2(v.z, v.w));
        dst[i] = make_uint2(*(uint32_t*)&a, *(uint32_t*)&b);
    }
}

// ---------------- K1: router scores ----------------
__global__ void scores_kernel(const float* __restrict__ hs, const float* __restrict__ rw,
                              float* __restrict__ scores) {
    int warp = (blockIdx.x * blockDim.x + threadIdx.x) >> 5;
    int lane = threadIdx.x & 31;
    if (warp >= NTOK) return;
    const float4* row = (const float4*)(hs + (size_t)warp * DD);
    const float4* w4  = (const float4*)rw;
    float s = 0.f;
    #pragma unroll 4
    for (int i = lane; i < DD/4; i += 32) {
        float4 a = row[i], b = w4[i];
        s += a.x*b.x + a.y*b.y + a.z*b.z + a.w*b.w;
    }
    #pragma unroll
    for (int o = 16; o; o >>= 1) s += __shfl_xor_sync(0xffffffffu, s, o);
    if (lane == 0) scores[warp] = s;
}

// ---------------- K2: radix-select top-k + ascending compaction ----------------
__global__ void topk_radix(const float* __restrict__ scores, float* __restrict__ tgt,
                           int* __restrict__ idxo, float* __restrict__ gateo) {
    __shared__ unsigned su[TT];
    __shared__ int hist[256];
    __shared__ int wsum[32];
    __shared__ unsigned s_prefix;
    __shared__ int s_remain;
    int b = blockIdx.x, tid = threadIdx.x;
    const float* sc = scores + (size_t)b * TT;

    for (int i = tid; i < TT; i += 1024) {
        unsigned bits = __float_as_uint(sc[i]);
        unsigned mask = (unsigned)((int)bits >> 31) | 0x80000000u;
        su[i] = bits ^ mask;
    }
    if (tid == 0) { s_prefix = 0u; s_remain = KS; }
    __syncthreads();

    #pragma unroll
    for (int p = 24; p >= 0; p -= 8) {
        if (tid < 256) hist[tid] = 0;
        __syncthreads();
        unsigned pref = s_prefix;
        for (int i = tid; i < TT; i += 1024) {
            unsigned u = su[i];
            if (p == 24 || (u >> (p + 8)) == (pref >> (p + 8)))
                atomicAdd(&hist[(u >> p) & 255], 1);
        }
        __syncthreads();
        if (tid == 0) {
            int rem = s_remain;
            int bin = 255;
            for (;;) {
                int c = hist[bin];
                if (rem <= c) break;
                rem -= c; bin--;
            }
            s_prefix = pref | ((unsigned)bin << p);
            s_remain = rem;
        }
        __syncthreads();
    }
    unsigned thr = s_prefix;

    int base = tid * 4;
    int flg[4]; int cnt = 0;
    #pragma unroll
    for (int j = 0; j < 4; j++) { flg[j] = (su[base + j] >= thr) ? 1 : 0; cnt += flg[j]; }
    int lane = tid & 31, warp = tid >> 5;
    int inc = cnt;
    #pragma unroll
    for (int o = 1; o < 32; o <<= 1) {
        int n2 = __shfl_up_sync(0xffffffffu, inc, o);
        if (lane >= o) inc += n2;
    }
    if (lane == 31) wsum[warp] = inc;
    __syncthreads();
    if (tid < 32) {
        int v = wsum[tid];
        #pragma unroll
        for (int o = 1; o < 32; o <<= 1) {
            int n2 = __shfl_up_sync(0xffffffffu, v, o);
            if (tid >= o) v += n2;
        }
        wsum[tid] = v;
    }
    __syncthreads();
    int off = inc - cnt + (warp ? wsum[warp - 1] : 0);
    #pragma unroll
    for (int j = 0; j < 4; j++) {
        tgt[(size_t)b*TT + base + j] = flg[j] ? 1.f : 0.f;
        if (flg[j]) {
            idxo[b*KS + off] = base + j;
            float s = sc[base + j];
            gateo[b*KS + off] = 1.f / (1.f + expf(-s));
            off++;
        }
    }
}

// ---------------- K3: copy hidden -> out ----------------
__global__ void copy_kernel(const float4* __restrict__ src, float4* __restrict__ dst, int n4) {
    int stride = gridDim.x * blockDim.x;
    for (int i = blockIdx.x * blockDim.x + threadIdx.x; i < n4; i += stride)
        dst[i] = src[i];
}

// ---------------- K4: fused gather + rmsnorm(ln1) -> sel f32, a f16 ----------------
__global__ void gather_rms_kernel(const float* __restrict__ hs, const int* __restrict__ idx,
                                  const float* __restrict__ g,
                                  float* __restrict__ sel, __half* __restrict__ a16) {
    __shared__ float red[8];
    int r = blockIdx.x, tid = threadIdx.x;
    int b = r / KS;
    int pos = idx[r];
    const float4* src = (const float4*)(hs + ((size_t)b*TT + pos) * DD);
    float4 x = src[tid];
    ((float4*)(sel + (size_t)r * DD))[tid] = x;
    float ss = x.x*x.x + x.y*x.y + x.z*x.z + x.w*x.w;
    #pragma unroll
    for (int o = 16; o; o >>= 1) ss += __shfl_xor_sync(0xffffffffu, ss, o);
    if ((tid & 31) == 0) red[tid >> 5] = ss;
    __syncthreads();
    if (tid < 8) {
        float v = red[tid];
        #pragma unroll
        for (int o = 4; o; o >>= 1) v += __shfl_xor_sync(0xffu, v, o);
        if (tid == 0) red[0] = v;
    }
    __syncthreads();
    float rs = rsqrtf(red[0] / (float)DD + 1e-6f);
    const float4* g4 = (const float4*)g;
    float4 gg = g4[tid];
    __half2 h0 = __float22half2_rn(make_float2(x.x*rs*gg.x, x.y*rs*gg.y));
    __half2 h1 = __float22half2_rn(make_float2(x.z*rs*gg.z, x.w*rs*gg.w));
    uint2* dst = (uint2*)(a16 + (size_t)r * DD);
    dst[tid] = make_uint2(*(uint32_t*)&h0, *(uint32_t*)&h1);
}

// ---------------- K5: rmsnorm f32 -> f16 ----------------
__global__ void rmsnorm_h_kernel(const float* __restrict__ in, const float* __restrict__ g,
                                 __half* __restrict__ out) {
    __shared__ float red[8];
    int r = blockIdx.x, tid = threadIdx.x;
    const float4* x4 = (const float4*)(in + (size_t)r * DD);
    float4 x = x4[tid];
    float ss = x.x*x.x + x.y*x.y + x.z*x.z + x.w*x.w;
    #pragma unroll
    for (int o = 16; o; o >>= 1) ss += __shfl_xor_sync(0xffffffffu, ss, o);
    if ((tid & 31) == 0) red[tid >> 5] = ss;
    __syncthreads();
    if (tid < 8) {
        float v = red[tid];
        #pragma unroll
        for (int o = 4; o; o >>= 1) v += __shfl_xor_sync(0xffu, v, o);
        if (tid == 0) red[0] = v;
    }
    __syncthreads();
    float rs = rsqrtf(red[0] / (float)DD + 1e-6f);
    const float4* g4 = (const float4*)g;
    float4 gg = g4[tid];
    __half2 h0 = __float22half2_rn(make_float2(x.x*rs*gg.x, x.y*rs*gg.y));
    __half2 h1 = __float22half2_rn(make_float2(x.z*rs*gg.z, x.w*rs*gg.w));
    uint2* dst = (uint2*)(out + (size_t)r * DD);
    dst[tid] = make_uint2(*(uint32_t*)&h0, *(uint32_t*)&h1);
}

// ---------------- K6: FP16 GEMM 128x128x32, 3-stage cp.async + ldmatrix ----------------
// A[M,K] f16 row-major, Bt[N,K] f16 row-major. epi: 0 none, 1 gelu(+bias), 2 +resid, 3 silu*aux
#define LDH 40                       // halfs per smem row (32 + 8 pad)
#define T_ST (128*LDH)               // halfs per tile stage
#define GEMM_SMEM (3*2*T_ST*2)       // 61440 bytes

__global__ __launch_bounds__(256)
void mma_gemm(const __half* __restrict__ A, const __half* __restrict__ Bt, void* __restrict__ Cv,
              int M, int N, int K, const float* __restrict__ aux, int epi, int ohalf) {
    extern __shared__ __half dynh[];
    __half* As = dynh;                // [3][128][40]
    __half* Bs = dynh + 3*T_ST;       // [3][128][40]

    int tid = threadIdx.x;
    int m0 = blockIdx.y * 128, n0 = blockIdx.x * 128;
    int warp = tid >> 5, lane = tid & 31;
    int wm = (warp >> 2) * 64;
    int wn = (warp & 3) * 32;
    int g = lane >> 2, c = lane & 3;

    float acc[4][4][4];
    #pragma unroll
    for (int i = 0; i < 4; i++)
        #pragma unroll
        for (int j = 0; j < 4; j++)
            #pragma unroll
            for (int r = 0; r < 4; r++) acc[i][j][r] = 0.f;

    int ch0 = tid * 2;
    int ldRow = ch0 >> 2;
    int ldOff = (ch0 & 3) * 8;

    uint32_t asBase = (uint32_t)__cvta_generic_to_shared(As);
    uint32_t bsBase = (uint32_t)__cvta_generic_to_shared(Bs);

    // ldmatrix lane addressing
    int aRowL = lane & 15;
    int aColL = (lane >> 4) << 3;
    int bRowL = (lane & 7) + ((lane & 16) ? 8 : 0);
    int bColL = (lane & 8) ? 8 : 0;

    int nk = K / 32;

    auto prefetch = [&](int kt) {
        int st = kt % 3;
        const __half* Ag = A + (size_t)(m0 + ldRow) * K + kt*32 + ldOff;
        uint32_t ad = asBase + (st*T_ST + ldRow*LDH + ldOff) * 2;
        cpa16(ad,      Ag);
        cpa16(ad + 16, Ag + 8);
        const __half* Bg = Bt + (size_t)(n0 + ldRow) * K + kt*32 + ldOff;
        uint32_t bd = bsBase + (st*T_ST + ldRow*LDH + ldOff) * 2;
        cpa16(bd,      Bg);
        cpa16(bd + 16, Bg + 8);
        asm volatile("cp.async.commit_group;" ::: "memory");
    };

    prefetch(0);
    if (nk > 1) prefetch(1);

    for (int kt = 0; kt < nk; kt++) {
        if (kt + 1 < nk) {
            asm volatile("cp.async.wait_group 1;" ::: "memory");
        } else {
            asm volatile("cp.async.wait_group 0;" ::: "memory");
        }
        __syncthreads();
        if (kt + 2 < nk) prefetch(kt + 2);

        int st = kt % 3;
        uint32_t aStage = asBase + st*T_ST*2;
        uint32_t bStage = bsBase + st*T_ST*2;
        #pragma unroll
        for (int ks = 0; ks < 2; ks++) {
            int ko = ks * 16;
            uint32_t af[4][4], bf[4][2];
            #pragma unroll
            for (int i = 0; i < 4; i++) {
                uint32_t addr = aStage + ((wm + i*16 + aRowL)*LDH + ko + aColL) * 2;
                ldsm_x4(af[i][0], af[i][1], af[i][2], af[i][3], addr);
            }
            #pragma unroll
            for (int jp = 0; jp < 2; jp++) {
                uint32_t addr = bStage + ((wn + jp*16 + bRowL)*LDH + ko + bColL) * 2;
                ldsm_x4(bf[jp*2][0], bf[jp*2][1], bf[jp*2+1][0], bf[jp*2+1][1], addr);
            }
            #pragma unroll
            for (int i = 0; i < 4; i++)
                #pragma unroll
                for (int j = 0; j < 4; j++)
                    mma_f16(acc[i][j], af[i][0], af[i][1], af[i][2], af[i][3],
                            bf[j][0], bf[j][1]);
        }
    }

    float* C = (float*)Cv;
    __half* C16 = (__half*)Cv;
    #pragma unroll
    for (int i = 0; i < 4; i++) {
        int r0 = m0 + wm + i*16 + g;
        #pragma unroll
        for (int j = 0; j < 4; j++) {
            int col = n0 + wn + j*8 + c*2;
            float2 lo = make_float2(acc[i][j][0], acc[i][j][1]);
            float2 hi = make_float2(acc[i][j][2], acc[i][j][3]);
            if (epi == 1) {
                float b0 = aux[col], b1 = aux[col+1];
                lo.x = gelu_tanh(lo.x + b0); lo.y = gelu_tanh(lo.y + b1);
                hi.x = gelu_tanh(hi.x + b0); hi.y = gelu_tanh(hi.y + b1);
            } else if (epi == 2) {
                const float2 s0 = *(const float2*)&aux[(size_t)r0*N + col];
                const float2 s1 = *(const float2*)&aux[(size_t)(r0+8)*N + col];
                lo.x += s0.x; lo.y += s0.y; hi.x += s1.x; hi.y += s1.y;
            } else if (epi == 3) {
                const float2 u0 = *(const float2*)&aux[(size_t)r0*N + col];
                const float2 u1 = *(const float2*)&aux[(size_t)(r0+8)*N + col];
                lo.x = lo.x / (1.f + expf(-lo.x)) * u0.x;
                lo.y = lo.y / (1.f + expf(-lo.y)) * u0.y;
                hi.x = hi.x / (1.f + expf(-hi.x)) * u1.x;
                hi.y = hi.y / (1.f + expf(-hi.y)) * u1.y;
            }
            if (ohalf) {
                __half2 l2 = __float22half2_rn(lo);
                __half2 h2 = __float22half2_rn(hi);
                *(__half2*)&C16[(size_t)r0*N + col] = l2;
                *(__half2*)&C16[(size_t)(r0+8)*N + col] = h2;
            } else {
                *(float2*)&C[(size_t)r0*N + col] = lo;
                *(float2*)&C[(size_t)(r0+8)*N + col] = hi;
            }
        }
    }
}

// ---------------- K7: RoPE fp16 (q and k in one launch) ----------------
__global__ void rope2h_kernel(__half* __restrict__ q, __half* __restrict__ k,
                              const int* __restrict__ idx) {
    int blk = blockIdx.x;
    __half* buf = (blk < ROWS) ? q : k;
    int r = (blk < ROWS) ? blk : blk - ROWS;
    float pos = (float)idx[r];
    __half* base = buf + (size_t)r * DD;
    const float C = -0.415241011861f;   // -log2(10000)/32
    for (int c = threadIdx.x; c < 512; c += 256) {
        int h = c >> 5, i = c & 31;
        float inv = exp2f((float)i * C);
        float ang = pos * inv;
        float s, co; sincosf(ang, &s, &co);
        __half* p = base + h * 64;
        float x1 = __half2float(p[i]), x2 = __half2float(p[i + 32]);
        p[i]      = __float2half_rn(x1*co - x2*s);
        p[i + 32] = __float2half_rn(x2*co + x1*s);
    }
}

// ---------------- K8: fused flash attention fp16 ----------------
__global__ __launch_bounds__(256)
void flash_kernel(const __half* __restrict__ q, const __half* __restrict__ k,
                  const __half* __restrict__ v, __half* __restrict__ pv) {
    __shared__ __half Ks[64*72];
    __shared__ __half Vs[64*72];
    __shared__ __half Ps[128*72];

    int qp = 3 - blockIdx.x;
    int bh = blockIdx.y, b = bh >> 4, h = bh & 15;
    int tid = threadIdx.x;
    int w = tid >> 5, lane = tid & 31, g = lane >> 2, c = lane & 3;

    #pragma unroll
    for (int p = 0; p < 4; p++) {
        int e = p*256 + tid;
        int row = e >> 3, col = (e & 7) * 8;
        *(float4*)&Ps[row*72 + col] =
            *(const float4*)&q[((size_t)(b*KS + qp*128 + row))*DD + h*64 + col];
    }
    __syncthreads();
    uint32_t qa[4][4];
    {
        const __half* pr0 = &Ps[(w*16 + g)*72];
        const __half* pr1 = &Ps[(w*16 + g + 8)*72];
        #pragma unroll
        for (int d = 0; d < 4; d++) {
            qa[d][0] = *(const uint32_t*)&pr0[d*16 + c*2];
            qa[d][1] = *(const uint32_t*)&pr1[d*16 + c*2];
            qa[d][2] = *(const uint32_t*)&pr0[d*16 + c*2 + 8];
            qa[d][3] = *(const uint32_t*)&pr1[d*16 + c*2 + 8];
        }
    }

    float o[8][4];
    #pragma unroll
    for (int j = 0; j < 8; j++)
        #pragma unroll
        for (int r = 0; r < 4; r++) o[j][r] = 0.f;
    float m0 = -1e38f, m1 = -1e38f, l0 = 0.f, l1 = 0.f;

    int q0 = qp*128 + w*16 + g;
    int q1 = q0 + 8;
    const float SC = 0.125f;
    int ktmax = 2*qp + 1;
    uint32_t vsBase = (uint32_t)__cvta_generic_to_shared(Vs);
    uint32_t ksBase = (uint32_t)__cvta_generic_to_shared(Ks);
    int bRowL = (lane & 7) + ((lane & 16) ? 8 : 0);
    int bColL = (lane & 8) ? 8 : 0;

    for (int kt = 0; kt <= ktmax; kt++) {
        __syncthreads();
        #pragma unroll
        for (int p = 0; p < 2; p++) {
            int e = p*256 + tid;
            int row = e >> 3, col = (e & 7) * 8;
            *(float4*)&Ks[row*72 + col] =
                *(const float4*)&k[((size_t)(b*KS + kt*64 + row))*DD + h*64 + col];
            *(float4*)&Vs[row*72 + col] =
                *(const float4*)&v[((size_t)(b*KS + kt*64 + row))*DD + h*64 + col];
        }
        __syncthreads();

        // S = Q K^T (K b-frags via ldmatrix)
        float s[8][4];
        #pragma unroll
        for (int j = 0; j < 8; j++)
            #pragma unroll
            for (int r = 0; r < 4; r++) s[j][r] = 0.f;
        #pragma unroll
        for (int d = 0; d < 4; d++) {
            #pragma unroll
            for (int jp = 0; jp < 4; jp++) {
                uint32_t addr = ksBase + ((jp*16 + bRowL)*72 + d*16 + bColL) * 2;
                uint32_t b0a, b1a, b0b, b1b;
                ldsm_x4(b0a, b1a, b0b, b1b, addr);
                mma_f16(s[jp*2  ], qa[d][0], qa[d][1], qa[d][2], qa[d][3], b0a, b1a);
                mma_f16(s[jp*2+1], qa[d][0], qa[d][1], qa[d][2], qa[d][3], b0b, b1b);
            }
        }

        // scale + causal mask + online softmax
        float mx0 = m0, mx1 = m1;
        #pragma unroll
        for (int j = 0; j < 8; j++) {
            int kc = kt*64 + j*8 + c*2;
            s[j][0] = (kc   <= q0) ? s[j][0]*SC : -1e30f;
            s[j][1] = (kc+1 <= q0) ? s[j][1]*SC : -1e30f;
            s[j][2] = (kc   <= q1) ? s[j][2]*SC : -1e30f;
            s[j][3] = (kc+1 <= q1) ? s[j][3]*SC : -1e30f;
            mx0 = fmaxf(mx0, fmaxf(s[j][0], s[j][1]));
            mx1 = fmaxf(mx1, fmaxf(s[j][2], s[j][3]));
        }
        mx0 = fmaxf(mx0, __shfl_xor_sync(0xffffffffu, mx0, 1));
        mx0 = fmaxf(mx0, __shfl_xor_sync(0xffffffffu, mx0, 2));
        mx1 = fmaxf(mx1, __shfl_xor_sync(0xffffffffu, mx1, 1));
        mx1 = fmaxf(mx1, __shfl_xor_sync(0xffffffffu, mx1, 2));

        float al0 = expf(m0 - mx0), al1 = expf(m1 - mx1);
        m0 = mx0; m1 = mx1;
        float sum0 = 0.f, sum1 = 0.f;
        #pragma unroll
        for (int j = 0; j < 8; j++) {
            s[j][0] = expf(s[j][0] - mx0);
            s[j][1] = expf(s[j][1] - mx0);
            s[j][2] = expf(s[j][2] - mx1);
            s[j][3] = expf(s[j][3] - mx1);
            sum0 += s[j][0] + s[j][1];
            sum1 += s[j][2] + s[j][3];
        }
        sum0 += __shfl_xor_sync(0xffffffffu, sum0, 1);
        sum0 += __shfl_xor_sync(0xffffffffu, sum0, 2);
        sum1 += __shfl_xor_sync(0xffffffffu, sum1, 1);
        sum1 += __shfl_xor_sync(0xffffffffu, sum1, 2);
        l0 = l0*al0 + sum0;
        l1 = l1*al1 + sum1;
        #pragma unroll
        for (int j = 0; j < 8; j++) {
            o[j][0] *= al0; o[j][1] *= al0;
            o[j][2] *= al1; o[j][3] *= al1;
        }

        // P (fp16) -> own rows of Ps
        {
            __half* pr0 = &Ps[(w*16 + g)*72];
            __half* pr1 = &Ps[(w*16 + g + 8)*72];
            #pragma unroll
            for (int j = 0; j < 8; j++) {
                *(__half2*)&pr0[j*8 + c*2] = __float22half2_rn(make_float2(s[j][0], s[j][1]));
                *(__half2*)&pr1[j*8 + c*2] = __float22half2_rn(make_float2(s[j][2], s[j][3]));
            }
        }
        __syncwarp();

        // O += P V   (V b-frags via ldmatrix.trans)
        {
            const __half* pr0 = &Ps[(w*16 + g)*72];
            const __half* pr1 = &Ps[(w*16 + g + 8)*72];
            #pragma unroll
            for (int ksl = 0; ksl < 4; ksl++) {
                uint32_t pa0 = *(const uint32_t*)&pr0[ksl*16 + c*2];
                uint32_t pa1 = *(const uint32_t*)&pr1[ksl*16 + c*2];
                uint32_t pa2 = *(const uint32_t*)&pr0[ksl*16 + c*2 + 8];
                uint32_t pa3 = *(const uint32_t*)&pr1[ksl*16 + c*2 + 8];
                #pragma unroll
                for (int jp = 0; jp < 4; jp++) {
                    int mrow = ksl*16 + (lane & 8) + (lane & 7);
                    int mcol = jp*16 + ((lane >> 4) << 3);
                    uint32_t addr = vsBase + (mrow*72 + mcol) * 2;
                    uint32_t b0e, b1e, b0o, b1o;
                    ldsm_x4_t(b0e, b1e, b0o, b1o, addr);
                    mma_f16(o[jp*2  ], pa0, pa1, pa2, pa3, b0e, b1e);
                    mma_f16(o[jp*2+1], pa0, pa1, pa2, pa3, b0o, b1o);
                }
            }
        }
    }

    float inv0 = 1.f / l0, inv1 = 1.f / l1;
    size_t r0 = (size_t)(b*KS + q0) * DD + h*64;
    size_t r1 = (size_t)(b*KS + q1) * DD + h*64;
    #pragma unroll
    for (int j = 0; j < 8; j++) {
        *(__half2*)&pv[r0 + j*8 + c*2] = __float22half2_rn(make_float2(o[j][0]*inv0, o[j][1]*inv0));
        *(__half2*)&pv[r1 + j*8 + c*2] = __float22half2_rn(make_float2(o[j][2]*inv1, o[j][3]*inv1));
    }
}

// ---------------- K12: scatter ----------------
__global__ void scatter_kernel(const float* __restrict__ sel, const float* __restrict__ bo,
                               const int* __restrict__ idx, const float* __restrict__ gate,
                               float* __restrict__ out) {
    int r = blockIdx.x;
    int b = r / KS;
    int pos = idx[r];
    float ga = gate[r];
    const float4* s4 = (const float4*)(sel + (size_t)r * DD);
    const float4* b4 = (const float4*)(bo  + (size_t)r * DD);
    float4* o4 = (float4*)(out + ((size_t)b*TT + pos) * DD);
    float4 s = s4[threadIdx.x], bb = b4[threadIdx.x];
    float4 u = make_float4(s.x + ga*(bb.x - s.x), s.y + ga*(bb.y - s.y),
                           s.z + ga*(bb.z - s.z), s.w + ga*(bb.w - s.w));
    o4[threadIdx.x] = u;
}

// ---------------- K13: predictor logits + per-row BCE ----------------
__global__ void predrow_kernel(const float* __restrict__ h1, const float* __restrict__ fc2w,
                               const float* __restrict__ fc2b, const float* __restrict__ tgt,
                               float* __restrict__ pred) {
    int warp = (blockIdx.x * blockDim.x + threadIdx.x) >> 5;
    int lane = threadIdx.x & 31;
    if (warp >= NTOK) return;
    const float* row = h1 + (size_t)warp * DQ;
    float s = 0.f;
    #pragma unroll
    for (int i = lane; i < DQ; i += 32) s += row[i] * fc2w[i];
    #pragma unroll
    for (int o = 16; o; o >>= 1) s += __shfl_xor_sync(0xffffffffu, s, o);
    if (lane == 0) {
        float x = s + fc2b[0];
        pred[warp] = bce_term(x, tgt[warp]);
    }
}

// ---------------- K14: loss reduce ----------------
__global__ void loss_reduce(const float* __restrict__ scores, const float* __restrict__ tgt,
                            const float* __restrict__ pred, float* __restrict__ out_aux) {
    __shared__ float sm_main[1024];
    __shared__ float sm_pred[1024];
    int tid = threadIdx.x;
    float sm = 0.f, sp = 0.f;
    for (int i = tid; i < NTOK; i += 1024) {
        sm += bce_term(scores[i], tgt[i]);
        sp += pred[i];
    }
    sm_main[tid] = sm; sm_pred[tid] = sp;
    __syncthreads();
    for (int s = 512; s > 0; s >>= 1) {
        if (tid < s) { sm_main[tid] += sm_main[tid+s]; sm_pred[tid] += sm_pred[tid+s]; }
        __syncthreads();
    }
    if (tid == 0)
        out_aux[0] = 0.01f * (sm_main[0] + sm_pred[0]) / (float)NTOK;
}

// ---------------- host launch ----------------
extern "C" void kernel_launch(void* const* d_in, const int* in_sizes, int n_in,
                              void* d_out, int out_size) {
    const float* hs   = (const float*)d_in[0];
    const float* rw   = (const float*)d_in[1];
    const float* fc1w = (const float*)d_in[2];
    const float* fc1b = (const float*)d_in[3];
    const float* fc2w = (const float*)d_in[4];
    const float* fc2b = (const float*)d_in[5];
    const float* ln1  = (const float*)d_in[6];
    const float* ln2  = (const float*)d_in[7];
    const float* wq   = (const float*)d_in[8];
    const float* wk   = (const float*)d_in[9];
    const float* wv   = (const float*)d_in[10];
    const float* wo   = (const float*)d_in[11];
    const float* wg   = (const float*)d_in[12];
    const float* wu   = (const float*)d_in[13];
    const float* wd   = (const float*)d_in[14];
    float* out = (float*)d_out;

    float *scores, *tgt, *gate, *sel, *h, *ub, *bo, *h1, *pred;
    __half *a16, *q16, *k16, *v16, *pv16, *m16, *gb16, *hs16;
    __half *wqT, *wkT, *wvT, *woT, *wuT, *wgT, *wdT, *fc1T;
    int* idx;
    cudaGetSymbolAddress((void**)&scores, g_scores);
    cudaGetSymbolAddress((void**)&tgt,    g_tgt);
    cudaGetSymbolAddress((void**)&idx,    g_idx);
    cudaGetSymbolAddress((void**)&gate,   g_gate);
    cudaGetSymbolAddress((void**)&sel,    g_sel);
    cudaGetSymbolAddress((void**)&a16,    g_a16);
    cudaGetSymbolAddress((void**)&q16,    g_q16);
    cudaGetSymbolAddress((void**)&k16,    g_k16);
    cudaGetSymbolAddress((void**)&v16,    g_v16);
    cudaGetSymbolAddress((void**)&pv16,   g_pv16);
    cudaGetSymbolAddress((void**)&h,      g_h);
    cudaGetSymbolAddress((void**)&m16,    g_m16);
    cudaGetSymbolAddress((void**)&ub,     g_ub);
    cudaGetSymbolAddress((void**)&gb16,   g_gb16);
    cudaGetSymbolAddress((void**)&bo,     g_bo);
    cudaGetSymbolAddress((void**)&hs16,   g_hs16);
    cudaGetSymbolAddress((void**)&h1,     g_h1);
    cudaGetSymbolAddress((void**)&pred,   g_pred);
    cudaGetSymbolAddress((void**)&wqT,    g_wqT);
    cudaGetSymbolAddress((void**)&wkT,    g_wkT);
    cudaGetSymbolAddress((void**)&wvT,    g_wvT);
    cudaGetSymbolAddress((void**)&woT,    g_woT);
    cudaGetSymbolAddress((void**)&wuT,    g_wuT);
    cudaGetSymbolAddress((void**)&wgT,    g_wgT);
    cudaGetSymbolAddress((void**)&wdT,    g_wdT);
    cudaGetSymbolAddress((void**)&fc1T,   g_fc1T);

    cudaFuncSetAttribute(mma_gemm, cudaFuncAttributeMaxDynamicSharedMemorySize, GEMM_SMEM);

    // ---- weight transpose+convert on s3 ----
    cudaEventRecord(eStart, 0);
    cudaStreamWaitEvent(s3, eStart, 0);
    cudaStreamWaitEvent(s2, eStart, 0);
    cudaStreamWaitEvent(s1, eStart, 0);
    wconv_kernel<<<dim3(32, 32), 256, 0, s3>>>(wq, wqT, DD, DD);
    wconv_kernel<<<dim3(32, 32), 256, 0, s3>>>(wk, wkT, DD, DD);
    wconv_kernel<<<dim3(32, 32), 256, 0, s3>>>(wv, wvT, DD, DD);
    wconv_kernel<<<dim3(32, 32), 256, 0, s3>>>(wo, woT, DD, DD);
    wconv_kernel<<<dim3(128, 32), 256, 0, s3>>>(wu, wuT, DD, FF);
    wconv_kernel<<<dim3(128, 32), 256, 0, s3>>>(wg, wgT, DD, FF);
    wconv_kernel<<<dim3(32, 128), 256, 0, s3>>>(wd, wdT, FF, DD);
    wconv_kernel<<<dim3(8, 32), 256, 0, s3>>>(fc1w, fc1T, DD, DQ);
    cudaEventRecord(eW, s3);

    // ---- copy hidden -> out on s2 ----
    copy_kernel<<<4096, 256, 0, s2>>>((const float4*)hs, (float4*)out, NTOK*DD/4);
    cudaEventRecord(eC, s2);

    // ---- hs -> f16 on s1, then fc1 GEMM + predrow ----
    f2h_kernel<<<4096, 256, 0, s1>>>((const float4*)hs, (uint2*)hs16, NTOK*DD/4);
    cudaStreamWaitEvent(s1, eW, 0);
    mma_gemm<<<dim3(DQ/128, NTOK/128), 256, GEMM_SMEM, s1>>>(hs16, fc1T, h1, NTOK, DQ, DD, fc1b, 1, 0);

    // ---- router + top-k on main ----
    scores_kernel<<<NTOK/8, 256>>>(hs, rw, scores);
    topk_radix<<<BB, 1024>>>(scores, tgt, idx, gate);
    cudaEventRecord(eTopk, 0);

    cudaStreamWaitEvent(s1, eTopk, 0);
    predrow_kernel<<<NTOK/8, 256, 0, s1>>>(h1, fc2w, fc2b, tgt, pred);
    cudaEventRecord(eP, s1);

    // ---- decoder block ----
    gather_rms_kernel<<<ROWS, 256>>>(hs, idx, ln1, sel, a16);
    cudaEventRecord(eA, 0);
    cudaStreamWaitEvent(s2, eA, 0);
    cudaStreamWaitEvent(s2, eW, 0);
    cudaStreamWaitEvent(s3, eA, 0);
    mma_gemm<<<dim3(DD/128, ROWS/128), 256, GEMM_SMEM, s2>>>(a16, wkT, k16, ROWS, DD, DD, nullptr, 0, 1);
    cudaEventRecord(eK, s2);
    mma_gemm<<<dim3(DD/128, ROWS/128), 256, GEMM_SMEM, s3>>>(a16, wvT, v16, ROWS, DD, DD, nullptr, 0, 1);
    cudaEventRecord(eV, s3);
    cudaStreamWaitEvent(0, eW, 0);
    mma_gemm<<<dim3(DD/128, ROWS/128), 256, GEMM_SMEM>>>(a16, wqT, q16, ROWS, DD, DD, nullptr, 0, 1);
    cudaStreamWaitEvent(0, eK, 0);
    rope2h_kernel<<<2*ROWS, 256>>>(q16, k16, idx);
    cudaStreamWaitEvent(0, eV, 0);
    flash_kernel<<<dim3(4, BB*HH), 256>>>(q16, k16, v16, pv16);
    mma_gemm<<<dim3(DD/128, ROWS/128), 256, GEMM_SMEM>>>(pv16, woT, h, ROWS, DD, DD, sel, 2, 0);

    rmsnorm_h_kernel<<<ROWS, 256>>>(h, ln2, m16);
    mma_gemm<<<dim3(FF/128, ROWS/128), 256, GEMM_SMEM>>>(m16, wuT, ub, ROWS, FF, DD, nullptr, 0, 0);
    mma_gemm<<<dim3(FF/128, ROWS/128), 256, GEMM_SMEM>>>(m16, wgT, gb16, ROWS, FF, DD, ub, 3, 1);
    mma_gemm<<<dim3(DD/128, ROWS/128), 256, GEMM_SMEM>>>(gb16, wdT, bo, ROWS, DD, FF, h, 2, 0);

    cudaStreamWaitEvent(0, eC, 0);
    scatter_kernel<<<ROWS, 256>>>(sel, bo, idx, gate, out);

    cudaStreamWaitEvent(0, eP, 0);
    loss_reduce<<<1, 1024>>>(scores, tgt, pred, out + (size_t)NTOK*DD);
}

// round 9
// speedup vs baseline: 5.6907x; 1.0370x over previous
#include <cuda_runtime.h>
#include <cuda_fp16.h>
#include <math.h>
#include <stdint.h>

// ---------------- problem constants ----------------
#define BB 4
#define TT 4096
#define DD 1024
#define FF 4096
#define HH 16
#define HD 64
#define KS 512
#define DQ 256
#define ROWS (BB*KS)           // 2048
#define NTOK (BB*TT)           // 16384

// ---------------- device scratch ----------------
__device__ float  g_scores[NTOK];
__device__ float  g_tgt[NTOK];
__device__ int    g_idx[ROWS];
__device__ float  g_gate[ROWS];
__device__ float  g_sel[ROWS*DD];
__device__ __half g_a16[ROWS*DD];
__device__ __half g_q16[ROWS*DD];
__device__ __half g_k16[ROWS*DD];
__device__ __half g_v16[ROWS*DD];
__device__ __half g_pv16[ROWS*DD];
__device__ float  g_h[ROWS*DD];
__device__ __half g_m16[ROWS*DD];
__device__ __half g_gb16[ROWS*FF];
__device__ float  g_bo[ROWS*DD];
__device__ __half g_hs16[(size_t)NTOK*DD];
__device__ float  g_h1[(size_t)NTOK*DQ];
__device__ float  g_pred[NTOK];
// transposed fp16 weights [N][K]
__device__ __half g_wqT[DD*DD];
__device__ __half g_wkT[DD*DD];
__device__ __half g_wvT[DD*DD];
__device__ __half g_woT[DD*DD];
__device__ __half g_wuT[(size_t)FF*DD];
__device__ __half g_wgT[(size_t)FF*DD];
__device__ __half g_wdT[(size_t)DD*FF];
__device__ __half g_fc1T[DQ*DD];

// ---------------- static streams/events ----------------
static cudaStream_t s1, s2, s3;
static cudaEvent_t eStart, eTopk, eA, eK, eV, eP, eC, eW, eH;
static struct StreamInit {
    StreamInit() {
        cudaStreamCreateWithFlags(&s1, cudaStreamNonBlocking);
        cudaStreamCreateWithFlags(&s2, cudaStreamNonBlocking);
        cudaStreamCreateWithFlags(&s3, cudaStreamNonBlocking);
        cudaEventCreateWithFlags(&eStart, cudaEventDisableTiming);
        cudaEventCreateWithFlags(&eTopk,  cudaEventDisableTiming);
        cudaEventCreateWithFlags(&eA,     cudaEventDisableTiming);
        cudaEventCreateWithFlags(&eK,     cudaEventDisableTiming);
        cudaEventCreateWithFlags(&eV,     cudaEventDisableTiming);
        cudaEventCreateWithFlags(&eP,     cudaEventDisableTiming);
        cudaEventCreateWithFlags(&eC,     cudaEventDisableTiming);
        cudaEventCreateWithFlags(&eW,     cudaEventDisableTiming);
        cudaEventCreateWithFlags(&eH,     cudaEventDisableTiming);
    }
} s_init;

// ---------------- helpers ----------------
__device__ __forceinline__ float gelu_tanh(float x) {
    float x3 = x*x*x;
    return 0.5f * x * (1.f + tanhf(0.7978845608028654f * (x + 0.044715f * x3)));
}
__device__ __forceinline__ float bce_term(float x, float t) {
    return fmaxf(x, 0.f) - x*t + log1pf(expf(-fabsf(x)));
}
__device__ __forceinline__ void cpa16(uint32_t s, const void* g) {
    asm volatile("cp.async.cg.shared.global [%0], [%1], 16;" :: "r"(s), "l"(g));
}
__device__ __forceinline__ void mma_f16(float* d, uint32_t a0, uint32_t a1, uint32_t a2, uint32_t a3,
                                        uint32_t b0, uint32_t b1) {
    asm volatile(
        "mma.sync.aligned.m16n8k16.row.col.f32.f16.f16.f32 "
        "{%0,%1,%2,%3}, {%4,%5,%6,%7}, {%8,%9}, {%0,%1,%2,%3};"
        : "+f"(d[0]), "+f"(d[1]), "+f"(d[2]), "+f"(d[3])
        : "r"(a0), "r"(a1), "r"(a2), "r"(a3), "r"(b0), "r"(b1));
}
__device__ __forceinline__ void ldsm_x4(uint32_t& r0, uint32_t& r1, uint32_t& r2, uint32_t& r3,
                                        uint32_t addr) {
    asm volatile("ldmatrix.sync.aligned.m8n8.x4.shared.b16 {%0,%1,%2,%3}, [%4];"
        : "=r"(r0), "=r"(r1), "=r"(r2), "=r"(r3) : "r"(addr));
}
__device__ __forceinline__ void ldsm_x4_t(uint32_t& r0, uint32_t& r1, uint32_t& r2, uint32_t& r3,
                                          uint32_t addr) {
    asm volatile("ldmatrix.sync.aligned.m8n8.x4.trans.shared.b16 {%0,%1,%2,%3}, [%4];"
        : "=r"(r0), "=r"(r1), "=r"(r2), "=r"(r3) : "r"(addr));
}

// ---------------- W0: weight transpose + f32->f16: w[K][N] -> wt[N][K] ----------------
__global__ void wconv_kernel(const float* __restrict__ w, __half* __restrict__ wt, int K, int N) {
    __shared__ float t[32][33];
    int k0 = blockIdx.y * 32, n0 = blockIdx.x * 32;
    int tx = threadIdx.x & 31, ty = threadIdx.x >> 5;   // 32 x 8
    #pragma unroll
    for (int i = 0; i < 32; i += 8)
        t[ty + i][tx] = w[(size_t)(k0 + ty + i) * N + n0 + tx];
    __syncthreads();
    #pragma unroll
    for (int i = 0; i < 32; i += 8)
        wt[(size_t)(n0 + ty + i) * K + k0 + tx] = __float2half_rn(t[tx][ty + i]);
}

// ---------------- K1: router scores + f32->f16 conversion (fused hs readers) ----------------
__global__ void scores_f2h_kernel(const float* __restrict__ hs, const float* __restrict__ rw,
                                  float* __restrict__ scores, __half* __restrict__ hs16) {
    int warp = (blockIdx.x * blockDim.x + threadIdx.x) >> 5;
    int lane = threadIdx.x & 31;
    if (warp >= NTOK) return;
    const float4* row = (const float4*)(hs + (size_t)warp * DD);
    const float4* w4  = (const float4*)rw;
    uint2* h16 = (uint2*)(hs16 + (size_t)warp * DD);
    float s = 0.f;
    #pragma unroll
    for (int i = lane; i < DD/4; i += 32) {
        float4 a = row[i], b = w4[i];
        s += a.x*b.x + a.y*b.y + a.z*b.z + a.w*b.w;
        __half2 h0 = __float22half2_rn(make_float2(a.x, a.y));
        __half2 h1 = __float22half2_rn(make_float2(a.z, a.w));
        h16[i] = make_uint2(*(uint32_t*)&h0, *(uint32_t*)&h1);
    }
    #pragma unroll
    for (int o = 16; o; o >>= 1) s += __shfl_xor_sync(0xffffffffu, s, o);
    if (lane == 0) scores[warp] = s;
}

// ---------------- K2: radix-select top-k + ascending compaction ----------------
__global__ void topk_radix(const float* __restrict__ scores, float* __restrict__ tgt,
                           int* __restrict__ idxo, float* __restrict__ gateo) {
    __shared__ unsigned su[TT];
    __shared__ int hist[256];
    __shared__ int wsum[32];
    __shared__ unsigned s_prefix;
    __shared__ int s_remain;
    int b = blockIdx.x, tid = threadIdx.x;
    const float* sc = scores + (size_t)b * TT;

    for (int i = tid; i < TT; i += 1024) {
        unsigned bits = __float_as_uint(sc[i]);
        unsigned mask = (unsigned)((int)bits >> 31) | 0x80000000u;
        su[i] = bits ^ mask;
    }
    if (tid == 0) { s_prefix = 0u; s_remain = KS; }
    __syncthreads();

    #pragma unroll
    for (int p = 24; p >= 0; p -= 8) {
        if (tid < 256) hist[tid] = 0;
        __syncthreads();
        unsigned pref = s_prefix;
        for (int i = tid; i < TT; i += 1024) {
            unsigned u = su[i];
            if (p == 24 || (u >> (p + 8)) == (pref >> (p + 8)))
                atomicAdd(&hist[(u >> p) & 255], 1);
        }
        __syncthreads();
        if (tid == 0) {
            int rem = s_remain;
            int bin = 255;
            for (;;) {
                int c = hist[bin];
                if (rem <= c) break;
                rem -= c; bin--;
            }
            s_prefix = pref | ((unsigned)bin << p);
            s_remain = rem;
        }
        __syncthreads();
    }
    unsigned thr = s_prefix;

    int base = tid * 4;
    int flg[4]; int cnt = 0;
    #pragma unroll
    for (int j = 0; j < 4; j++) { flg[j] = (su[base + j] >= thr) ? 1 : 0; cnt += flg[j]; }
    int lane = tid & 31, warp = tid >> 5;
    int inc = cnt;
    #pragma unroll
    for (int o = 1; o < 32; o <<= 1) {
        int n2 = __shfl_up_sync(0xffffffffu, inc, o);
        if (lane >= o) inc += n2;
    }
    if (lane == 31) wsum[warp] = inc;
    __syncthreads();
    if (tid < 32) {
        int v = wsum[tid];
        #pragma unroll
        for (int o = 1; o < 32; o <<= 1) {
            int n2 = __shfl_up_sync(0xffffffffu, v, o);
            if (tid >= o) v += n2;
        }
        wsum[tid] = v;
    }
    __syncthreads();
    int off = inc - cnt + (warp ? wsum[warp - 1] : 0);
    #pragma unroll
    for (int j = 0; j < 4; j++) {
        tgt[(size_t)b*TT + base + j] = flg[j] ? 1.f : 0.f;
        if (flg[j]) {
            idxo[b*KS + off] = base + j;
            float s = sc[base + j];
            gateo[b*KS + off] = 1.f / (1.f + expf(-s));
            off++;
        }
    }
}

// ---------------- K3: copy hidden -> out ----------------
__global__ void copy_kernel(const float4* __restrict__ src, float4* __restrict__ dst, int n4) {
    int stride = gridDim.x * blockDim.x;
    for (int i = blockIdx.x * blockDim.x + threadIdx.x; i < n4; i += stride)
        dst[i] = src[i];
}

// ---------------- K4: fused gather + rmsnorm(ln1) -> sel f32, a f16 ----------------
__global__ void gather_rms_kernel(const float* __restrict__ hs, const int* __restrict__ idx,
                                  const float* __restrict__ g,
                                  float* __restrict__ sel, __half* __restrict__ a16) {
    __shared__ float red[8];
    int r = blockIdx.x, tid = threadIdx.x;
    int b = r / KS;
    int pos = idx[r];
    const float4* src = (const float4*)(hs + ((size_t)b*TT + pos) * DD);
    float4 x = src[tid];
    ((float4*)(sel + (size_t)r * DD))[tid] = x;
    float ss = x.x*x.x + x.y*x.y + x.z*x.z + x.w*x.w;
    #pragma unroll
    for (int o = 16; o; o >>= 1) ss += __shfl_xor_sync(0xffffffffu, ss, o);
    if ((tid & 31) == 0) red[tid >> 5] = ss;
    __syncthreads();
    if (tid < 8) {
        float v = red[tid];
        #pragma unroll
        for (int o = 4; o; o >>= 1) v += __shfl_xor_sync(0xffu, v, o);
        if (tid == 0) red[0] = v;
    }
    __syncthreads();
    float rs = rsqrtf(red[0] / (float)DD + 1e-6f);
    const float4* g4 = (const float4*)g;
    float4 gg = g4[tid];
    __half2 h0 = __float22half2_rn(make_float2(x.x*rs*gg.x, x.y*rs*gg.y));
    __half2 h1 = __float22half2_rn(make_float2(x.z*rs*gg.z, x.w*rs*gg.w));
    uint2* dst = (uint2*)(a16 + (size_t)r * DD);
    dst[tid] = make_uint2(*(uint32_t*)&h0, *(uint32_t*)&h1);
}

// ---------------- K5: rmsnorm f32 -> f16 ----------------
__global__ void rmsnorm_h_kernel(const float* __restrict__ in, const float* __restrict__ g,
                                 __half* __restrict__ out) {
    __shared__ float red[8];
    int r = blockIdx.x, tid = threadIdx.x;
    const float4* x4 = (const float4*)(in + (size_t)r * DD);
    float4 x = x4[tid];
    float ss = x.x*x.x + x.y*x.y + x.z*x.z + x.w*x.w;
    #pragma unroll
    for (int o = 16; o; o >>= 1) ss += __shfl_xor_sync(0xffffffffu, ss, o);
    if ((tid & 31) == 0) red[tid >> 5] = ss;
    __syncthreads();
    if (tid < 8) {
        float v = red[tid];
        #pragma unroll
        for (int o = 4; o; o >>= 1) v += __shfl_xor_sync(0xffu, v, o);
        if (tid == 0) red[0] = v;
    }
    __syncthreads();
    float rs = rsqrtf(red[0] / (float)DD + 1e-6f);
    const float4* g4 = (const float4*)g;
    float4 gg = g4[tid];
    __half2 h0 = __float22half2_rn(make_float2(x.x*rs*gg.x, x.y*rs*gg.y));
    __half2 h1 = __float22half2_rn(make_float2(x.z*rs*gg.z, x.w*rs*gg.w));
    uint2* dst = (uint2*)(out + (size_t)r * DD);
    dst[tid] = make_uint2(*(uint32_t*)&h0, *(uint32_t*)&h1);
}

// ---------------- K6: FP16 GEMM 128x128x32, 3-stage cp.async + ldmatrix ----------------
#define LDH 40
#define T_ST (128*LDH)
#define GEMM_SMEM (3*2*T_ST*2)       // 61440 bytes
#define DUAL_SMEM (3*3*T_ST*2)       // 92160 bytes

__global__ __launch_bounds__(256)
void mma_gemm(const __half* __restrict__ A, const __half* __restrict__ Bt, void* __restrict__ Cv,
              int M, int N, int K, const float* __restrict__ aux, int epi, int ohalf) {
    extern __shared__ __half dynh[];
    __half* As = dynh;
    __half* Bs = dynh + 3*T_ST;

    int tid = threadIdx.x;
    int m0 = blockIdx.y * 128, n0 = blockIdx.x * 128;
    int warp = tid >> 5, lane = tid & 31;
    int wm = (warp >> 2) * 64;
    int wn = (warp & 3) * 32;
    int g = lane >> 2, c = lane & 3;

    float acc[4][4][4];
    #pragma unroll
    for (int i = 0; i < 4; i++)
        #pragma unroll
        for (int j = 0; j < 4; j++)
            #pragma unroll
            for (int r = 0; r < 4; r++) acc[i][j][r] = 0.f;

    int ch0 = tid * 2;
    int ldRow = ch0 >> 2;
    int ldOff = (ch0 & 3) * 8;

    uint32_t asBase = (uint32_t)__cvta_generic_to_shared(As);
    uint32_t bsBase = (uint32_t)__cvta_generic_to_shared(Bs);

    int aRowL = lane & 15;
    int aColL = (lane >> 4) << 3;
    int bRowL = (lane & 7) + ((lane & 16) ? 8 : 0);
    int bColL = (lane & 8) ? 8 : 0;

    int nk = K / 32;

    auto prefetch = [&](int kt) {
        int st = kt % 3;
        const __half* Ag = A + (size_t)(m0 + ldRow) * K + kt*32 + ldOff;
        uint32_t ad = asBase + (st*T_ST + ldRow*LDH + ldOff) * 2;
        cpa16(ad,      Ag);
        cpa16(ad + 16, Ag + 8);
        const __half* Bg = Bt + (size_t)(n0 + ldRow) * K + kt*32 + ldOff;
        uint32_t bd = bsBase + (st*T_ST + ldRow*LDH + ldOff) * 2;
        cpa16(bd,      Bg);
        cpa16(bd + 16, Bg + 8);
        asm volatile("cp.async.commit_group;" ::: "memory");
    };

    prefetch(0);
    if (nk > 1) prefetch(1);

    for (int kt = 0; kt < nk; kt++) {
        if (kt + 1 < nk) {
            asm volatile("cp.async.wait_group 1;" ::: "memory");
        } else {
            asm volatile("cp.async.wait_group 0;" ::: "memory");
        }
        __syncthreads();
        if (kt + 2 < nk) prefetch(kt + 2);

        int st = kt % 3;
        uint32_t aStage = asBase + st*T_ST*2;
        uint32_t bStage = bsBase + st*T_ST*2;
        #pragma unroll
        for (int ks = 0; ks < 2; ks++) {
            int ko = ks * 16;
            uint32_t af[4][4], bf[4][2];
            #pragma unroll
            for (int i = 0; i < 4; i++) {
                uint32_t addr = aStage + ((wm + i*16 + aRowL)*LDH + ko + aColL) * 2;
                ldsm_x4(af[i][0], af[i][1], af[i][2], af[i][3], addr);
            }
            #pragma unroll
            for (int jp = 0; jp < 2; jp++) {
                uint32_t addr = bStage + ((wn + jp*16 + bRowL)*LDH + ko + bColL) * 2;
                ldsm_x4(bf[jp*2][0], bf[jp*2][1], bf[jp*2+1][0], bf[jp*2+1][1], addr);
            }
            #pragma unroll
            for (int i = 0; i < 4; i++)
                #pragma unroll
                for (int j = 0; j < 4; j++)
                    mma_f16(acc[i][j], af[i][0], af[i][1], af[i][2], af[i][3],
                            bf[j][0], bf[j][1]);
        }
    }

    float* C = (float*)Cv;
    __half* C16 = (__half*)Cv;
    #pragma unroll
    for (int i = 0; i < 4; i++) {
        int r0 = m0 + wm + i*16 + g;
        #pragma unroll
        for (int j = 0; j < 4; j++) {
            int col = n0 + wn + j*8 + c*2;
            float2 lo = make_float2(acc[i][j][0], acc[i][j][1]);
            float2 hi = make_float2(acc[i][j][2], acc[i][j][3]);
            if (epi == 1) {
                float b0 = aux[col], b1 = aux[col+1];
                lo.x = gelu_tanh(lo.x + b0); lo.y = gelu_tanh(lo.y + b1);
                hi.x = gelu_tanh(hi.x + b0); hi.y = gelu_tanh(hi.y + b1);
            } else if (epi == 2) {
                const float2 s0 = *(const float2*)&aux[(size_t)r0*N + col];
                const float2 s1 = *(const float2*)&aux[(size_t)(r0+8)*N + col];
                lo.x += s0.x; lo.y += s0.y; hi.x += s1.x; hi.y += s1.y;
            }
            if (ohalf) {
                __half2 l2 = __float22half2_rn(lo);
                __half2 h2 = __float22half2_rn(hi);
                *(__half2*)&C16[(size_t)r0*N + col] = l2;
                *(__half2*)&C16[(size_t)(r0+8)*N + col] = h2;
            } else {
                *(float2*)&C[(size_t)r0*N + col] = lo;
                *(float2*)&C[(size_t)(r0+8)*N + col] = hi;
            }
        }
    }
}

// ---------------- K6b: dual-B GEMM: C16 = silu(A@Bg^T) * (A@Bu^T) ----------------
__global__ __launch_bounds__(256, 1)
void mma_gemm_dual(const __half* __restrict__ A, const __half* __restrict__ Bgt,
                   const __half* __restrict__ But, __half* __restrict__ C16,
                   int M, int N, int K) {
    extern __shared__ __half dynh[];
    __half* As  = dynh;                 // 3 stages
    __half* Bgs = dynh + 3*T_ST;
    __half* Bus = dynh + 6*T_ST;

    int tid = threadIdx.x;
    int m0 = blockIdx.y * 128, n0 = blockIdx.x * 128;
    int warp = tid >> 5, lane = tid & 31;
    int wm = (warp >> 2) * 64;
    int wn = (warp & 3) * 32;
    int g = lane >> 2, c = lane & 3;

    float accg[4][4][4], accu[4][4][4];
    #pragma unroll
    for (int i = 0; i < 4; i++)
        #pragma unroll
        for (int j = 0; j < 4; j++)
            #pragma unroll
            for (int r = 0; r < 4; r++) { accg[i][j][r] = 0.f; accu[i][j][r] = 0.f; }

    int ch0 = tid * 2;
    int ldRow = ch0 >> 2;
    int ldOff = (ch0 & 3) * 8;

    uint32_t asBase = (uint32_t)__cvta_generic_to_shared(As);
    uint32_t bgBase = (uint32_t)__cvta_generic_to_shared(Bgs);
    uint32_t buBase = (uint32_t)__cvta_generic_to_shared(Bus);

    int aRowL = lane & 15;
    int aColL = (lane >> 4) << 3;
    int bRowL = (lane & 7) + ((lane & 16) ? 8 : 0);
    int bColL = (lane & 8) ? 8 : 0;

    int nk = K / 32;

    auto prefetch = [&](int kt) {
        int st = kt % 3;
        const __half* Ag = A + (size_t)(m0 + ldRow) * K + kt*32 + ldOff;
        uint32_t ad = asBase + (st*T_ST + ldRow*LDH + ldOff) * 2;
        cpa16(ad,      Ag);
        cpa16(ad + 16, Ag + 8);
        const __half* Gg = Bgt + (size_t)(n0 + ldRow) * K + kt*32 + ldOff;
        uint32_t gd = bgBase + (st*T_ST + ldRow*LDH + ldOff) * 2;
        cpa16(gd,      Gg);
        cpa16(gd + 16, Gg + 8);
        const __half* Ug = But + (size_t)(n0 + ldRow) * K + kt*32 + ldOff;
        uint32_t ud = buBase + (st*T_ST + ldRow*LDH + ldOff) * 2;
        cpa16(ud,      Ug);
        cpa16(ud + 16, Ug + 8);
        asm volatile("cp.async.commit_group;" ::: "memory");
    };

    prefetch(0);
    if (nk > 1) prefetch(1);

    for (int kt = 0; kt < nk; kt++) {
        if (kt + 1 < nk) {
            asm volatile("cp.async.wait_group 1;" ::: "memory");
        } else {
            asm volatile("cp.async.wait_group 0;" ::: "memory");
        }
        __syncthreads();
        if (kt + 2 < nk) prefetch(kt + 2);

        int st = kt % 3;
        uint32_t aStage = asBase + st*T_ST*2;
        uint32_t gStage = bgBase + st*T_ST*2;
        uint32_t uStage = buBase + st*T_ST*2;
        #pragma unroll
        for (int ks = 0; ks < 2; ks++) {
            int ko = ks * 16;
            uint32_t af[4][4], bg[4][2], bu[4][2];
            #pragma unroll
            for (int i = 0; i < 4; i++) {
                uint32_t addr = aStage + ((wm + i*16 + aRowL)*LDH + ko + aColL) * 2;
                ldsm_x4(af[i][0], af[i][1], af[i][2], af[i][3], addr);
            }
            #pragma unroll
            for (int jp = 0; jp < 2; jp++) {
                uint32_t ga = gStage + ((wn + jp*16 + bRowL)*LDH + ko + bColL) * 2;
                ldsm_x4(bg[jp*2][0], bg[jp*2][1], bg[jp*2+1][0], bg[jp*2+1][1], ga);
                uint32_t ua = uStage + ((wn + jp*16 + bRowL)*LDH + ko + bColL) * 2;
                ldsm_x4(bu[jp*2][0], bu[jp*2][1], bu[jp*2+1][0], bu[jp*2+1][1], ua);
            }
            #pragma unroll
            for (int i = 0; i < 4; i++)
                #pragma unroll
                for (int j = 0; j < 4; j++) {
                    mma_f16(accg[i][j], af[i][0], af[i][1], af[i][2], af[i][3],
                            bg[j][0], bg[j][1]);
                    mma_f16(accu[i][j], af[i][0], af[i][1], af[i][2], af[i][3],
                            bu[j][0], bu[j][1]);
                }
        }
    }

    #pragma unroll
    for (int i = 0; i < 4; i++) {
        int r0 = m0 + wm + i*16 + g;
        #pragma unroll
        for (int j = 0; j < 4; j++) {
            int col = n0 + wn + j*8 + c*2;
            float g0 = accg[i][j][0], g1 = accg[i][j][1];
            float g2 = accg[i][j][2], g3 = accg[i][j][3];
            float v0 = g0 / (1.f + expf(-g0)) * accu[i][j][0];
            float v1 = g1 / (1.f + expf(-g1)) * accu[i][j][1];
            float v2 = g2 / (1.f + expf(-g2)) * accu[i][j][2];
            float v3 = g3 / (1.f + expf(-g3)) * accu[i][j][3];
            __half2 l2 = __float22half2_rn(make_float2(v0, v1));
            __half2 h2 = __float22half2_rn(make_float2(v2, v3));
            *(__half2*)&C16[(size_t)r0*N + col] = l2;
            *(__half2*)&C16[(size_t)(r0+8)*N + col] = h2;
        }
    }
}

// ---------------- K7: RoPE fp16 (q and k in one launch) ----------------
__global__ void rope2h_kernel(__half* __restrict__ q, __half* __restrict__ k,
                              const int* __restrict__ idx) {
    int blk = blockIdx.x;
    __half* buf = (blk < ROWS) ? q : k;
    int r = (blk < ROWS) ? blk : blk - ROWS;
    float pos = (float)idx[r];
    __half* base = buf + (size_t)r * DD;
    const float C = -0.415241011861f;   // -log2(10000)/32
    for (int c = threadIdx.x; c < 512; c += 256) {
        int h = c >> 5, i = c & 31;
        float inv = exp2f((float)i * C);
        float ang = pos * inv;
        float s, co; sincosf(ang, &s, &co);
        __half* p = base + h * 64;
        float x1 = __half2float(p[i]), x2 = __half2float(p[i + 32]);
        p[i]      = __float2half_rn(x1*co - x2*s);
        p[i + 32] = __float2half_rn(x2*co + x1*s);
    }
}

// ---------------- K8: fused flash attention fp16 ----------------
__global__ __launch_bounds__(256)
void flash_kernel(const __half* __restrict__ q, const __half* __restrict__ k,
                  const __half* __restrict__ v, __half* __restrict__ pv) {
    __shared__ __half Ks[64*72];
    __shared__ __half Vs[64*72];
    __shared__ __half Ps[128*72];

    int qp = 3 - blockIdx.x;
    int bh = blockIdx.y, b = bh >> 4, h = bh & 15;
    int tid = threadIdx.x;
    int w = tid >> 5, lane = tid & 31, g = lane >> 2, c = lane & 3;

    #pragma unroll
    for (int p = 0; p < 4; p++) {
        int e = p*256 + tid;
        int row = e >> 3, col = (e & 7) * 8;
        *(float4*)&Ps[row*72 + col] =
            *(const float4*)&q[((size_t)(b*KS + qp*128 + row))*DD + h*64 + col];
    }
    __syncthreads();
    uint32_t qa[4][4];
    {
        const __half* pr0 = &Ps[(w*16 + g)*72];
        const __half* pr1 = &Ps[(w*16 + g + 8)*72];
        #pragma unroll
        for (int d = 0; d < 4; d++) {
            qa[d][0] = *(const uint32_t*)&pr0[d*16 + c*2];
            qa[d][1] = *(const uint32_t*)&pr1[d*16 + c*2];
            qa[d][2] = *(const uint32_t*)&pr0[d*16 + c*2 + 8];
            qa[d][3] = *(const uint32_t*)&pr1[d*16 + c*2 + 8];
        }
    }

    float o[8][4];
    #pragma unroll
    for (int j = 0; j < 8; j++)
        #pragma unroll
        for (int r = 0; r < 4; r++) o[j][r] = 0.f;
    float m0 = -1e38f, m1 = -1e38f, l0 = 0.f, l1 = 0.f;

    int q0 = qp*128 + w*16 + g;
    int q1 = q0 + 8;
    const float SC = 0.125f;
    int ktmax = 2*qp + 1;
    uint32_t vsBase = (uint32_t)__cvta_generic_to_shared(Vs);
    uint32_t ksBase = (uint32_t)__cvta_generic_to_shared(Ks);
    int bRowL = (lane & 7) + ((lane & 16) ? 8 : 0);
    int bColL = (lane & 8) ? 8 : 0;

    for (int kt = 0; kt <= ktmax; kt++) {
        __syncthreads();
        #pragma unroll
        for (int p = 0; p < 2; p++) {
            int e = p*256 + tid;
            int row = e >> 3, col = (e & 7) * 8;
            *(float4*)&Ks[row*72 + col] =
                *(const float4*)&k[((size_t)(b*KS + kt*64 + row))*DD + h*64 + col];
            *(float4*)&Vs[row*72 + col] =
                *(const float4*)&v[((size_t)(b*KS + kt*64 + row))*DD + h*64 + col];
        }
        __syncthreads();

        float s[8][4];
        #pragma unroll
        for (int j = 0; j < 8; j++)
            #pragma unroll
            for (int r = 0; r < 4; r++) s[j][r] = 0.f;
        #pragma unroll
        for (int d = 0; d < 4; d++) {
            #pragma unroll
            for (int jp = 0; jp < 4; jp++) {
                uint32_t addr = ksBase + ((jp*16 + bRowL)*72 + d*16 + bColL) * 2;
                uint32_t b0a, b1a, b0b, b1b;
                ldsm_x4(b0a, b1a, b0b, b1b, addr);
                mma_f16(s[jp*2  ], qa[d][0], qa[d][1], qa[d][2], qa[d][3], b0a, b1a);
                mma_f16(s[jp*2+1], qa[d][0], qa[d][1], qa[d][2], qa[d][3], b0b, b1b);
            }
        }

        float mx0 = m0, mx1 = m1;
        #pragma unroll
        for (int j = 0; j < 8; j++) {
            int kc = kt*64 + j*8 + c*2;
            s[j][0] = (kc   <= q0) ? s[j][0]*SC : -1e30f;
            s[j][1] = (kc+1 <= q0) ? s[j][1]*SC : -1e30f;
            s[j][2] = (kc   <= q1) ? s[j][2]*SC : -1e30f;
            s[j][3] = (kc+1 <= q1) ? s[j][3]*SC : -1e30f;
            mx0 = fmaxf(mx0, fmaxf(s[j][0], s[j][1]));
            mx1 = fmaxf(mx1, fmaxf(s[j][2], s[j][3]));
        }
        mx0 = fmaxf(mx0, __shfl_xor_sync(0xffffffffu, mx0, 1));
        mx0 = fmaxf(mx0, __shfl_xor_sync(0xffffffffu, mx0, 2));
        mx1 = fmaxf(mx1, __shfl_xor_sync(0xffffffffu, mx1, 1));
        mx1 = fmaxf(mx1, __shfl_xor_sync(0xffffffffu, mx1, 2));

        float al0 = expf(m0 - mx0), al1 = expf(m1 - mx1);
        m0 = mx0; m1 = mx1;
        float sum0 = 0.f, sum1 = 0.f;
        #pragma unroll
        for (int j = 0; j < 8; j++) {
            s[j][0] = expf(s[j][0] - mx0);
            s[j][1] = expf(s[j][1] - mx0);
            s[j][2] = expf(s[j][2] - mx1);
            s[j][3] = expf(s[j][3] - mx1);
            sum0 += s[j][0] + s[j][1];
            sum1 += s[j][2] + s[j][3];
        }
        sum0 += __shfl_xor_sync(0xffffffffu, sum0, 1);
        sum0 += __shfl_xor_sync(0xffffffffu, sum0, 2);
        sum1 += __shfl_xor_sync(0xffffffffu, sum1, 1);
        sum1 += __shfl_xor_sync(0xffffffffu, sum1, 2);
        l0 = l0*al0 + sum0;
        l1 = l1*al1 + sum1;
        #pragma unroll
        for (int j = 0; j < 8; j++) {
            o[j][0] *= al0; o[j][1] *= al0;
            o[j][2] *= al1; o[j][3] *= al1;
        }

        {
            __half* pr0 = &Ps[(w*16 + g)*72];
            __half* pr1 = &Ps[(w*16 + g + 8)*72];
            #pragma unroll
            for (int j = 0; j < 8; j++) {
                *(__half2*)&pr0[j*8 + c*2] = __float22half2_rn(make_float2(s[j][0], s[j][1]));
                *(__half2*)&pr1[j*8 + c*2] = __float22half2_rn(make_float2(s[j][2], s[j][3]));
            }
        }
        __syncwarp();

        {
            const __half* pr0 = &Ps[(w*16 + g)*72];
            const __half* pr1 = &Ps[(w*16 + g + 8)*72];
            #pragma unroll
            for (int ksl = 0; ksl < 4; ksl++) {
                uint32_t pa0 = *(const uint32_t*)&pr0[ksl*16 + c*2];
                uint32_t pa1 = *(const uint32_t*)&pr1[ksl*16 + c*2];
                uint32_t pa2 = *(const uint32_t*)&pr0[ksl*16 + c*2 + 8];
                uint32_t pa3 = *(const uint32_t*)&pr1[ksl*16 + c*2 + 8];
                #pragma unroll
                for (int jp = 0; jp < 4; jp++) {
                    int mrow = ksl*16 + (lane & 8) + (lane & 7);
                    int mcol = jp*16 + ((lane >> 4) << 3);
                    uint32_t addr = vsBase + (mrow*72 + mcol) * 2;
                    uint32_t b0e, b1e, b0o, b1o;
                    ldsm_x4_t(b0e, b1e, b0o, b1o, addr);
                    mma_f16(o[jp*2  ], pa0, pa1, pa2, pa3, b0e, b1e);
                    mma_f16(o[jp*2+1], pa0, pa1, pa2, pa3, b0o, b1o);
                }
            }
        }
    }

    float inv0 = 1.f / l0, inv1 = 1.f / l1;
    size_t r0 = (size_t)(b*KS + q0) * DD + h*64;
    size_t r1 = (size_t)(b*KS + q1) * DD + h*64;
    #pragma unroll
    for (int j = 0; j < 8; j++) {
        *(__half2*)&pv[r0 + j*8 + c*2] = __float22half2_rn(make_float2(o[j][0]*inv0, o[j][1]*inv0));
        *(__half2*)&pv[r1 + j*8 + c*2] = __float22half2_rn(make_float2(o[j][2]*inv1, o[j][3]*inv1));
    }
}

// ---------------- K12: scatter ----------------
__global__ void scatter_kernel(const float* __restrict__ sel, const float* __restrict__ bo,
                               const int* __restrict__ idx, const float* __restrict__ gate,
                               float* __restrict__ out) {
    int r = blockIdx.x;
    int b = r / KS;
    int pos = idx[r];
    float ga = gate[r];
    const float4* s4 = (const float4*)(sel + (size_t)r * DD);
    const float4* b4 = (const float4*)(bo  + (size_t)r * DD);
    float4* o4 = (float4*)(out + ((size_t)b*TT + pos) * DD);
    float4 s = s4[threadIdx.x], bb = b4[threadIdx.x];
    float4 u = make_float4(s.x + ga*(bb.x - s.x), s.y + ga*(bb.y - s.y),
                           s.z + ga*(bb.z - s.z), s.w + ga*(bb.w - s.w));
    o4[threadIdx.x] = u;
}

// ---------------- K13: predictor logits + per-row BCE ----------------
__global__ void predrow_kernel(const float* __restrict__ h1, const float* __restrict__ fc2w,
                               const float* __restrict__ fc2b, const float* __restrict__ tgt,
                               float* __restrict__ pred) {
    int warp = (blockIdx.x * blockDim.x + threadIdx.x) >> 5;
    int lane = threadIdx.x & 31;
    if (warp >= NTOK) return;
    const float* row = h1 + (size_t)warp * DQ;
    float s = 0.f;
    #pragma unroll
    for (int i = lane; i < DQ; i += 32) s += row[i] * fc2w[i];
    #pragma unroll
    for (int o = 16; o; o >>= 1) s += __shfl_xor_sync(0xffffffffu, s, o);
    if (lane == 0) {
        float x = s + fc2b[0];
        pred[warp] = bce_term(x, tgt[warp]);
    }
}

// ---------------- K14: loss reduce ----------------
__global__ void loss_reduce(const float* __restrict__ scores, const float* __restrict__ tgt,
                            const float* __restrict__ pred, float* __restrict__ out_aux) {
    __shared__ float sm_main[1024];
    __shared__ float sm_pred[1024];
    int tid = threadIdx.x;
    float sm = 0.f, sp = 0.f;
    for (int i = tid; i < NTOK; i += 1024) {
        sm += bce_term(scores[i], tgt[i]);
        sp += pred[i];
    }
    sm_main[tid] = sm; sm_pred[tid] = sp;
    __syncthreads();
    for (int s = 512; s > 0; s >>= 1) {
        if (tid < s) { sm_main[tid] += sm_main[tid+s]; sm_pred[tid] += sm_pred[tid+s]; }
        __syncthreads();
    }
    if (tid == 0)
        out_aux[0] = 0.01f * (sm_main[0] + sm_pred[0]) / (float)NTOK;
}

// ---------------- host launch ----------------
extern "C" void kernel_launch(void* const* d_in, const int* in_sizes, int n_in,
                              void* d_out, int out_size) {
    const float* hs   = (const float*)d_in[0];
    const float* rw   = (const float*)d_in[1];
    const float* fc1w = (const float*)d_in[2];
    const float* fc1b = (const float*)d_in[3];
    const float* fc2w = (const float*)d_in[4];
    const float* fc2b = (const float*)d_in[5];
    const float* ln1  = (const float*)d_in[6];
    const float* ln2  = (const float*)d_in[7];
    const float* wq   = (const float*)d_in[8];
    const float* wk   = (const float*)d_in[9];
    const float* wv   = (const float*)d_in[10];
    const float* wo   = (const float*)d_in[11];
    const float* wg   = (const float*)d_in[12];
    const float* wu   = (const float*)d_in[13];
    const float* wd   = (const float*)d_in[14];
    float* out = (float*)d_out;

    float *scores, *tgt, *gate, *sel, *h, *bo, *h1, *pred;
    __half *a16, *q16, *k16, *v16, *pv16, *m16, *gb16, *hs16;
    __half *wqT, *wkT, *wvT, *woT, *wuT, *wgT, *wdT, *fc1T;
    int* idx;
    cudaGetSymbolAddress((void**)&scores, g_scores);
    cudaGetSymbolAddress((void**)&tgt,    g_tgt);
    cudaGetSymbolAddress((void**)&idx,    g_idx);
    cudaGetSymbolAddress((void**)&gate,   g_gate);
    cudaGetSymbolAddress((void**)&sel,    g_sel);
    cudaGetSymbolAddress((void**)&a16,    g_a16);
    cudaGetSymbolAddress((void**)&q16,    g_q16);
    cudaGetSymbolAddress((void**)&k16,    g_k16);
    cudaGetSymbolAddress((void**)&v16,    g_v16);
    cudaGetSymbolAddress((void**)&pv16,   g_pv16);
    cudaGetSymbolAddress((void**)&h,      g_h);
    cudaGetSymbolAddress((void**)&m16,    g_m16);
    cudaGetSymbolAddress((void**)&gb16,   g_gb16);
    cudaGetSymbolAddress((void**)&bo,     g_bo);
    cudaGetSymbolAddress((void**)&hs16,   g_hs16);
    cudaGetSymbolAddress((void**)&h1,     g_h1);
    cudaGetSymbolAddress((void**)&pred,   g_pred);
    cudaGetSymbolAddress((void**)&wqT,    g_wqT);
    cudaGetSymbolAddress((void**)&wkT,    g_wkT);
    cudaGetSymbolAddress((void**)&wvT,    g_wvT);
    cudaGetSymbolAddress((void**)&woT,    g_woT);
    cudaGetSymbolAddress((void**)&wuT,    g_wuT);
    cudaGetSymbolAddress((void**)&wgT,    g_wgT);
    cudaGetSymbolAddress((void**)&wdT,    g_wdT);
    cudaGetSymbolAddress((void**)&fc1T,   g_fc1T);

    cudaFuncSetAttribute(mma_gemm, cudaFuncAttributeMaxDynamicSharedMemorySize, GEMM_SMEM);
    cudaFuncSetAttribute(mma_gemm_dual, cudaFuncAttributeMaxDynamicSharedMemorySize, DUAL_SMEM);

    // ---- weight transpose+convert on s3 ----
    cudaEventRecord(eStart, 0);
    cudaStreamWaitEvent(s3, eStart, 0);
    cudaStreamWaitEvent(s2, eStart, 0);
    cudaStreamWaitEvent(s1, eStart, 0);
    wconv_kernel<<<dim3(32, 32), 256, 0, s3>>>(wq, wqT, DD, DD);
    wconv_kernel<<<dim3(32, 32), 256, 0, s3>>>(wk, wkT, DD, DD);
    wconv_kernel<<<dim3(32, 32), 256, 0, s3>>>(wv, wvT, DD, DD);
    wconv_kernel<<<dim3(32, 32), 256, 0, s3>>>(wo, woT, DD, DD);
    wconv_kernel<<<dim3(128, 32), 256, 0, s3>>>(wu, wuT, DD, FF);
    wconv_kernel<<<dim3(128, 32), 256, 0, s3>>>(wg, wgT, DD, FF);
    wconv_kernel<<<dim3(32, 128), 256, 0, s3>>>(wd, wdT, FF, DD);
    wconv_kernel<<<dim3(8, 32), 256, 0, s3>>>(fc1w, fc1T, DD, DQ);
    cudaEventRecord(eW, s3);

    // ---- copy hidden -> out on s2 ----
    copy_kernel<<<4096, 256, 0, s2>>>((const float4*)hs, (float4*)out, NTOK*DD/4);
    cudaEventRecord(eC, s2);

    // ---- router scores + hs->f16 (fused) on main ----
    scores_f2h_kernel<<<NTOK/8, 256>>>(hs, rw, scores, hs16);
    cudaEventRecord(eH, 0);
    topk_radix<<<BB, 1024>>>(scores, tgt, idx, gate);
    cudaEventRecord(eTopk, 0);

    // ---- predictor path on s1 ----
    cudaStreamWaitEvent(s1, eH, 0);
    cudaStreamWaitEvent(s1, eW, 0);
    mma_gemm<<<dim3(DQ/128, NTOK/128), 256, GEMM_SMEM, s1>>>(hs16, fc1T, h1, NTOK, DQ, DD, fc1b, 1, 0);
    cudaStreamWaitEvent(s1, eTopk, 0);
    predrow_kernel<<<NTOK/8, 256, 0, s1>>>(h1, fc2w, fc2b, tgt, pred);
    cudaEventRecord(eP, s1);

    // ---- decoder block ----
    gather_rms_kernel<<<ROWS, 256>>>(hs, idx, ln1, sel, a16);
    cudaEventRecord(eA, 0);
    cudaStreamWaitEvent(s2, eA, 0);
    cudaStreamWaitEvent(s2, eW, 0);
    cudaStreamWaitEvent(s3, eA, 0);
    mma_gemm<<<dim3(DD/128, ROWS/128), 256, GEMM_SMEM, s2>>>(a16, wkT, k16, ROWS, DD, DD, nullptr, 0, 1);
    cudaEventRecord(eK, s2);
    mma_gemm<<<dim3(DD/128, ROWS/128), 256, GEMM_SMEM, s3>>>(a16, wvT, v16, ROWS, DD, DD, nullptr, 0, 1);
    cudaEventRecord(eV, s3);
    cudaStreamWaitEvent(0, eW, 0);
    mma_gemm<<<dim3(DD/128, ROWS/128), 256, GEMM_SMEM>>>(a16, wqT, q16, ROWS, DD, DD, nullptr, 0, 1);
    cudaStreamWaitEvent(0, eK, 0);
    rope2h_kernel<<<2*ROWS, 256>>>(q16, k16, idx);
    cudaStreamWaitEvent(0, eV, 0);
    flash_kernel<<<dim3(4, BB*HH), 256>>>(q16, k16, v16, pv16);
    mma_gemm<<<dim3(DD/128, ROWS/128), 256, GEMM_SMEM>>>(pv16, woT, h, ROWS, DD, DD, sel, 2, 0);

    rmsnorm_h_kernel<<<ROWS, 256>>>(h, ln2, m16);
    mma_gemm_dual<<<dim3(FF/128, ROWS/128), 256, DUAL_SMEM>>>(m16, wgT, wuT, gb16, ROWS, FF, DD);
    mma_gemm<<<dim3(DD/128, ROWS/128), 256, GEMM_SMEM>>>(gb16, wdT, bo, ROWS, DD, FF, h, 2, 0);

    cudaStreamWaitEvent(0, eC, 0);
    scatter_kernel<<<ROWS, 256>>>(sel, bo, idx, gate, out);

    cudaStreamWaitEvent(0, eP, 0);
    loss_reduce<<<1, 1024>>>(scores, tgt, pred, out + (size_t)NTOK*DD);
}

// round 10
// speedup vs baseline: 5.9191x; 1.0401x over previous
#include <cuda_runtime.h>
#include <cuda_fp16.h>
#include <math.h>
#include <stdint.h>

// ---------------- problem constants ----------------
#define BB 4
#define TT 4096
#define DD 1024
#define FF 4096
#define HH 16
#define HD 64
#define KS 512
#define DQ 256
#define ROWS (BB*KS)           // 2048
#define NTOK (BB*TT)           // 16384

// ---------------- device scratch ----------------
__device__ float  g_scores[NTOK];
__device__ float  g_tgt[NTOK];
__device__ int    g_idx[ROWS];
__device__ float  g_gate[ROWS];
__device__ float  g_sel[ROWS*DD];
__device__ __half g_a16[ROWS*DD];
__device__ __half g_q16[ROWS*DD];
__device__ __half g_k16[ROWS*DD];
__device__ __half g_v16[ROWS*DD];
__device__ __half g_pv16[ROWS*DD];
__device__ float  g_h[ROWS*DD];
__device__ __half g_m16[ROWS*DD];
__device__ __half g_gb16[ROWS*FF];
__device__ float  g_bo[ROWS*DD];
__device__ __half g_hs16[(size_t)NTOK*DD];
__device__ float  g_h1[(size_t)NTOK*DQ];
__device__ float  g_pred[NTOK];
__device__ __half g_wqT[DD*DD];
__device__ __half g_wkT[DD*DD];
__device__ __half g_wvT[DD*DD];
__device__ __half g_woT[DD*DD];
__device__ __half g_wuT[(size_t)FF*DD];
__device__ __half g_wgT[(size_t)FF*DD];
__device__ __half g_wdT[(size_t)DD*FF];
__device__ __half g_fc1T[DQ*DD];

// ---------------- static streams/events ----------------
static cudaStream_t s1, s2, s3;
static cudaEvent_t eStart, eTopk, eA, eK, eV, eP, eC, eW, eH;
static struct StreamInit {
    StreamInit() {
        cudaStreamCreateWithFlags(&s1, cudaStreamNonBlocking);
        cudaStreamCreateWithFlags(&s2, cudaStreamNonBlocking);
        cudaStreamCreateWithFlags(&s3, cudaStreamNonBlocking);
        cudaEventCreateWithFlags(&eStart, cudaEventDisableTiming);
        cudaEventCreateWithFlags(&eTopk,  cudaEventDisableTiming);
        cudaEventCreateWithFlags(&eA,     cudaEventDisableTiming);
        cudaEventCreateWithFlags(&eK,     cudaEventDisableTiming);
        cudaEventCreateWithFlags(&eV,     cudaEventDisableTiming);
        cudaEventCreateWithFlags(&eP,     cudaEventDisableTiming);
        cudaEventCreateWithFlags(&eC,     cudaEventDisableTiming);
        cudaEventCreateWithFlags(&eW,     cudaEventDisableTiming);
        cudaEventCreateWithFlags(&eH,     cudaEventDisableTiming);
    }
} s_init;

// ---------------- helpers ----------------
__device__ __forceinline__ float gelu_tanh(float x) {
    float x3 = x*x*x;
    return 0.5f * x * (1.f + tanhf(0.7978845608028654f * (x + 0.044715f * x3)));
}
__device__ __forceinline__ float bce_term(float x, float t) {
    return fmaxf(x, 0.f) - x*t + log1pf(expf(-fabsf(x)));
}
__device__ __forceinline__ void cpa16(uint32_t s, const void* g) {
    asm volatile("cp.async.cg.shared.global [%0], [%1], 16;" :: "r"(s), "l"(g));
}
__device__ __forceinline__ void mma_f16(float* d, uint32_t a0, uint32_t a1, uint32_t a2, uint32_t a3,
                                        uint32_t b0, uint32_t b1) {
    asm volatile(
        "mma.sync.aligned.m16n8k16.row.col.f32.f16.f16.f32 "
        "{%0,%1,%2,%3}, {%4,%5,%6,%7}, {%8,%9}, {%0,%1,%2,%3};"
        : "+f"(d[0]), "+f"(d[1]), "+f"(d[2]), "+f"(d[3])
        : "r"(a0), "r"(a1), "r"(a2), "r"(a3), "r"(b0), "r"(b1));
}
__device__ __forceinline__ void ldsm_x4(uint32_t& r0, uint32_t& r1, uint32_t& r2, uint32_t& r3,
                                        uint32_t addr) {
    asm volatile("ldmatrix.sync.aligned.m8n8.x4.shared.b16 {%0,%1,%2,%3}, [%4];"
        : "=r"(r0), "=r"(r1), "=r"(r2), "=r"(r3) : "r"(addr));
}
__device__ __forceinline__ void ldsm_x4_t(uint32_t& r0, uint32_t& r1, uint32_t& r2, uint32_t& r3,
                                          uint32_t addr) {
    asm volatile("ldmatrix.sync.aligned.m8n8.x4.trans.shared.b16 {%0,%1,%2,%3}, [%4];"
        : "=r"(r0), "=r"(r1), "=r"(r2), "=r"(r3) : "r"(addr));
}

// ---------------- W0: weight transpose + f32->f16 ----------------
__global__ void wconv_kernel(const float* __restrict__ w, __half* __restrict__ wt, int K, int N) {
    __shared__ float t[32][33];
    int k0 = blockIdx.y * 32, n0 = blockIdx.x * 32;
    int tx = threadIdx.x & 31, ty = threadIdx.x >> 5;
    #pragma unroll
    for (int i = 0; i < 32; i += 8)
        t[ty + i][tx] = w[(size_t)(k0 + ty + i) * N + n0 + tx];
    __syncthreads();
    #pragma unroll
    for (int i = 0; i < 32; i += 8)
        wt[(size_t)(n0 + ty + i) * K + k0 + tx] = __float2half_rn(t[tx][ty + i]);
}

// ---------------- K1: router scores + f32->f16 ----------------
__global__ void scores_f2h_kernel(const float* __restrict__ hs, const float* __restrict__ rw,
                                  float* __restrict__ scores, __half* __restrict__ hs16) {
    int warp = (blockIdx.x * blockDim.x + threadIdx.x) >> 5;
    int lane = threadIdx.x & 31;
    if (warp >= NTOK) return;
    const float4* row = (const float4*)(hs + (size_t)warp * DD);
    const float4* w4  = (const float4*)rw;
    uint2* h16 = (uint2*)(hs16 + (size_t)warp * DD);
    float s = 0.f;
    #pragma unroll
    for (int i = lane; i < DD/4; i += 32) {
        float4 a = row[i], b = w4[i];
        s += a.x*b.x + a.y*b.y + a.z*b.z + a.w*b.w;
        __half2 h0 = __float22half2_rn(make_float2(a.x, a.y));
        __half2 h1 = __float22half2_rn(make_float2(a.z, a.w));
        h16[i] = make_uint2(*(uint32_t*)&h0, *(uint32_t*)&h1);
    }
    #pragma unroll
    for (int o = 16; o; o >>= 1) s += __shfl_xor_sync(0xffffffffu, s, o);
    if (lane == 0) scores[warp] = s;
}

// ---------------- K2: radix-select top-k ----------------
__global__ void topk_radix(const float* __restrict__ scores, float* __restrict__ tgt,
                           int* __restrict__ idxo, float* __restrict__ gateo) {
    __shared__ unsigned su[TT];
    __shared__ int hist[256];
    __shared__ int wsum[32];
    __shared__ unsigned s_prefix;
    __shared__ int s_remain;
    int b = blockIdx.x, tid = threadIdx.x;
    const float* sc = scores + (size_t)b * TT;

    for (int i = tid; i < TT; i += 1024) {
        unsigned bits = __float_as_uint(sc[i]);
        unsigned mask = (unsigned)((int)bits >> 31) | 0x80000000u;
        su[i] = bits ^ mask;
    }
    if (tid == 0) { s_prefix = 0u; s_remain = KS; }
    __syncthreads();

    #pragma unroll
    for (int p = 24; p >= 0; p -= 8) {
        if (tid < 256) hist[tid] = 0;
        __syncthreads();
        unsigned pref = s_prefix;
        for (int i = tid; i < TT; i += 1024) {
            unsigned u = su[i];
            if (p == 24 || (u >> (p + 8)) == (pref >> (p + 8)))
                atomicAdd(&hist[(u >> p) & 255], 1);
        }
        __syncthreads();
        if (tid == 0) {
            int rem = s_remain;
            int bin = 255;
            for (;;) {
                int c = hist[bin];
                if (rem <= c) break;
                rem -= c; bin--;
            }
            s_prefix = pref | ((unsigned)bin << p);
            s_remain = rem;
        }
        __syncthreads();
    }
    unsigned thr = s_prefix;

    int base = tid * 4;
    int flg[4]; int cnt = 0;
    #pragma unroll
    for (int j = 0; j < 4; j++) { flg[j] = (su[base + j] >= thr) ? 1 : 0; cnt += flg[j]; }
    int lane = tid & 31, warp = tid >> 5;
    int inc = cnt;
    #pragma unroll
    for (int o = 1; o < 32; o <<= 1) {
        int n2 = __shfl_up_sync(0xffffffffu, inc, o);
        if (lane >= o) inc += n2;
    }
    if (lane == 31) wsum[warp] = inc;
    __syncthreads();
    if (tid < 32) {
        int v = wsum[tid];
        #pragma unroll
        for (int o = 1; o < 32; o <<= 1) {
            int n2 = __shfl_up_sync(0xffffffffu, v, o);
            if (tid >= o) v += n2;
        }
        wsum[tid] = v;
    }
    __syncthreads();
    int off = inc - cnt + (warp ? wsum[warp - 1] : 0);
    #pragma unroll
    for (int j = 0; j < 4; j++) {
        tgt[(size_t)b*TT + base + j] = flg[j] ? 1.f : 0.f;
        if (flg[j]) {
            idxo[b*KS + off] = base + j;
            float s = sc[base + j];
            gateo[b*KS + off] = 1.f / (1.f + expf(-s));
            off++;
        }
    }
}

// ---------------- K3: copy hidden -> out ----------------
__global__ void copy_kernel(const float4* __restrict__ src, float4* __restrict__ dst, int n4) {
    int stride = gridDim.x * blockDim.x;
    for (int i = blockIdx.x * blockDim.x + threadIdx.x; i < n4; i += stride)
        dst[i] = src[i];
}

// ---------------- K4: fused gather + rmsnorm(ln1) ----------------
__global__ void gather_rms_kernel(const float* __restrict__ hs, const int* __restrict__ idx,
                                  const float* __restrict__ g,
                                  float* __restrict__ sel, __half* __restrict__ a16) {
    __shared__ float red[8];
    int r = blockIdx.x, tid = threadIdx.x;
    int b = r / KS;
    int pos = idx[r];
    const float4* src = (const float4*)(hs + ((size_t)b*TT + pos) * DD);
    float4 x = src[tid];
    ((float4*)(sel + (size_t)r * DD))[tid] = x;
    float ss = x.x*x.x + x.y*x.y + x.z*x.z + x.w*x.w;
    #pragma unroll
    for (int o = 16; o; o >>= 1) ss += __shfl_xor_sync(0xffffffffu, ss, o);
    if ((tid & 31) == 0) red[tid >> 5] = ss;
    __syncthreads();
    if (tid < 8) {
        float v = red[tid];
        #pragma unroll
        for (int o = 4; o; o >>= 1) v += __shfl_xor_sync(0xffu, v, o);
        if (tid == 0) red[0] = v;
    }
    __syncthreads();
    float rs = rsqrtf(red[0] / (float)DD + 1e-6f);
    const float4* g4 = (const float4*)g;
    float4 gg = g4[tid];
    __half2 h0 = __float22half2_rn(make_float2(x.x*rs*gg.x, x.y*rs*gg.y));
    __half2 h1 = __float22half2_rn(make_float2(x.z*rs*gg.z, x.w*rs*gg.w));
    uint2* dst = (uint2*)(a16 + (size_t)r * DD);
    dst[tid] = make_uint2(*(uint32_t*)&h0, *(uint32_t*)&h1);
}

// ---------------- K5: rmsnorm f32 -> f16 ----------------
__global__ void rmsnorm_h_kernel(const float* __restrict__ in, const float* __restrict__ g,
                                 __half* __restrict__ out) {
    __shared__ float red[8];
    int r = blockIdx.x, tid = threadIdx.x;
    const float4* x4 = (const float4*)(in + (size_t)r * DD);
    float4 x = x4[tid];
    float ss = x.x*x.x + x.y*x.y + x.z*x.z + x.w*x.w;
    #pragma unroll
    for (int o = 16; o; o >>= 1) ss += __shfl_xor_sync(0xffffffffu, ss, o);
    if ((tid & 31) == 0) red[tid >> 5] = ss;
    __syncthreads();
    if (tid < 8) {
        float v = red[tid];
        #pragma unroll
        for (int o = 4; o; o >>= 1) v += __shfl_xor_sync(0xffu, v, o);
        if (tid == 0) red[0] = v;
    }
    __syncthreads();
    float rs = rsqrtf(red[0] / (float)DD + 1e-6f);
    const float4* g4 = (const float4*)g;
    float4 gg = g4[tid];
    __half2 h0 = __float22half2_rn(make_float2(x.x*rs*gg.x, x.y*rs*gg.y));
    __half2 h1 = __float22half2_rn(make_float2(x.z*rs*gg.z, x.w*rs*gg.w));
    uint2* dst = (uint2*)(out + (size_t)r * DD);
    dst[tid] = make_uint2(*(uint32_t*)&h0, *(uint32_t*)&h1);
}

// ---------------- K6: FP16 GEMM 64x128x32, 3-stage cp.async + ldmatrix ----------------
#define LDH 40
#define A_ST (64*LDH)                 // 2560 halfs
#define B_ST (128*LDH)                // 5120 halfs
#define GEMM_SMEM (3*(A_ST + B_ST)*2) // 46080 bytes
#define DUAL_T_ST (128*LDH)
#define DUAL_SMEM (3*3*DUAL_T_ST*2)   // 92160 bytes

__global__ __launch_bounds__(256)
void mma_gemm(const __half* __restrict__ A, const __half* __restrict__ Bt, void* __restrict__ Cv,
              int M, int N, int K, const float* __restrict__ aux, int epi, int ohalf) {
    extern __shared__ __half dynh[];
    __half* As = dynh;                // [3][64][40]
    __half* Bs = dynh + 3*A_ST;       // [3][128][40]

    int tid = threadIdx.x;
    int m0 = blockIdx.y * 64, n0 = blockIdx.x * 128;
    int warp = tid >> 5, lane = tid & 31;
    int wm = (warp >> 2) * 32;        // 0 or 32
    int wn = (warp & 3) * 32;
    int g = lane >> 2, c = lane & 3;

    float acc[2][4][4];
    #pragma unroll
    for (int i = 0; i < 2; i++)
        #pragma unroll
        for (int j = 0; j < 4; j++)
            #pragma unroll
            for (int r = 0; r < 4; r++) acc[i][j][r] = 0.f;

    // A: 256 chunks (1/thread), B: 512 chunks (2/thread)
    int aRow = tid >> 2, aOff = (tid & 3) * 8;
    int ch0 = tid * 2;
    int bRow = ch0 >> 2, bOff = (ch0 & 3) * 8;

    uint32_t asBase = (uint32_t)__cvta_generic_to_shared(As);
    uint32_t bsBase = (uint32_t)__cvta_generic_to_shared(Bs);

    int aRowL = lane & 15;
    int aColL = (lane >> 4) << 3;
    int bRowL = (lane & 7) + ((lane & 16) ? 8 : 0);
    int bColL = (lane & 8) ? 8 : 0;

    int nk = K / 32;

    auto prefetch = [&](int kt) {
        int st = kt % 3;
        const __half* Ag = A + (size_t)(m0 + aRow) * K + kt*32 + aOff;
        cpa16(asBase + (st*A_ST + aRow*LDH + aOff) * 2, Ag);
        const __half* Bg = Bt + (size_t)(n0 + bRow) * K + kt*32 + bOff;
        uint32_t bd = bsBase + (st*B_ST + bRow*LDH + bOff) * 2;
        cpa16(bd,      Bg);
        cpa16(bd + 16, Bg + 8);
        asm volatile("cp.async.commit_group;" ::: "memory");
    };

    prefetch(0);
    if (nk > 1) prefetch(1);

    for (int kt = 0; kt < nk; kt++) {
        if (kt + 1 < nk) {
            asm volatile("cp.async.wait_group 1;" ::: "memory");
        } else {
            asm volatile("cp.async.wait_group 0;" ::: "memory");
        }
        __syncthreads();
        if (kt + 2 < nk) prefetch(kt + 2);

        int st = kt % 3;
        uint32_t aStage = asBase + st*A_ST*2;
        uint32_t bStage = bsBase + st*B_ST*2;
        #pragma unroll
        for (int ks = 0; ks < 2; ks++) {
            int ko = ks * 16;
            uint32_t af[2][4], bf[4][2];
            #pragma unroll
            for (int i = 0; i < 2; i++) {
                uint32_t addr = aStage + ((wm + i*16 + aRowL)*LDH + ko + aColL) * 2;
                ldsm_x4(af[i][0], af[i][1], af[i][2], af[i][3], addr);
            }
            #pragma unroll
            for (int jp = 0; jp < 2; jp++) {
                uint32_t addr = bStage + ((wn + jp*16 + bRowL)*LDH + ko + bColL) * 2;
                ldsm_x4(bf[jp*2][0], bf[jp*2][1], bf[jp*2+1][0], bf[jp*2+1][1], addr);
            }
            #pragma unroll
            for (int i = 0; i < 2; i++)
                #pragma unroll
                for (int j = 0; j < 4; j++)
                    mma_f16(acc[i][j], af[i][0], af[i][1], af[i][2], af[i][3],
                            bf[j][0], bf[j][1]);
        }
    }

    float* C = (float*)Cv;
    __half* C16 = (__half*)Cv;
    #pragma unroll
    for (int i = 0; i < 2; i++) {
        int r0 = m0 + wm + i*16 + g;
        #pragma unroll
        for (int j = 0; j < 4; j++) {
            int col = n0 + wn + j*8 + c*2;
            float2 lo = make_float2(acc[i][j][0], acc[i][j][1]);
            float2 hi = make_float2(acc[i][j][2], acc[i][j][3]);
            if (epi == 1) {
                float b0 = aux[col], b1 = aux[col+1];
                lo.x = gelu_tanh(lo.x + b0); lo.y = gelu_tanh(lo.y + b1);
                hi.x = gelu_tanh(hi.x + b0); hi.y = gelu_tanh(hi.y + b1);
            } else if (epi == 2) {
                const float2 s0 = *(const float2*)&aux[(size_t)r0*N + col];
                const float2 s1 = *(const float2*)&aux[(size_t)(r0+8)*N + col];
                lo.x += s0.x; lo.y += s0.y; hi.x += s1.x; hi.y += s1.y;
            }
            if (ohalf) {
                __half2 l2 = __float22half2_rn(lo);
                __half2 h2 = __float22half2_rn(hi);
                *(__half2*)&C16[(size_t)r0*N + col] = l2;
                *(__half2*)&C16[(size_t)(r0+8)*N + col] = h2;
            } else {
                *(float2*)&C[(size_t)r0*N + col] = lo;
                *(float2*)&C[(size_t)(r0+8)*N + col] = hi;
            }
        }
    }
}

// ---------------- K6b: dual-B GEMM 128x128: C16 = silu(A@Bg^T) * (A@Bu^T) ----------------
__global__ __launch_bounds__(256, 1)
void mma_gemm_dual(const __half* __restrict__ A, const __half* __restrict__ Bgt,
                   const __half* __restrict__ But, __half* __restrict__ C16,
                   int M, int N, int K) {
    extern __shared__ __half dynh[];
    __half* As  = dynh;
    __half* Bgs = dynh + 3*DUAL_T_ST;
    __half* Bus = dynh + 6*DUAL_T_ST;

    int tid = threadIdx.x;
    int m0 = blockIdx.y * 128, n0 = blockIdx.x * 128;
    int warp = tid >> 5, lane = tid & 31;
    int wm = (warp >> 2) * 64;
    int wn = (warp & 3) * 32;
    int g = lane >> 2, c = lane & 3;

    float accg[4][4][4], accu[4][4][4];
    #pragma unroll
    for (int i = 0; i < 4; i++)
        #pragma unroll
        for (int j = 0; j < 4; j++)
            #pragma unroll
            for (int r = 0; r < 4; r++) { accg[i][j][r] = 0.f; accu[i][j][r] = 0.f; }

    int ch0 = tid * 2;
    int ldRow = ch0 >> 2;
    int ldOff = (ch0 & 3) * 8;

    uint32_t asBase = (uint32_t)__cvta_generic_to_shared(As);
    uint32_t bgBase = (uint32_t)__cvta_generic_to_shared(Bgs);
    uint32_t buBase = (uint32_t)__cvta_generic_to_shared(Bus);

    int aRowL = lane & 15;
    int aColL = (lane >> 4) << 3;
    int bRowL = (lane & 7) + ((lane & 16) ? 8 : 0);
    int bColL = (lane & 8) ? 8 : 0;

    int nk = K / 32;

    auto prefetch = [&](int kt) {
        int st = kt % 3;
        const __half* Ag = A + (size_t)(m0 + ldRow) * K + kt*32 + ldOff;
        uint32_t ad = asBase + (st*DUAL_T_ST + ldRow*LDH + ldOff) * 2;
        cpa16(ad,      Ag);
        cpa16(ad + 16, Ag + 8);
        const __half* Gg = Bgt + (size_t)(n0 + ldRow) * K + kt*32 + ldOff;
        uint32_t gd = bgBase + (st*DUAL_T_ST + ldRow*LDH + ldOff) * 2;
        cpa16(gd,      Gg);
        cpa16(gd + 16, Gg + 8);
        const __half* Ug = But + (size_t)(n0 + ldRow) * K + kt*32 + ldOff;
        uint32_t ud = buBase + (st*DUAL_T_ST + ldRow*LDH + ldOff) * 2;
        cpa16(ud,      Ug);
        cpa16(ud + 16, Ug + 8);
        asm volatile("cp.async.commit_group;" ::: "memory");
    };

    prefetch(0);
    if (nk > 1) prefetch(1);

    for (int kt = 0; kt < nk; kt++) {
        if (kt + 1 < nk) {
            asm volatile("cp.async.wait_group 1;" ::: "memory");
        } else {
            asm volatile("cp.async.wait_group 0;" ::: "memory");
        }
        __syncthreads();
        if (kt + 2 < nk) prefetch(kt + 2);

        int st = kt % 3;
        uint32_t aStage = asBase + st*DUAL_T_ST*2;
        uint32_t gStage = bgBase + st*DUAL_T_ST*2;
        uint32_t uStage = buBase + st*DUAL_T_ST*2;
        #pragma unroll
        for (int ks = 0; ks < 2; ks++) {
            int ko = ks * 16;
            uint32_t af[4][4], bg[4][2], bu[4][2];
            #pragma unroll
            for (int i = 0; i < 4; i++) {
                uint32_t addr = aStage + ((wm + i*16 + aRowL)*LDH + ko + aColL) * 2;
                ldsm_x4(af[i][0], af[i][1], af[i][2], af[i][3], addr);
            }
            #pragma unroll
            for (int jp = 0; jp < 2; jp++) {
                uint32_t ga = gStage + ((wn + jp*16 + bRowL)*LDH + ko + bColL) * 2;
                ldsm_x4(bg[jp*2][0], bg[jp*2][1], bg[jp*2+1][0], bg[jp*2+1][1], ga);
                uint32_t ua = uStage + ((wn + jp*16 + bRowL)*LDH + ko + bColL) * 2;
                ldsm_x4(bu[jp*2][0], bu[jp*2][1], bu[jp*2+1][0], bu[jp*2+1][1], ua);
            }
            #pragma unroll
            for (int i = 0; i < 4; i++)
                #pragma unroll
                for (int j = 0; j < 4; j++) {
                    mma_f16(accg[i][j], af[i][0], af[i][1], af[i][2], af[i][3],
                            bg[j][0], bg[j][1]);
                    mma_f16(accu[i][j], af[i][0], af[i][1], af[i][2], af[i][3],
                            bu[j][0], bu[j][1]);
                }
        }
    }

    #pragma unroll
    for (int i = 0; i < 4; i++) {
        int r0 = m0 + wm + i*16 + g;
        #pragma unroll
        for (int j = 0; j < 4; j++) {
            int col = n0 + wn + j*8 + c*2;
            float g0 = accg[i][j][0], g1 = accg[i][j][1];
            float g2 = accg[i][j][2], g3 = accg[i][j][3];
            float v0 = g0 / (1.f + expf(-g0)) * accu[i][j][0];
            float v1 = g1 / (1.f + expf(-g1)) * accu[i][j][1];
            float v2 = g2 / (1.f + expf(-g2)) * accu[i][j][2];
            float v3 = g3 / (1.f + expf(-g3)) * accu[i][j][3];
            __half2 l2 = __float22half2_rn(make_float2(v0, v1));
            __half2 h2 = __float22half2_rn(make_float2(v2, v3));
            *(__half2*)&C16[(size_t)r0*N + col] = l2;
            *(__half2*)&C16[(size_t)(r0+8)*N + col] = h2;
        }
    }
}

// ---------------- K7: RoPE fp16 ----------------
__global__ void rope2h_kernel(__half* __restrict__ q, __half* __restrict__ k,
                              const int* __restrict__ idx) {
    int blk = blockIdx.x;
    __half* buf = (blk < ROWS) ? q : k;
    int r = (blk < ROWS) ? blk : blk - ROWS;
    float pos = (float)idx[r];
    __half* base = buf + (size_t)r * DD;
    const float C = -0.415241011861f;
    for (int c = threadIdx.x; c < 512; c += 256) {
        int h = c >> 5, i = c & 31;
        float inv = exp2f((float)i * C);
        float ang = pos * inv;
        float s, co; sincosf(ang, &s, &co);
        __half* p = base + h * 64;
        float x1 = __half2float(p[i]), x2 = __half2float(p[i + 32]);
        p[i]      = __float2half_rn(x1*co - x2*s);
        p[i + 32] = __float2half_rn(x2*co + x1*s);
    }
}

// ---------------- K8: fused flash attention fp16, cp.async double-buffered ----------------
__global__ __launch_bounds__(256)
void flash_kernel(const __half* __restrict__ q, const __half* __restrict__ k,
                  const __half* __restrict__ v, __half* __restrict__ pv) {
    __shared__ __half Ks[2][64*72];
    __shared__ __half Vs[2][64*72];
    __shared__ __half Ps[128*72];

    int qp = 3 - blockIdx.x;
    int bh = blockIdx.y, b = bh >> 4, h = bh & 15;
    int tid = threadIdx.x;
    int w = tid >> 5, lane = tid & 31, g = lane >> 2, c = lane & 3;

    uint32_t ksBase = (uint32_t)__cvta_generic_to_shared(&Ks[0][0]);
    uint32_t vsBase = (uint32_t)__cvta_generic_to_shared(&Vs[0][0]);
    const int ST = 64*72;   // halfs per stage

    int ldRow = tid >> 1;                // 0..127 covers 64 rows x2 chunks? no:
    // K/V tile: 64 rows x 64 halfs = 128B/row = 8 chunks/row = 512 chunks; 256 thr -> 2 each
    int e0 = tid * 2;
    int kvRow = e0 >> 3;                 // 0..63
    int kvCol = (e0 & 7) * 8;            // halfs

    auto prefetch = [&](int kt) {
        int st = kt & 1;
        const __half* Kg = k + ((size_t)(b*KS + kt*64 + kvRow))*DD + h*64 + kvCol;
        const __half* Vg = v + ((size_t)(b*KS + kt*64 + kvRow))*DD + h*64 + kvCol;
        uint32_t kd = ksBase + (st*ST + kvRow*72 + kvCol) * 2;
        uint32_t vd = vsBase + (st*ST + kvRow*72 + kvCol) * 2;
        cpa16(kd,      Kg);
        cpa16(kd + 16, Kg + 8);
        cpa16(vd,      Vg);
        cpa16(vd + 16, Vg + 8);
        asm volatile("cp.async.commit_group;" ::: "memory");
    };

    // stage Q tile through Ps, extract a-fragments
    #pragma unroll
    for (int p = 0; p < 4; p++) {
        int e = p*256 + tid;
        int row = e >> 3, col = (e & 7) * 8;
        *(float4*)&Ps[row*72 + col] =
            *(const float4*)&q[((size_t)(b*KS + qp*128 + row))*DD + h*64 + col];
    }
    prefetch(0);
    __syncthreads();
    uint32_t qa[4][4];
    {
        const __half* pr0 = &Ps[(w*16 + g)*72];
        const __half* pr1 = &Ps[(w*16 + g + 8)*72];
        #pragma unroll
        for (int d = 0; d < 4; d++) {
            qa[d][0] = *(const uint32_t*)&pr0[d*16 + c*2];
            qa[d][1] = *(const uint32_t*)&pr1[d*16 + c*2];
            qa[d][2] = *(const uint32_t*)&pr0[d*16 + c*2 + 8];
            qa[d][3] = *(const uint32_t*)&pr1[d*16 + c*2 + 8];
        }
    }

    float o[8][4];
    #pragma unroll
    for (int j = 0; j < 8; j++)
        #pragma unroll
        for (int r = 0; r < 4; r++) o[j][r] = 0.f;
    float m0 = -1e38f, m1 = -1e38f, l0 = 0.f, l1 = 0.f;

    int q0 = qp*128 + w*16 + g;
    int q1 = q0 + 8;
    const float SC = 0.125f;
    int ktmax = 2*qp + 1;
    int bRowL = (lane & 7) + ((lane & 16) ? 8 : 0);
    int bColL = (lane & 8) ? 8 : 0;

    for (int kt = 0; kt <= ktmax; kt++) {
        asm volatile("cp.async.wait_group 0;" ::: "memory");
        __syncthreads();
        if (kt + 1 <= ktmax) prefetch(kt + 1);
        int st = kt & 1;
        uint32_t kStage = ksBase + st*ST*2;
        uint32_t vStage = vsBase + st*ST*2;

        float s[8][4];
        #pragma unroll
        for (int j = 0; j < 8; j++)
            #pragma unroll
            for (int r = 0; r < 4; r++) s[j][r] = 0.f;
        #pragma unroll
        for (int d = 0; d < 4; d++) {
            #pragma unroll
            for (int jp = 0; jp < 4; jp++) {
                uint32_t addr = kStage + ((jp*16 + bRowL)*72 + d*16 + bColL) * 2;
                uint32_t b0a, b1a, b0b, b1b;
                ldsm_x4(b0a, b1a, b0b, b1b, addr);
                mma_f16(s[jp*2  ], qa[d][0], qa[d][1], qa[d][2], qa[d][3], b0a, b1a);
                mma_f16(s[jp*2+1], qa[d][0], qa[d][1], qa[d][2], qa[d][3], b0b, b1b);
            }
        }

        float mx0 = m0, mx1 = m1;
        #pragma unroll
        for (int j = 0; j < 8; j++) {
            int kc = kt*64 + j*8 + c*2;
            s[j][0] = (kc   <= q0) ? s[j][0]*SC : -1e30f;
            s[j][1] = (kc+1 <= q0) ? s[j][1]*SC : -1e30f;
            s[j][2] = (kc   <= q1) ? s[j][2]*SC : -1e30f;
            s[j][3] = (kc+1 <= q1) ? s[j][3]*SC : -1e30f;
            mx0 = fmaxf(mx0, fmaxf(s[j][0], s[j][1]));
            mx1 = fmaxf(mx1, fmaxf(s[j][2], s[j][3]));
        }
        mx0 = fmaxf(mx0, __shfl_xor_sync(0xffffffffu, mx0, 1));
        mx0 = fmaxf(mx0, __shfl_xor_sync(0xffffffffu, mx0, 2));
        mx1 = fmaxf(mx1, __shfl_xor_sync(0xffffffffu, mx1, 1));
        mx1 = fmaxf(mx1, __shfl_xor_sync(0xffffffffu, mx1, 2));

        float al0 = expf(m0 - mx0), al1 = expf(m1 - mx1);
        m0 = mx0; m1 = mx1;
        float sum0 = 0.f, sum1 = 0.f;
        #pragma unroll
        for (int j = 0; j < 8; j++) {
            s[j][0] = expf(s[j][0] - mx0);
            s[j][1] = expf(s[j][1] - mx0);
            s[j][2] = expf(s[j][2] - mx1);
            s[j][3] = expf(s[j][3] - mx1);
            sum0 += s[j][0] + s[j][1];
            sum1 += s[j][2] + s[j][3];
        }
        sum0 += __shfl_xor_sync(0xffffffffu, sum0, 1);
        sum0 += __shfl_xor_sync(0xffffffffu, sum0, 2);
        sum1 += __shfl_xor_sync(0xffffffffu, sum1, 1);
        sum1 += __shfl_xor_sync(0xffffffffu, sum1, 2);
        l0 = l0*al0 + sum0;
        l1 = l1*al1 + sum1;
        #pragma unroll
        for (int j = 0; j < 8; j++) {
            o[j][0] *= al0; o[j][1] *= al0;
            o[j][2] *= al1; o[j][3] *= al1;
        }

        {
            __half* pr0 = &Ps[(w*16 + g)*72];
            __half* pr1 = &Ps[(w*16 + g + 8)*72];
            #pragma unroll
            for (int j = 0; j < 8; j++) {
                *(__half2*)&pr0[j*8 + c*2] = __float22half2_rn(make_float2(s[j][0], s[j][1]));
                *(__half2*)&pr1[j*8 + c*2] = __float22half2_rn(make_float2(s[j][2], s[j][3]));
            }
        }
        __syncwarp();

        {
            const __half* pr0 = &Ps[(w*16 + g)*72];
            const __half* pr1 = &Ps[(w*16 + g + 8)*72];
            #pragma unroll
            for (int ksl = 0; ksl < 4; ksl++) {
                uint32_t pa0 = *(const uint32_t*)&pr0[ksl*16 + c*2];
                uint32_t pa1 = *(const uint32_t*)&pr1[ksl*16 + c*2];
                uint32_t pa2 = *(const uint32_t*)&pr0[ksl*16 + c*2 + 8];
                uint32_t pa3 = *(const uint32_t*)&pr1[ksl*16 + c*2 + 8];
                #pragma unroll
                for (int jp = 0; jp < 4; jp++) {
                    int mrow = ksl*16 + (lane & 8) + (lane & 7);
                    int mcol = jp*16 + ((lane >> 4) << 3);
                    uint32_t addr = vStage + (mrow*72 + mcol) * 2;
                    uint32_t b0e, b1e, b0o, b1o;
                    ldsm_x4_t(b0e, b1e, b0o, b1o, addr);
                    mma_f16(o[jp*2  ], pa0, pa1, pa2, pa3, b0e, b1e);
                    mma_f16(o[jp*2+1], pa0, pa1, pa2, pa3, b0o, b1o);
                }
            }
        }
    }

    float inv0 = 1.f / l0, inv1 = 1.f / l1;
    size_t r0 = (size_t)(b*KS + q0) * DD + h*64;
    size_t r1 = (size_t)(b*KS + q1) * DD + h*64;
    #pragma unroll
    for (int j = 0; j < 8; j++) {
        *(__half2*)&pv[r0 + j*8 + c*2] = __float22half2_rn(make_float2(o[j][0]*inv0, o[j][1]*inv0));
        *(__half2*)&pv[r1 + j*8 + c*2] = __float22half2_rn(make_float2(o[j][2]*inv1, o[j][3]*inv1));
    }
}

// ---------------- K12: scatter ----------------
__global__ void scatter_kernel(const float* __restrict__ sel, const float* __restrict__ bo,
                               const int* __restrict__ idx, const float* __restrict__ gate,
                               float* __restrict__ out) {
    int r = blockIdx.x;
    int b = r / KS;
    int pos = idx[r];
    float ga = gate[r];
    const float4* s4 = (const float4*)(sel + (size_t)r * DD);
    const float4* b4 = (const float4*)(bo  + (size_t)r * DD);
    float4* o4 = (float4*)(out + ((size_t)b*TT + pos) * DD);
    float4 s = s4[threadIdx.x], bb = b4[threadIdx.x];
    float4 u = make_float4(s.x + ga*(bb.x - s.x), s.y + ga*(bb.y - s.y),
                           s.z + ga*(bb.z - s.z), s.w + ga*(bb.w - s.w));
    o4[threadIdx.x] = u;
}

// ---------------- K13: predictor logits + per-row BCE ----------------
__global__ void predrow_kernel(const float* __restrict__ h1, const float* __restrict__ fc2w,
                               const float* __restrict__ fc2b, const float* __restrict__ tgt,
                               float* __restrict__ pred) {
    int warp = (blockIdx.x * blockDim.x + threadIdx.x) >> 5;
    int lane = threadIdx.x & 31;
    if (warp >= NTOK) return;
    const float* row = h1 + (size_t)warp * DQ;
    float s = 0.f;
    #pragma unroll
    for (int i = lane; i < DQ; i += 32) s += row[i] * fc2w[i];
    #pragma unroll
    for (int o = 16; o; o >>= 1) s += __shfl_xor_sync(0xffffffffu, s, o);
    if (lane == 0) {
        float x = s + fc2b[0];
        pred[warp] = bce_term(x, tgt[warp]);
    }
}

// ---------------- K14: loss reduce ----------------
__global__ void loss_reduce(const float* __restrict__ scores, const float* __restrict__ tgt,
                            const float* __restrict__ pred, float* __restrict__ out_aux) {
    __shared__ float sm_main[1024];
    __shared__ float sm_pred[1024];
    int tid = threadIdx.x;
    float sm = 0.f, sp = 0.f;
    for (int i = tid; i < NTOK; i += 1024) {
        sm += bce_term(scores[i], tgt[i]);
        sp += pred[i];
    }
    sm_main[tid] = sm; sm_pred[tid] = sp;
    __syncthreads();
    for (int s = 512; s > 0; s >>= 1) {
        if (tid < s) { sm_main[tid] += sm_main[tid+s]; sm_pred[tid] += sm_pred[tid+s]; }
        __syncthreads();
    }
    if (tid == 0)
        out_aux[0] = 0.01f * (sm_main[0] + sm_pred[0]) / (float)NTOK;
}

// ---------------- host launch ----------------
extern "C" void kernel_launch(void* const* d_in, const int* in_sizes, int n_in,
                              void* d_out, int out_size) {
    const float* hs   = (const float*)d_in[0];
    const float* rw   = (const float*)d_in[1];
    const float* fc1w = (const float*)d_in[2];
    const float* fc1b = (const float*)d_in[3];
    const float* fc2w = (const float*)d_in[4];
    const float* fc2b = (const float*)d_in[5];
    const float* ln1  = (const float*)d_in[6];
    const float* ln2  = (const float*)d_in[7];
    const float* wq   = (const float*)d_in[8];
    const float* wk   = (const float*)d_in[9];
    const float* wv   = (const float*)d_in[10];
    const float* wo   = (const float*)d_in[11];
    const float* wg   = (const float*)d_in[12];
    const float* wu   = (const float*)d_in[13];
    const float* wd   = (const float*)d_in[14];
    float* out = (float*)d_out;

    float *scores, *tgt, *gate, *sel, *h, *bo, *h1, *pred;
    __half *a16, *q16, *k16, *v16, *pv16, *m16, *gb16, *hs16;
    __half *wqT, *wkT, *wvT, *woT, *wuT, *wgT, *wdT, *fc1T;
    int* idx;
    cudaGetSymbolAddress((void**)&scores, g_scores);
    cudaGetSymbolAddress((void**)&tgt,    g_tgt);
    cudaGetSymbolAddress((void**)&idx,    g_idx);
    cudaGetSymbolAddress((void**)&gate,   g_gate);
    cudaGetSymbolAddress((void**)&sel,    g_sel);
    cudaGetSymbolAddress((void**)&a16,    g_a16);
    cudaGetSymbolAddress((void**)&q16,    g_q16);
    cudaGetSymbolAddress((void**)&k16,    g_k16);
    cudaGetSymbolAddress((void**)&v16,    g_v16);
    cudaGetSymbolAddress((void**)&pv16,   g_pv16);
    cudaGetSymbolAddress((void**)&h,      g_h);
    cudaGetSymbolAddress((void**)&m16,    g_m16);
    cudaGetSymbolAddress((void**)&gb16,   g_gb16);
    cudaGetSymbolAddress((void**)&bo,     g_bo);
    cudaGetSymbolAddress((void**)&hs16,   g_hs16);
    cudaGetSymbolAddress((void**)&h1,     g_h1);
    cudaGetSymbolAddress((void**)&pred,   g_pred);
    cudaGetSymbolAddress((void**)&wqT,    g_wqT);
    cudaGetSymbolAddress((void**)&wkT,    g_wkT);
    cudaGetSymbolAddress((void**)&wvT,    g_wvT);
    cudaGetSymbolAddress((void**)&woT,    g_woT);
    cudaGetSymbolAddress((void**)&wuT,    g_wuT);
    cudaGetSymbolAddress((void**)&wgT,    g_wgT);
    cudaGetSymbolAddress((void**)&wdT,    g_wdT);
    cudaGetSymbolAddress((void**)&fc1T,   g_fc1T);

    cudaFuncSetAttribute(mma_gemm, cudaFuncAttributeMaxDynamicSharedMemorySize, GEMM_SMEM);
    cudaFuncSetAttribute(mma_gemm_dual, cudaFuncAttributeMaxDynamicSharedMemorySize, DUAL_SMEM);

    // ---- weight transpose+convert on s3 ----
    cudaEventRecord(eStart, 0);
    cudaStreamWaitEvent(s3, eStart, 0);
    cudaStreamWaitEvent(s2, eStart, 0);
    cudaStreamWaitEvent(s1, eStart, 0);
    wconv_kernel<<<dim3(32, 32), 256, 0, s3>>>(wq, wqT, DD, DD);
    wconv_kernel<<<dim3(32, 32), 256, 0, s3>>>(wk, wkT, DD, DD);
    wconv_kernel<<<dim3(32, 32), 256, 0, s3>>>(wv, wvT, DD, DD);
    wconv_kernel<<<dim3(32, 32), 256, 0, s3>>>(wo, woT, DD, DD);
    wconv_kernel<<<dim3(128, 32), 256, 0, s3>>>(wu, wuT, DD, FF);
    wconv_kernel<<<dim3(128, 32), 256, 0, s3>>>(wg, wgT, DD, FF);
    wconv_kernel<<<dim3(32, 128), 256, 0, s3>>>(wd, wdT, FF, DD);
    wconv_kernel<<<dim3(8, 32), 256, 0, s3>>>(fc1w, fc1T, DD, DQ);
    cudaEventRecord(eW, s3);

    // ---- copy hidden -> out on s2 ----
    copy_kernel<<<4096, 256, 0, s2>>>((const float4*)hs, (float4*)out, NTOK*DD/4);
    cudaEventRecord(eC, s2);

    // ---- router scores + hs->f16 (fused) on main ----
    scores_f2h_kernel<<<NTOK/8, 256>>>(hs, rw, scores, hs16);
    cudaEventRecord(eH, 0);
    topk_radix<<<BB, 1024>>>(scores, tgt, idx, gate);
    cudaEventRecord(eTopk, 0);

    // ---- predictor path on s1 ----
    cudaStreamWaitEvent(s1, eH, 0);
    cudaStreamWaitEvent(s1, eW, 0);
    mma_gemm<<<dim3(DQ/128, NTOK/64), 256, GEMM_SMEM, s1>>>(hs16, fc1T, h1, NTOK, DQ, DD, fc1b, 1, 0);
    cudaStreamWaitEvent(s1, eTopk, 0);
    predrow_kernel<<<NTOK/8, 256, 0, s1>>>(h1, fc2w, fc2b, tgt, pred);
    cudaEventRecord(eP, s1);

    // ---- decoder block ----
    gather_rms_kernel<<<ROWS, 256>>>(hs, idx, ln1, sel, a16);
    cudaEventRecord(eA, 0);
    cudaStreamWaitEvent(s2, eA, 0);
    cudaStreamWaitEvent(s2, eW, 0);
    cudaStreamWaitEvent(s3, eA, 0);
    mma_gemm<<<dim3(DD/128, ROWS/64), 256, GEMM_SMEM, s2>>>(a16, wkT, k16, ROWS, DD, DD, nullptr, 0, 1);
    cudaEventRecord(eK, s2);
    mma_gemm<<<dim3(DD/128, ROWS/64), 256, GEMM_SMEM, s3>>>(a16, wvT, v16, ROWS, DD, DD, nullptr, 0, 1);
    cudaEventRecord(eV, s3);
    cudaStreamWaitEvent(0, eW, 0);
    mma_gemm<<<dim3(DD/128, ROWS/64), 256, GEMM_SMEM>>>(a16, wqT, q16, ROWS, DD, DD, nullptr, 0, 1);
    cudaStreamWaitEvent(0, eK, 0);
    rope2h_kernel<<<2*ROWS, 256>>>(q16, k16, idx);
    cudaStreamWaitEvent(0, eV, 0);
    flash_kernel<<<dim3(4, BB*HH), 256>>>(q16, k16, v16, pv16);
    mma_gemm<<<dim3(DD/128, ROWS/64), 256, GEMM_SMEM>>>(pv16, woT, h, ROWS, DD, DD, sel, 2, 0);

    rmsnorm_h_kernel<<<ROWS, 256>>>(h, ln2, m16);
    mma_gemm_dual<<<dim3(FF/128, ROWS/128), 256, DUAL_SMEM>>>(m16, wgT, wuT, gb16, ROWS, FF, DD);
    mma_gemm<<<dim3(DD/128, ROWS/64), 256, GEMM_SMEM>>>(gb16, wdT, bo, ROWS, DD, FF, h, 2, 0);

    cudaStreamWaitEvent(0, eC, 0);
    scatter_kernel<<<ROWS, 256>>>(sel, bo, idx, gate, out);

    cudaStreamWaitEvent(0, eP, 0);
    loss_reduce<<<1, 1024>>>(scores, tgt, pred, out + (size_t)NTOK*DD);
}